// round 2
// baseline (speedup 1.0000x reference)
#include <cuda_runtime.h>

#define SLEN   2048
#define NBATCH 2
#define DMODEL 1024
#define PROJ   512
#define MTOT   (NBATCH*SLEN)
#define NHEAD  8

// ---------------- scratch (device globals; no allocation allowed) ----------------
__device__ float g_q   [MTOT*PROJ];
__device__ float g_k   [MTOT*PROJ];
__device__ float g_v   [MTOT*PROJ];
__device__ float g_qa  [MTOT*PROJ];
__device__ float g_ka  [MTOT*PROJ];
__device__ float g_qr  [MTOT*PROJ];
__device__ float g_kr  [MTOT*PROJ];
__device__ float g_sv  [MTOT*PROJ];
__device__ float g_sactx[MTOT*PROJ];
__device__ float g_ractx[MTOT*PROJ];
__device__ float g_rel[(size_t)NBATCH*8*SLEN*SLEN];   // 268 MB

// ---------------- GEMM: Y[m,n] = sum_k X[m,k]*W[n,k], optional fused RoPE -------
// BM=128, BN=64, BK=16, 256 threads, 8x4 per-thread microtile.
__global__ __launch_bounds__(256) void gemm_kernel(
    const float* __restrict__ X, const float* __restrict__ W,
    float* __restrict__ Y, int M, int N, int K,
    int ldy, int col_off, int do_rope,
    const float* __restrict__ fc, const float* __restrict__ fs)
{
    __shared__ float As[16][128];
    __shared__ float Bs[16][64];
    const int tid = threadIdx.x;
    const int tx = tid & 15, ty = tid >> 4;
    const int mBase = blockIdx.y * 128, nBase = blockIdx.x * 64;

    float acc[8][4];
#pragma unroll
    for (int i = 0; i < 8; i++)
#pragma unroll
        for (int j = 0; j < 4; j++) acc[i][j] = 0.f;

    for (int k0 = 0; k0 < K; k0 += 16) {
        // A tile: 128x16
#pragma unroll
        for (int u = 0; u < 2; u++) {
            int e = tid + u * 256;        // float4 slot
            int row = e >> 2, c4 = e & 3;
            float4 vv = *reinterpret_cast<const float4*>(
                &X[(size_t)(mBase + row) * K + k0 + c4 * 4]);
            As[c4*4+0][row] = vv.x; As[c4*4+1][row] = vv.y;
            As[c4*4+2][row] = vv.z; As[c4*4+3][row] = vv.w;
        }
        // B tile: 64x16
        {
            int row = tid >> 2, c4 = tid & 3;
            float4 vv = *reinterpret_cast<const float4*>(
                &W[(size_t)(nBase + row) * K + k0 + c4 * 4]);
            Bs[c4*4+0][row] = vv.x; Bs[c4*4+1][row] = vv.y;
            Bs[c4*4+2][row] = vv.z; Bs[c4*4+3][row] = vv.w;
        }
        __syncthreads();
#pragma unroll
        for (int kk = 0; kk < 16; kk++) {
            float a[8], bb[4];
            float4 a0 = *reinterpret_cast<float4*>(&As[kk][ty*8]);
            float4 a1 = *reinterpret_cast<float4*>(&As[kk][ty*8+4]);
            a[0]=a0.x; a[1]=a0.y; a[2]=a0.z; a[3]=a0.w;
            a[4]=a1.x; a[5]=a1.y; a[6]=a1.z; a[7]=a1.w;
            float4 b0 = *reinterpret_cast<float4*>(&Bs[kk][tx*4]);
            bb[0]=b0.x; bb[1]=b0.y; bb[2]=b0.z; bb[3]=b0.w;
#pragma unroll
            for (int i = 0; i < 8; i++)
#pragma unroll
                for (int j = 0; j < 4; j++)
                    acc[i][j] = fmaf(a[i], bb[j], acc[i][j]);
        }
        __syncthreads();
    }

#pragma unroll
    for (int i = 0; i < 8; i++) {
        int m = mBase + ty * 8 + i;
        if (!do_rope) {
            float4 vv = make_float4(acc[i][0], acc[i][1], acc[i][2], acc[i][3]);
            *reinterpret_cast<float4*>(&Y[(size_t)m * ldy + col_off + nBase + tx*4]) = vv;
        } else {
            int srow = m & (SLEN - 1);
#pragma unroll
            for (int p = 0; p < 2; p++) {
                int n0 = nBase + tx * 4 + p * 2;
                int t = (n0 & 63) >> 1;
                float cz = fc[srow * 32 + t], sz = fs[srow * 32 + t];
                float xr = acc[i][p*2], xi = acc[i][p*2+1];
                Y[(size_t)m * ldy + n0    ] = xr * cz - xi * sz;
                Y[(size_t)m * ldy + n0 + 1] = xr * sz + xi * cz;
            }
        }
    }
}

// ---------------- rel[b,r,i,j] = rel_scale * qr[b,i,r,:]·kr[b,j,r,:] (causal tiles)
__global__ __launch_bounds__(256) void rel_kernel(
    const float* __restrict__ QR, const float* __restrict__ KR)
{
    const int jt = blockIdx.x, it = blockIdx.y, br = blockIdx.z;
    if (jt > it) return;
    const int b = br >> 3, r = br & 7;
    __shared__ float Qs[64][65];
    __shared__ float Ks[64][65];
    const int tid = threadIdx.x;
    const int tx = tid & 15, ty = tid >> 4;
#pragma unroll
    for (int u = 0; u < 16; u++) {
        int e = tid + u * 256;
        int row = e >> 6, col = e & 63;
        Qs[row][col] = QR[((size_t)(b*SLEN) + it*64 + row) * PROJ + r*64 + col];
        Ks[row][col] = KR[((size_t)(b*SLEN) + jt*64 + row) * PROJ + r*64 + col];
    }
    __syncthreads();
    float acc[4][4] = {};
#pragma unroll
    for (int p = 0; p < 64; p++) {
        float a[4], bb[4];
#pragma unroll
        for (int i = 0; i < 4; i++) a[i]  = Qs[ty*4+i][p];
#pragma unroll
        for (int j = 0; j < 4; j++) bb[j] = Ks[tx*4+j][p];
#pragma unroll
        for (int i = 0; i < 4; i++)
#pragma unroll
            for (int j = 0; j < 4; j++)
                acc[i][j] = fmaf(a[i], bb[j], acc[i][j]);
    }
    float* out = g_rel + ((size_t)br * SLEN + it*64) * SLEN + jt*64;
#pragma unroll
    for (int i = 0; i < 4; i++)
#pragma unroll
        for (int j = 0; j < 4; j++)
            out[(size_t)(ty*4+i) * SLEN + tx*4 + j] = acc[i][j] * 0.125f;
}

// ---------------- flash attention, Q-tile 64, KV-tile 32, causal -----------------
// RA=true additionally accumulates attended_rel from g_rel and adds rel_out.
template<bool RA>
__global__ __launch_bounds__(256) void flash_kernel(
    const float* __restrict__ Q, const float* __restrict__ Kx,
    const float* __restrict__ V, const float* __restrict__ WR,
    float* __restrict__ Octx)
{
    __shared__ float Qs[64*64];
    __shared__ float Ks[32*65];   // K tile; reused as P (64x32)
    __shared__ float Vs[32*64];
    __shared__ float wrs[64*8];
    float* Ps = Ks;

    const int bh = blockIdx.y;
    const int b = bh >> 3, h = bh & 7;
    const int it = blockIdx.x;
    const int tid = threadIdx.x;
    const int tx = tid & 15, ty = tid >> 4;

#pragma unroll
    for (int u = 0; u < 16; u++) {
        int e = tid + u * 256;
        int row = e >> 6, col = e & 63;
        Qs[row*64 + col] = Q[((size_t)(b*SLEN + it*64 + row)) * PROJ + h*64 + col];
    }
    if (RA) {
        wrs[tid]       = WR[h*512 + tid];
        wrs[tid + 256] = WR[h*512 + 256 + tid];
    }
    __syncthreads();

    float o[4][4] = {};
    float ar[4][8];
    if (RA) {
#pragma unroll
        for (int i = 0; i < 4; i++)
#pragma unroll
            for (int r = 0; r < 8; r++) ar[i][r] = 0.f;
    }
    float mst[4], lst[4];
#pragma unroll
    for (int i = 0; i < 4; i++) { mst[i] = -1e30f; lst[i] = 0.f; }

    const int njt = (it + 1) * 2;
    for (int jt = 0; jt < njt; jt++) {
#pragma unroll
        for (int u = 0; u < 8; u++) {
            int e = tid + u * 256;
            int row = e >> 6, col = e & 63;
            size_t gidx = ((size_t)(b*SLEN + jt*32 + row)) * PROJ + h*64 + col;
            Ks[row*65 + col] = Kx[gidx];
            Vs[row*64 + col] = V[gidx];
        }
        __syncthreads();

        float s[4][2] = {};
#pragma unroll
        for (int d = 0; d < 64; d++) {
            float a[4], bb[2];
#pragma unroll
            for (int i = 0; i < 4; i++) a[i] = Qs[(ty*4+i)*64 + d];
            bb[0] = Ks[(tx*2+0)*65 + d];
            bb[1] = Ks[(tx*2+1)*65 + d];
#pragma unroll
            for (int i = 0; i < 4; i++) {
                s[i][0] = fmaf(a[i], bb[0], s[i][0]);
                s[i][1] = fmaf(a[i], bb[1], s[i][1]);
            }
        }
        const bool diag = (jt >= it * 2);
#pragma unroll
        for (int i = 0; i < 4; i++)
#pragma unroll
            for (int j = 0; j < 2; j++) {
                s[i][j] *= 0.125f;
                if (diag) {
                    int gi = it*64 + ty*4 + i, gj = jt*32 + tx*2 + j;
                    if (gj > gi) s[i][j] = -1e30f;
                }
            }
        float rm[4];
#pragma unroll
        for (int i = 0; i < 4; i++) rm[i] = fmaxf(s[i][0], s[i][1]);
#pragma unroll
        for (int off = 8; off >= 1; off >>= 1)
#pragma unroll
            for (int i = 0; i < 4; i++)
                rm[i] = fmaxf(rm[i], __shfl_xor_sync(0xffffffffu, rm[i], off));

        float scale[4], rs[4];
#pragma unroll
        for (int i = 0; i < 4; i++) {
            float nm = fmaxf(mst[i], rm[i]);
            scale[i] = __expf(mst[i] - nm);
            mst[i] = nm;
            s[i][0] = __expf(s[i][0] - nm);   // s becomes p
            s[i][1] = __expf(s[i][1] - nm);
            rs[i] = s[i][0] + s[i][1];
        }
#pragma unroll
        for (int off = 8; off >= 1; off >>= 1)
#pragma unroll
            for (int i = 0; i < 4; i++)
                rs[i] += __shfl_xor_sync(0xffffffffu, rs[i], off);
#pragma unroll
        for (int i = 0; i < 4; i++) {
            lst[i] = lst[i] * scale[i] + rs[i];
#pragma unroll
            for (int dd = 0; dd < 4; dd++) o[i][dd] *= scale[i];
        }

        if (RA) {
            const size_t relbase = ((size_t)(b * 8)) * SLEN * SLEN;
#pragma unroll
            for (int i = 0; i < 4; i++) {
#pragma unroll
                for (int r = 0; r < 8; r++) ar[i][r] *= scale[i];
                int gi = it*64 + ty*4 + i;
#pragma unroll
                for (int r = 0; r < 8; r++) {
                    const float2 rv = *reinterpret_cast<const float2*>(
                        &g_rel[relbase + ((size_t)r * SLEN + gi) * SLEN + jt*32 + tx*2]);
                    ar[i][r] = fmaf(s[i][0], rv.x, ar[i][r]);
                    ar[i][r] = fmaf(s[i][1], rv.y, ar[i][r]);
                }
            }
        }
        __syncthreads();              // everyone done reading Ks
#pragma unroll
        for (int i = 0; i < 4; i++) {
            Ps[(ty*4+i)*32 + tx*2 + 0] = s[i][0];
            Ps[(ty*4+i)*32 + tx*2 + 1] = s[i][1];
        }
        __syncthreads();              // P visible
#pragma unroll
        for (int j = 0; j < 32; j++) {
            float pv[4];
#pragma unroll
            for (int i = 0; i < 4; i++) pv[i] = Ps[(ty*4+i)*32 + j];
            float4 v4 = *reinterpret_cast<float4*>(&Vs[j*64 + tx*4]);
            float vv[4] = {v4.x, v4.y, v4.z, v4.w};
#pragma unroll
            for (int i = 0; i < 4; i++)
#pragma unroll
                for (int dd = 0; dd < 4; dd++)
                    o[i][dd] = fmaf(pv[i], vv[dd], o[i][dd]);
        }
        __syncthreads();              // before next K/V load
    }

    if (RA) {
#pragma unroll
        for (int off = 8; off >= 1; off >>= 1)
#pragma unroll
            for (int i = 0; i < 4; i++)
#pragma unroll
                for (int r = 0; r < 8; r++)
                    ar[i][r] += __shfl_xor_sync(0xffffffffu, ar[i][r], off);
    }
#pragma unroll
    for (int i = 0; i < 4; i++) {
        float inv = 1.f / lst[i];
        int m = b*SLEN + it*64 + ty*4 + i;
#pragma unroll
        for (int dd = 0; dd < 4; dd++) {
            int d = tx*4 + dd;
            float val = o[i][dd] * inv;
            if (RA) {
                float ro = 0.f;
#pragma unroll
                for (int r = 0; r < 8; r++)
                    ro = fmaf(ar[i][r] * inv, wrs[d*8 + r], ro);
                val += ro;
            }
            Octx[(size_t)m * PROJ + h*64 + d] = val;
        }
    }
}

// ---------------- host launcher --------------------------------------------------
extern "C" void kernel_launch(void* const* d_in, const int* in_sizes, int n_in,
                              void* d_out, int out_size)
{
    const float* x       = (const float*)d_in[0];
    const float* symbols = (const float*)d_in[1];
    const float* fc      = (const float*)d_in[2];
    const float* fs      = (const float*)d_in[3];
    const float* wq_sa   = (const float*)d_in[4];
    const float* wk_sa   = (const float*)d_in[5];
    const float* wv_sa   = (const float*)d_in[6];
    const float* wo_sa   = (const float*)d_in[7];
    const float* wq_attn = (const float*)d_in[8];
    const float* wk_attn = (const float*)d_in[9];
    const float* wq_rel  = (const float*)d_in[10];
    const float* wk_rel  = (const float*)d_in[11];
    const float* wr      = (const float*)d_in[12];
    const float* wv_ra   = (const float*)d_in[13];
    const float* wo_ra   = (const float*)d_in[14];
    float* out = (float*)d_out;

    float *q, *k, *v, *qa, *ka, *qr, *kr, *sv, *sactx, *ractx;
    cudaGetSymbolAddress((void**)&q,  g_q);
    cudaGetSymbolAddress((void**)&k,  g_k);
    cudaGetSymbolAddress((void**)&v,  g_v);
    cudaGetSymbolAddress((void**)&qa, g_qa);
    cudaGetSymbolAddress((void**)&ka, g_ka);
    cudaGetSymbolAddress((void**)&qr, g_qr);
    cudaGetSymbolAddress((void**)&kr, g_kr);
    cudaGetSymbolAddress((void**)&sv, g_sv);
    cudaGetSymbolAddress((void**)&sactx, g_sactx);
    cudaGetSymbolAddress((void**)&ractx, g_ractx);

    dim3 blk(256);
    dim3 gproj(PROJ / 64, MTOT / 128);

    // projections (RoPE fused where needed)
    gemm_kernel<<<gproj, blk>>>(x, wq_sa,   q,  MTOT, PROJ, DMODEL, PROJ, 0, 1, fc, fs);
    gemm_kernel<<<gproj, blk>>>(x, wk_sa,   k,  MTOT, PROJ, DMODEL, PROJ, 0, 1, fc, fs);
    gemm_kernel<<<gproj, blk>>>(x, wv_sa,   v,  MTOT, PROJ, DMODEL, PROJ, 0, 0, nullptr, nullptr);
    gemm_kernel<<<gproj, blk>>>(x, wq_attn, qa, MTOT, PROJ, DMODEL, PROJ, 0, 1, fc, fs);
    gemm_kernel<<<gproj, blk>>>(x, wk_attn, ka, MTOT, PROJ, DMODEL, PROJ, 0, 1, fc, fs);
    gemm_kernel<<<gproj, blk>>>(x, wq_rel,  qr, MTOT, PROJ, DMODEL, PROJ, 0, 0, nullptr, nullptr);
    gemm_kernel<<<gproj, blk>>>(x, wk_rel,  kr, MTOT, PROJ, DMODEL, PROJ, 0, 0, nullptr, nullptr);
    gemm_kernel<<<gproj, blk>>>(symbols, wv_ra, sv, MTOT, PROJ, DMODEL, PROJ, 0, 0, nullptr, nullptr);

    // rel scores (causal tiles only)
    dim3 grel(SLEN / 64, SLEN / 64, NBATCH * 8);
    rel_kernel<<<grel, blk>>>(qr, kr);

    // attentions
    dim3 gfl(SLEN / 64, NBATCH * NHEAD);
    flash_kernel<false><<<gfl, blk>>>(q,  k,  v,  nullptr, sactx);
    flash_kernel<true ><<<gfl, blk>>>(qa, ka, sv, wr,      ractx);

    // output projections into the two halves of out
    gemm_kernel<<<gproj, blk>>>(sactx, wo_sa, out, MTOT, PROJ, PROJ, DMODEL, 0,   0, nullptr, nullptr);
    gemm_kernel<<<gproj, blk>>>(ractx, wo_ra, out, MTOT, PROJ, PROJ, DMODEL, 512, 0, nullptr, nullptr);
}

// round 4
// speedup vs baseline: 1.5330x; 1.5330x over previous
#include <cuda_runtime.h>
#include <cuda_bf16.h>
#include <cstdint>

#define SLEN   2048
#define NBATCH 2
#define DMODEL 1024
#define PROJ   512
#define MTOT   (NBATCH*SLEN)
#define NHEAD  8

// ---------------- scratch (device globals; no allocation allowed) ----------------
__device__ float g_q   [MTOT*PROJ];
__device__ float g_k   [MTOT*PROJ];
__device__ float g_v   [MTOT*PROJ];
__device__ float g_qa  [MTOT*PROJ];
__device__ float g_ka  [MTOT*PROJ];
__device__ float g_sv  [MTOT*PROJ];
__device__ float g_ctx [2*MTOT*PROJ];                  // sactx | ractx
__device__ float g_rel[(size_t)NBATCH*8*SLEN*SLEN];    // 268 MB

// bf16 split buffers
__device__ __nv_bfloat16 g_xhi[MTOT*DMODEL];
__device__ __nv_bfloat16 g_xlo[MTOT*DMODEL];
__device__ __nv_bfloat16 g_shi[MTOT*DMODEL];
__device__ __nv_bfloat16 g_slo[MTOT*DMODEL];
#define WTOT (8*PROJ*DMODEL + 2*PROJ*PROJ)
__device__ __nv_bfloat16 g_whi[WTOT];
__device__ __nv_bfloat16 g_wlo[WTOT];
__device__ __nv_bfloat16 g_chi[2*MTOT*PROJ];
__device__ __nv_bfloat16 g_clo[2*MTOT*PROJ];
__device__ __nv_bfloat16 g_qrhi[MTOT*PROJ];
__device__ __nv_bfloat16 g_qrlo[MTOT*PROJ];
__device__ __nv_bfloat16 g_krhi[MTOT*PROJ];
__device__ __nv_bfloat16 g_krlo[MTOT*PROJ];

// ======================= PTX helpers (baseline ISA only, sm_103-safe) ============
__device__ __forceinline__ uint32_t smem_u32(const void* p) {
    uint32_t a;
    asm("{ .reg .u64 t; cvta.to.shared.u64 t, %1; cvt.u32.u64 %0, t; }" : "=r"(a) : "l"(p));
    return a;
}
__device__ __forceinline__ void ldsm4(uint32_t* r, uint32_t a) {
    asm volatile("ldmatrix.sync.aligned.m8n8.x4.shared.b16 {%0,%1,%2,%3}, [%4];"
        : "=r"(r[0]), "=r"(r[1]), "=r"(r[2]), "=r"(r[3]) : "r"(a));
}
__device__ __forceinline__ void mma16816(float* c, const uint32_t* a, const uint32_t* b) {
    asm volatile("mma.sync.aligned.m16n8k16.row.col.f32.bf16.bf16.f32 "
        "{%0,%1,%2,%3}, {%4,%5,%6,%7}, {%8,%9}, {%0,%1,%2,%3};"
        : "+f"(c[0]), "+f"(c[1]), "+f"(c[2]), "+f"(c[3])
        : "r"(a[0]), "r"(a[1]), "r"(a[2]), "r"(a[3]), "r"(b[0]), "r"(b[1]));
}

// ---------------- fp32 -> bf16 hi/lo split ---------------------------------------
__global__ __launch_bounds__(256) void split_kernel(
    const float* __restrict__ s, __nv_bfloat16* __restrict__ hi,
    __nv_bfloat16* __restrict__ lo, int n)
{
    int i = blockIdx.x * 256 + threadIdx.x;
    if (i < n) {
        float v = s[i];
        __nv_bfloat16 h = __float2bfloat16(v);
        float r = v - __bfloat162float(h);
        hi[i] = h;
        lo[i] = __float2bfloat16(r);
    }
}

// ---------------- HMMA batched GEMM: Y[m,n] = sum_k A[m,k]*B[n,k] ----------------
// CTA tile 128x64, 8 warps (4x2) of 32x32, K-chunk 32, bf16 2-term split.
struct GEntry {
    const __nv_bfloat16 *ahi, *alo, *bhi, *blo;
    float* y;
    __nv_bfloat16 *yhi, *ylo;
    int ldy, col_off, mode;   // 0 plain fp32, 1 rope fp32, 2 bf16 split
};
struct GBatch {
    GEntry e[8];
    const float *fc, *fs;
    int K;
};

__global__ __launch_bounds__(256, 2) void gemm_mma(GBatch args)
{
    const GEntry ge = args.e[blockIdx.z];
    const int K = args.K;
    __shared__ __align__(16) __nv_bfloat16 sA[2][128][40];
    __shared__ __align__(16) __nv_bfloat16 sB[2][64][40];

    const int tid = threadIdx.x;
    const int lane = tid & 31, wid = tid >> 5;
    const int warpM = wid & 3, warpN = wid >> 2;
    const int mBase = blockIdx.y * 128, nBase = blockIdx.x * 64;

    float acc[2][4][4];
#pragma unroll
    for (int i = 0; i < 2; i++)
#pragma unroll
        for (int j = 0; j < 4; j++)
#pragma unroll
            for (int t = 0; t < 4; t++) acc[i][j][t] = 0.f;

    const int ar = tid >> 2;          // A rows (0..63, +64); B rows (0..63)
    const int ag = (tid & 3) * 8;     // 8-elt granule within 32-col chunk

    // ldmatrix lane addresses (byte step per k16 = 32)
    uint32_t aAdH[2], aAdL[2], bAdH[2], bAdL[2];
#pragma unroll
    for (int t = 0; t < 2; t++) {
        int rA = warpM * 32 + t * 16 + (lane & 15);
        int cA = (lane >> 4) * 8;
        aAdH[t] = smem_u32(&sA[0][rA][cA]);
        aAdL[t] = smem_u32(&sA[1][rA][cA]);
        int rB = warpN * 32 + t * 16 + ((lane >> 4) << 3) + (lane & 7);
        int cB = ((lane >> 3) & 1) * 8;
        bAdH[t] = smem_u32(&sB[0][rB][cB]);
        bAdL[t] = smem_u32(&sB[1][rB][cB]);
    }

    uint4 pAh[2], pAl[2], pBh, pBl;
    const int NC = K / 32;

    // prefetch chunk 0
    {
        const int kof = ag;
        pAh[0] = *reinterpret_cast<const uint4*>(ge.ahi + (size_t)(mBase + ar) * K + kof);
        pAl[0] = *reinterpret_cast<const uint4*>(ge.alo + (size_t)(mBase + ar) * K + kof);
        pAh[1] = *reinterpret_cast<const uint4*>(ge.ahi + (size_t)(mBase + ar + 64) * K + kof);
        pAl[1] = *reinterpret_cast<const uint4*>(ge.alo + (size_t)(mBase + ar + 64) * K + kof);
        pBh    = *reinterpret_cast<const uint4*>(ge.bhi + (size_t)(nBase + ar) * K + kof);
        pBl    = *reinterpret_cast<const uint4*>(ge.blo + (size_t)(nBase + ar) * K + kof);
    }

    for (int c = 0; c < NC; c++) {
        if (c) __syncthreads();
        *reinterpret_cast<uint4*>(&sA[0][ar][ag])      = pAh[0];
        *reinterpret_cast<uint4*>(&sA[1][ar][ag])      = pAl[0];
        *reinterpret_cast<uint4*>(&sA[0][ar + 64][ag]) = pAh[1];
        *reinterpret_cast<uint4*>(&sA[1][ar + 64][ag]) = pAl[1];
        *reinterpret_cast<uint4*>(&sB[0][ar][ag])      = pBh;
        *reinterpret_cast<uint4*>(&sB[1][ar][ag])      = pBl;
        __syncthreads();

        if (c + 1 < NC) {
            const int kof = (c + 1) * 32 + ag;
            pAh[0] = *reinterpret_cast<const uint4*>(ge.ahi + (size_t)(mBase + ar) * K + kof);
            pAl[0] = *reinterpret_cast<const uint4*>(ge.alo + (size_t)(mBase + ar) * K + kof);
            pAh[1] = *reinterpret_cast<const uint4*>(ge.ahi + (size_t)(mBase + ar + 64) * K + kof);
            pAl[1] = *reinterpret_cast<const uint4*>(ge.alo + (size_t)(mBase + ar + 64) * K + kof);
            pBh    = *reinterpret_cast<const uint4*>(ge.bhi + (size_t)(nBase + ar) * K + kof);
            pBl    = *reinterpret_cast<const uint4*>(ge.blo + (size_t)(nBase + ar) * K + kof);
        }

#pragma unroll
        for (int ks = 0; ks < 2; ks++) {
            const uint32_t off = ks * 32;   // 16 bf16 = 32 bytes
            uint32_t ah[2][4], al[2][4], bh[2][4], bl[2][4];
            ldsm4(ah[0], aAdH[0] + off);  ldsm4(ah[1], aAdH[1] + off);
            ldsm4(al[0], aAdL[0] + off);  ldsm4(al[1], aAdL[1] + off);
            ldsm4(bh[0], bAdH[0] + off);  ldsm4(bh[1], bAdH[1] + off);
            ldsm4(bl[0], bAdL[0] + off);  ldsm4(bl[1], bAdL[1] + off);
#pragma unroll
            for (int i = 0; i < 2; i++)
#pragma unroll
                for (int j = 0; j < 4; j++) {
                    const uint32_t* bhp = &bh[j >> 1][(j & 1) * 2];
                    const uint32_t* blp = &bl[j >> 1][(j & 1) * 2];
                    mma16816(acc[i][j], ah[i], bhp);
                    mma16816(acc[i][j], al[i], bhp);
                    mma16816(acc[i][j], ah[i], blp);
                }
        }
    }

    // ---- epilogue ----
    const int mrow = lane >> 2, ncol = (lane & 3) * 2;
#pragma unroll
    for (int i = 0; i < 2; i++)
#pragma unroll
        for (int j = 0; j < 4; j++) {
            int m0 = mBase + warpM * 32 + i * 16 + mrow;
            int n  = nBase + warpN * 32 + j * 8 + ncol;
#pragma unroll
            for (int half = 0; half < 2; half++) {
                int m = m0 + half * 8;
                float c0 = acc[i][j][half * 2], c1 = acc[i][j][half * 2 + 1];
                if (ge.mode == 1) {
                    int srow = m & (SLEN - 1);
                    int t = (n & 63) >> 1;
                    float cz = args.fc[srow * 32 + t], sz = args.fs[srow * 32 + t];
                    float xr = c0, xi = c1;
                    c0 = xr * cz - xi * sz;
                    c1 = xr * sz + xi * cz;
                }
                if (ge.mode == 2) {
                    __nv_bfloat162 h2, l2;
                    h2.x = __float2bfloat16(c0);
                    h2.y = __float2bfloat16(c1);
                    l2.x = __float2bfloat16(c0 - __bfloat162float(h2.x));
                    l2.y = __float2bfloat16(c1 - __bfloat162float(h2.y));
                    *reinterpret_cast<__nv_bfloat162*>(&ge.yhi[(size_t)m * PROJ + n]) = h2;
                    *reinterpret_cast<__nv_bfloat162*>(&ge.ylo[(size_t)m * PROJ + n]) = l2;
                } else {
                    float2 vv = make_float2(c0, c1);
                    *reinterpret_cast<float2*>(&ge.y[(size_t)m * ge.ldy + ge.col_off + n]) = vv;
                }
            }
        }
}

// ---------------- rel[b,r,i,j] = 0.125 * qr[b,i,r,:]·kr[b,j,r,:] via HMMA --------
// CTA tile 128x64, K=64 (2 chunks of 32). Lower-triangular tiles only.
__global__ __launch_bounds__(256, 2) void rel_mma()
{
    const int mBase = blockIdx.y * 128, nBase = blockIdx.x * 64;
    if (nBase > mBase + 127) return;
    const int br = blockIdx.z;
    const int b = br >> 3, r = br & 7;

    __shared__ __align__(16) __nv_bfloat16 sA[2][128][40];
    __shared__ __align__(16) __nv_bfloat16 sB[2][64][40];

    const int tid = threadIdx.x;
    const int lane = tid & 31, wid = tid >> 5;
    const int warpM = wid & 3, warpN = wid >> 2;

    const __nv_bfloat16* Ah = g_qrhi + ((size_t)(b * SLEN + mBase)) * PROJ + r * 64;
    const __nv_bfloat16* Al = g_qrlo + ((size_t)(b * SLEN + mBase)) * PROJ + r * 64;
    const __nv_bfloat16* Bh = g_krhi + ((size_t)(b * SLEN + nBase)) * PROJ + r * 64;
    const __nv_bfloat16* Bl = g_krlo + ((size_t)(b * SLEN + nBase)) * PROJ + r * 64;

    float acc[2][4][4];
#pragma unroll
    for (int i = 0; i < 2; i++)
#pragma unroll
        for (int j = 0; j < 4; j++)
#pragma unroll
            for (int t = 0; t < 4; t++) acc[i][j][t] = 0.f;

    const int ar = tid >> 2;
    const int ag = (tid & 3) * 8;

    uint32_t aAdH[2], aAdL[2], bAdH[2], bAdL[2];
#pragma unroll
    for (int t = 0; t < 2; t++) {
        int rA = warpM * 32 + t * 16 + (lane & 15);
        int cA = (lane >> 4) * 8;
        aAdH[t] = smem_u32(&sA[0][rA][cA]);
        aAdL[t] = smem_u32(&sA[1][rA][cA]);
        int rB = warpN * 32 + t * 16 + ((lane >> 4) << 3) + (lane & 7);
        int cB = ((lane >> 3) & 1) * 8;
        bAdH[t] = smem_u32(&sB[0][rB][cB]);
        bAdL[t] = smem_u32(&sB[1][rB][cB]);
    }

    for (int c = 0; c < 2; c++) {
        const int kof = c * 32 + ag;
        uint4 v;
        if (c) __syncthreads();
        v = *reinterpret_cast<const uint4*>(Ah + (size_t)ar * PROJ + kof);
        *reinterpret_cast<uint4*>(&sA[0][ar][ag]) = v;
        v = *reinterpret_cast<const uint4*>(Al + (size_t)ar * PROJ + kof);
        *reinterpret_cast<uint4*>(&sA[1][ar][ag]) = v;
        v = *reinterpret_cast<const uint4*>(Ah + (size_t)(ar + 64) * PROJ + kof);
        *reinterpret_cast<uint4*>(&sA[0][ar + 64][ag]) = v;
        v = *reinterpret_cast<const uint4*>(Al + (size_t)(ar + 64) * PROJ + kof);
        *reinterpret_cast<uint4*>(&sA[1][ar + 64][ag]) = v;
        v = *reinterpret_cast<const uint4*>(Bh + (size_t)ar * PROJ + kof);
        *reinterpret_cast<uint4*>(&sB[0][ar][ag]) = v;
        v = *reinterpret_cast<const uint4*>(Bl + (size_t)ar * PROJ + kof);
        *reinterpret_cast<uint4*>(&sB[1][ar][ag]) = v;
        __syncthreads();

#pragma unroll
        for (int ks = 0; ks < 2; ks++) {
            const uint32_t off = ks * 32;
            uint32_t ah[2][4], al[2][4], bh[2][4], bl[2][4];
            ldsm4(ah[0], aAdH[0] + off);  ldsm4(ah[1], aAdH[1] + off);
            ldsm4(al[0], aAdL[0] + off);  ldsm4(al[1], aAdL[1] + off);
            ldsm4(bh[0], bAdH[0] + off);  ldsm4(bh[1], bAdH[1] + off);
            ldsm4(bl[0], bAdL[0] + off);  ldsm4(bl[1], bAdL[1] + off);
#pragma unroll
            for (int i = 0; i < 2; i++)
#pragma unroll
                for (int j = 0; j < 4; j++) {
                    const uint32_t* bhp = &bh[j >> 1][(j & 1) * 2];
                    const uint32_t* blp = &bl[j >> 1][(j & 1) * 2];
                    mma16816(acc[i][j], ah[i], bhp);
                    mma16816(acc[i][j], al[i], bhp);
                    mma16816(acc[i][j], ah[i], blp);
                }
        }
    }

    float* out = g_rel + ((size_t)br * SLEN + mBase) * SLEN + nBase;
    const int mrow = lane >> 2, ncol = (lane & 3) * 2;
#pragma unroll
    for (int i = 0; i < 2; i++)
#pragma unroll
        for (int j = 0; j < 4; j++) {
            int m0 = warpM * 32 + i * 16 + mrow;
            int n  = warpN * 32 + j * 8 + ncol;
#pragma unroll
            for (int half = 0; half < 2; half++) {
                int m = m0 + half * 8;
                float2 vv = make_float2(acc[i][j][half * 2] * 0.125f,
                                        acc[i][j][half * 2 + 1] * 0.125f);
                *reinterpret_cast<float2*>(&out[(size_t)m * SLEN + n]) = vv;
            }
        }
}

// ---------------- flash attention, Q-tile 64, KV-tile 32, causal -----------------
template<bool RA>
__global__ __launch_bounds__(256) void flash_kernel(
    const float* __restrict__ Q, const float* __restrict__ Kx,
    const float* __restrict__ V, const float* __restrict__ WR,
    float* __restrict__ Octx)
{
    __shared__ float Qs[64*64];
    __shared__ float Ks[32*65];   // K tile; reused as P (64x32)
    __shared__ float Vs[32*64];
    __shared__ float wrs[64*8];
    float* Ps = Ks;

    const int bh = blockIdx.y;
    const int b = bh >> 3, h = bh & 7;
    const int it = blockIdx.x;
    const int tid = threadIdx.x;
    const int tx = tid & 15, ty = tid >> 4;

#pragma unroll
    for (int u = 0; u < 16; u++) {
        int e = tid + u * 256;
        int row = e >> 6, col = e & 63;
        Qs[row*64 + col] = Q[((size_t)(b*SLEN + it*64 + row)) * PROJ + h*64 + col];
    }
    if (RA) {
        wrs[tid]       = WR[h*512 + tid];
        wrs[tid + 256] = WR[h*512 + 256 + tid];
    }
    __syncthreads();

    float o[4][4] = {};
    float ar[4][8];
    if (RA) {
#pragma unroll
        for (int i = 0; i < 4; i++)
#pragma unroll
            for (int r = 0; r < 8; r++) ar[i][r] = 0.f;
    }
    float mst[4], lst[4];
#pragma unroll
    for (int i = 0; i < 4; i++) { mst[i] = -1e30f; lst[i] = 0.f; }

    const int njt = (it + 1) * 2;
    for (int jt = 0; jt < njt; jt++) {
#pragma unroll
        for (int u = 0; u < 8; u++) {
            int e = tid + u * 256;
            int row = e >> 6, col = e & 63;
            size_t gidx = ((size_t)(b*SLEN + jt*32 + row)) * PROJ + h*64 + col;
            Ks[row*65 + col] = Kx[gidx];
            Vs[row*64 + col] = V[gidx];
        }
        __syncthreads();

        float s[4][2] = {};
#pragma unroll
        for (int d = 0; d < 64; d++) {
            float a[4], bb[2];
#pragma unroll
            for (int i = 0; i < 4; i++) a[i] = Qs[(ty*4+i)*64 + d];
            bb[0] = Ks[(tx*2+0)*65 + d];
            bb[1] = Ks[(tx*2+1)*65 + d];
#pragma unroll
            for (int i = 0; i < 4; i++) {
                s[i][0] = fmaf(a[i], bb[0], s[i][0]);
                s[i][1] = fmaf(a[i], bb[1], s[i][1]);
            }
        }
        const bool diag = (jt >= it * 2);
#pragma unroll
        for (int i = 0; i < 4; i++)
#pragma unroll
            for (int j = 0; j < 2; j++) {
                s[i][j] *= 0.125f;
                if (diag) {
                    int gi = it*64 + ty*4 + i, gj = jt*32 + tx*2 + j;
                    if (gj > gi) s[i][j] = -1e30f;
                }
            }
        float rm[4];
#pragma unroll
        for (int i = 0; i < 4; i++) rm[i] = fmaxf(s[i][0], s[i][1]);
#pragma unroll
        for (int off = 8; off >= 1; off >>= 1)
#pragma unroll
            for (int i = 0; i < 4; i++)
                rm[i] = fmaxf(rm[i], __shfl_xor_sync(0xffffffffu, rm[i], off));

        float scale[4], rs[4];
#pragma unroll
        for (int i = 0; i < 4; i++) {
            float nm = fmaxf(mst[i], rm[i]);
            scale[i] = __expf(mst[i] - nm);
            mst[i] = nm;
            s[i][0] = __expf(s[i][0] - nm);   // s becomes p
            s[i][1] = __expf(s[i][1] - nm);
            rs[i] = s[i][0] + s[i][1];
        }
#pragma unroll
        for (int off = 8; off >= 1; off >>= 1)
#pragma unroll
            for (int i = 0; i < 4; i++)
                rs[i] += __shfl_xor_sync(0xffffffffu, rs[i], off);
#pragma unroll
        for (int i = 0; i < 4; i++) {
            lst[i] = lst[i] * scale[i] + rs[i];
#pragma unroll
            for (int dd = 0; dd < 4; dd++) o[i][dd] *= scale[i];
        }

        if (RA) {
            const size_t relbase = ((size_t)(b * 8)) * SLEN * SLEN;
#pragma unroll
            for (int i = 0; i < 4; i++) {
#pragma unroll
                for (int r = 0; r < 8; r++) ar[i][r] *= scale[i];
                int gi = it*64 + ty*4 + i;
#pragma unroll
                for (int r = 0; r < 8; r++) {
                    const float2 rv = *reinterpret_cast<const float2*>(
                        &g_rel[relbase + ((size_t)r * SLEN + gi) * SLEN + jt*32 + tx*2]);
                    ar[i][r] = fmaf(s[i][0], rv.x, ar[i][r]);
                    ar[i][r] = fmaf(s[i][1], rv.y, ar[i][r]);
                }
            }
        }
        __syncthreads();              // everyone done reading Ks
#pragma unroll
        for (int i = 0; i < 4; i++) {
            Ps[(ty*4+i)*32 + tx*2 + 0] = s[i][0];
            Ps[(ty*4+i)*32 + tx*2 + 1] = s[i][1];
        }
        __syncthreads();              // P visible
#pragma unroll
        for (int j = 0; j < 32; j++) {
            float pv[4];
#pragma unroll
            for (int i = 0; i < 4; i++) pv[i] = Ps[(ty*4+i)*32 + j];
            float4 v4 = *reinterpret_cast<float4*>(&Vs[j*64 + tx*4]);
            float vv[4] = {v4.x, v4.y, v4.z, v4.w};
#pragma unroll
            for (int i = 0; i < 4; i++)
#pragma unroll
                for (int dd = 0; dd < 4; dd++)
                    o[i][dd] = fmaf(pv[i], vv[dd], o[i][dd]);
        }
        __syncthreads();              // before next K/V load
    }

    if (RA) {
#pragma unroll
        for (int off = 8; off >= 1; off >>= 1)
#pragma unroll
            for (int i = 0; i < 4; i++)
#pragma unroll
                for (int r = 0; r < 8; r++)
                    ar[i][r] += __shfl_xor_sync(0xffffffffu, ar[i][r], off);
    }
#pragma unroll
    for (int i = 0; i < 4; i++) {
        float inv = 1.f / lst[i];
        int m = b*SLEN + it*64 + ty*4 + i;
#pragma unroll
        for (int dd = 0; dd < 4; dd++) {
            int d = tx*4 + dd;
            float val = o[i][dd] * inv;
            if (RA) {
                float ro = 0.f;
#pragma unroll
                for (int r = 0; r < 8; r++)
                    ro = fmaf(ar[i][r] * inv, wrs[d*8 + r], ro);
                val += ro;
            }
            Octx[(size_t)m * PROJ + h*64 + d] = val;
        }
    }
}

// ---------------- host launcher --------------------------------------------------
extern "C" void kernel_launch(void* const* d_in, const int* in_sizes, int n_in,
                              void* d_out, int out_size)
{
    const float* x       = (const float*)d_in[0];
    const float* symbols = (const float*)d_in[1];
    const float* fc      = (const float*)d_in[2];
    const float* fs      = (const float*)d_in[3];
    const float* wsrc[10] = {
        (const float*)d_in[4],   // wq_sa
        (const float*)d_in[5],   // wk_sa
        (const float*)d_in[6],   // wv_sa
        (const float*)d_in[8],   // wq_attn
        (const float*)d_in[9],   // wk_attn
        (const float*)d_in[10],  // wq_rel
        (const float*)d_in[11],  // wk_rel
        (const float*)d_in[13],  // wv_ra
        (const float*)d_in[7],   // wo_sa
        (const float*)d_in[14],  // wo_ra
    };
    const float* wr = (const float*)d_in[12];
    float* out = (float*)d_out;

    float *q, *k, *v, *qa, *ka, *sv, *ctx;
    cudaGetSymbolAddress((void**)&q,  g_q);
    cudaGetSymbolAddress((void**)&k,  g_k);
    cudaGetSymbolAddress((void**)&v,  g_v);
    cudaGetSymbolAddress((void**)&qa, g_qa);
    cudaGetSymbolAddress((void**)&ka, g_ka);
    cudaGetSymbolAddress((void**)&sv, g_sv);
    cudaGetSymbolAddress((void**)&ctx, g_ctx);

    __nv_bfloat16 *xhi, *xlo, *shi, *slo, *whi, *wlo, *chi, *clo;
    __nv_bfloat16 *qrhi, *qrlo, *krhi, *krlo;
    cudaGetSymbolAddress((void**)&xhi, g_xhi);
    cudaGetSymbolAddress((void**)&xlo, g_xlo);
    cudaGetSymbolAddress((void**)&shi, g_shi);
    cudaGetSymbolAddress((void**)&slo, g_slo);
    cudaGetSymbolAddress((void**)&whi, g_whi);
    cudaGetSymbolAddress((void**)&wlo, g_wlo);
    cudaGetSymbolAddress((void**)&chi, g_chi);
    cudaGetSymbolAddress((void**)&clo, g_clo);
    cudaGetSymbolAddress((void**)&qrhi, g_qrhi);
    cudaGetSymbolAddress((void**)&qrlo, g_qrlo);
    cudaGetSymbolAddress((void**)&krhi, g_krhi);
    cudaGetSymbolAddress((void**)&krlo, g_krlo);

    const int wsz[10]  = { PROJ*DMODEL, PROJ*DMODEL, PROJ*DMODEL, PROJ*DMODEL, PROJ*DMODEL,
                           PROJ*DMODEL, PROJ*DMODEL, PROJ*DMODEL, PROJ*PROJ, PROJ*PROJ };
    size_t woff[10];
    { size_t o = 0; for (int i = 0; i < 10; i++) { woff[i] = o; o += wsz[i]; } }

    // splits
    {
        int n = MTOT * DMODEL;
        split_kernel<<<(n + 255) / 256, 256>>>(x, xhi, xlo, n);
        split_kernel<<<(n + 255) / 256, 256>>>(symbols, shi, slo, n);
    }
    for (int i = 0; i < 10; i++)
        split_kernel<<<(wsz[i] + 255) / 256, 256>>>(wsrc[i], whi + woff[i], wlo + woff[i], wsz[i]);

    // projection batch: z = 8 GEMMs, M=4096, N=512, K=1024
    {
        GBatch gb;
        gb.fc = fc; gb.fs = fs; gb.K = DMODEL;
        float* ys[8]   = { q, k, v, qa, ka, nullptr, nullptr, sv };
        int    modes[8]= { 1, 1, 0, 1,  1,  2,       2,       0 };
        for (int i = 0; i < 8; i++) {
            gb.e[i].ahi = (i == 7) ? shi : xhi;
            gb.e[i].alo = (i == 7) ? slo : xlo;
            gb.e[i].bhi = whi + woff[i];
            gb.e[i].blo = wlo + woff[i];
            gb.e[i].y = ys[i]; gb.e[i].ldy = PROJ; gb.e[i].col_off = 0;
            gb.e[i].mode = modes[i];
            gb.e[i].yhi = nullptr; gb.e[i].ylo = nullptr;
        }
        gb.e[5].yhi = qrhi; gb.e[5].ylo = qrlo;
        gb.e[6].yhi = krhi; gb.e[6].ylo = krlo;
        dim3 grid(PROJ / 64, MTOT / 128, 8);
        gemm_mma<<<grid, 256>>>(gb);
    }

    // rel scores (lower-triangular tiles), HMMA
    {
        dim3 grid(SLEN / 64, SLEN / 128, NBATCH * 8);
        rel_mma<<<grid, 256>>>();
    }

    // attentions
    dim3 blk(256);
    dim3 gfl(SLEN / 64, NBATCH * NHEAD);
    flash_kernel<false><<<gfl, blk>>>(q,  k,  v,  nullptr, ctx);
    flash_kernel<true ><<<gfl, blk>>>(qa, ka, sv, wr,      ctx + (size_t)MTOT * PROJ);

    // split contexts, then output projections into the two halves of out
    {
        int n = 2 * MTOT * PROJ;
        split_kernel<<<(n + 255) / 256, 256>>>(ctx, chi, clo, n);
    }
    {
        GBatch gb;
        gb.fc = fc; gb.fs = fs; gb.K = PROJ;
        gb.e[0].ahi = chi; gb.e[0].alo = clo;
        gb.e[0].bhi = whi + woff[8]; gb.e[0].blo = wlo + woff[8];
        gb.e[0].y = out; gb.e[0].ldy = DMODEL; gb.e[0].col_off = 0;   gb.e[0].mode = 0;
        gb.e[0].yhi = nullptr; gb.e[0].ylo = nullptr;
        gb.e[1] = gb.e[0];
        gb.e[1].ahi = chi + (size_t)MTOT * PROJ; gb.e[1].alo = clo + (size_t)MTOT * PROJ;
        gb.e[1].bhi = whi + woff[9]; gb.e[1].blo = wlo + woff[9];
        gb.e[1].col_off = 512;
        for (int i = 2; i < 8; i++) gb.e[i] = gb.e[0];
        dim3 grid(PROJ / 64, MTOT / 128, 2);
        gemm_mma<<<grid, 256>>>(gb);
    }
}

// round 5
// speedup vs baseline: 1.5493x; 1.0106x over previous
#include <cuda_runtime.h>
#include <cuda_bf16.h>
#include <cstdint>

#define SLEN   2048
#define NBATCH 2
#define DMODEL 1024
#define PROJ   512
#define MTOT   (NBATCH*SLEN)
#define NHEAD  8

// ---------------- scratch (device globals; no allocation allowed) ----------------
__device__ float g_q   [MTOT*PROJ];
__device__ float g_k   [MTOT*PROJ];
__device__ float g_v   [MTOT*PROJ];
__device__ float g_qa  [MTOT*PROJ];
__device__ float g_ka  [MTOT*PROJ];
__device__ float g_sv  [MTOT*PROJ];
__device__ float g_ctx [2*MTOT*PROJ];                  // sactx | ractx
__device__ float g_rel[(size_t)NBATCH*8*SLEN*SLEN];    // 268 MB

// bf16 split buffers
__device__ __nv_bfloat16 g_xhi[MTOT*DMODEL];
__device__ __nv_bfloat16 g_xlo[MTOT*DMODEL];
__device__ __nv_bfloat16 g_shi[MTOT*DMODEL];
__device__ __nv_bfloat16 g_slo[MTOT*DMODEL];
#define WTOT (8*PROJ*DMODEL + 2*PROJ*PROJ)
__device__ __nv_bfloat16 g_whi[WTOT];
__device__ __nv_bfloat16 g_wlo[WTOT];
__device__ __nv_bfloat16 g_chi[2*MTOT*PROJ];
__device__ __nv_bfloat16 g_clo[2*MTOT*PROJ];
__device__ __nv_bfloat16 g_qrhi[MTOT*PROJ];
__device__ __nv_bfloat16 g_qrlo[MTOT*PROJ];
__device__ __nv_bfloat16 g_krhi[MTOT*PROJ];
__device__ __nv_bfloat16 g_krlo[MTOT*PROJ];

// ======================= PTX helpers (baseline ISA only, sm_103-safe) ============
__device__ __forceinline__ uint32_t smem_u32(const void* p) {
    uint32_t a;
    asm("{ .reg .u64 t; cvta.to.shared.u64 t, %1; cvt.u32.u64 %0, t; }" : "=r"(a) : "l"(p));
    return a;
}
__device__ __forceinline__ void ldsm4(uint32_t* r, uint32_t a) {
    asm volatile("ldmatrix.sync.aligned.m8n8.x4.shared.b16 {%0,%1,%2,%3}, [%4];"
        : "=r"(r[0]), "=r"(r[1]), "=r"(r[2]), "=r"(r[3]) : "r"(a));
}
__device__ __forceinline__ void mma16816(float* c, const uint32_t* a, const uint32_t* b) {
    asm volatile("mma.sync.aligned.m16n8k16.row.col.f32.bf16.bf16.f32 "
        "{%0,%1,%2,%3}, {%4,%5,%6,%7}, {%8,%9}, {%0,%1,%2,%3};"
        : "+f"(c[0]), "+f"(c[1]), "+f"(c[2]), "+f"(c[3])
        : "r"(a[0]), "r"(a[1]), "r"(a[2]), "r"(a[3]), "r"(b[0]), "r"(b[1]));
}

// ---------------- fp32 -> bf16 hi/lo split ---------------------------------------
__global__ __launch_bounds__(256) void split_kernel(
    const float* __restrict__ s, __nv_bfloat16* __restrict__ hi,
    __nv_bfloat16* __restrict__ lo, int n)
{
    int i = blockIdx.x * 256 + threadIdx.x;
    if (i < n) {
        float v = s[i];
        __nv_bfloat16 h = __float2bfloat16(v);
        float r = v - __bfloat162float(h);
        hi[i] = h;
        lo[i] = __float2bfloat16(r);
    }
}

// ---------------- HMMA batched GEMM: Y[m,n] = sum_k A[m,k]*B[n,k] ----------------
// CTA tile 128x64, 8 warps (4x2) of 32x32, K-chunk 32, bf16 2-term split.
struct GEntry {
    const __nv_bfloat16 *ahi, *alo, *bhi, *blo;
    float* y;
    __nv_bfloat16 *yhi, *ylo;
    int ldy, col_off, mode;   // 0 plain fp32, 1 rope fp32, 2 bf16 split
};
struct GBatch {
    GEntry e[8];
    const float *fc, *fs;
    int K;
};

__global__ __launch_bounds__(256, 2) void gemm_mma(GBatch args)
{
    const GEntry ge = args.e[blockIdx.z];
    const int K = args.K;
    __shared__ __align__(16) __nv_bfloat16 sA[2][128][40];
    __shared__ __align__(16) __nv_bfloat16 sB[2][64][40];

    const int tid = threadIdx.x;
    const int lane = tid & 31, wid = tid >> 5;
    const int warpM = wid & 3, warpN = wid >> 2;
    const int mBase = blockIdx.y * 128, nBase = blockIdx.x * 64;

    float acc[2][4][4];
#pragma unroll
    for (int i = 0; i < 2; i++)
#pragma unroll
        for (int j = 0; j < 4; j++)
#pragma unroll
            for (int t = 0; t < 4; t++) acc[i][j][t] = 0.f;

    const int ar = tid >> 2;          // A rows (0..63, +64); B rows (0..63)
    const int ag = (tid & 3) * 8;     // 8-elt granule within 32-col chunk

    // ldmatrix lane addresses (byte step per k16 = 32)
    uint32_t aAdH[2], aAdL[2], bAdH[2], bAdL[2];
#pragma unroll
    for (int t = 0; t < 2; t++) {
        int rA = warpM * 32 + t * 16 + (lane & 15);
        int cA = (lane >> 4) * 8;
        aAdH[t] = smem_u32(&sA[0][rA][cA]);
        aAdL[t] = smem_u32(&sA[1][rA][cA]);
        int rB = warpN * 32 + t * 16 + ((lane >> 4) << 3) + (lane & 7);
        int cB = ((lane >> 3) & 1) * 8;
        bAdH[t] = smem_u32(&sB[0][rB][cB]);
        bAdL[t] = smem_u32(&sB[1][rB][cB]);
    }

    uint4 pAh[2], pAl[2], pBh, pBl;
    const int NC = K / 32;

    // prefetch chunk 0
    {
        const int kof = ag;
        pAh[0] = *reinterpret_cast<const uint4*>(ge.ahi + (size_t)(mBase + ar) * K + kof);
        pAl[0] = *reinterpret_cast<const uint4*>(ge.alo + (size_t)(mBase + ar) * K + kof);
        pAh[1] = *reinterpret_cast<const uint4*>(ge.ahi + (size_t)(mBase + ar + 64) * K + kof);
        pAl[1] = *reinterpret_cast<const uint4*>(ge.alo + (size_t)(mBase + ar + 64) * K + kof);
        pBh    = *reinterpret_cast<const uint4*>(ge.bhi + (size_t)(nBase + ar) * K + kof);
        pBl    = *reinterpret_cast<const uint4*>(ge.blo + (size_t)(nBase + ar) * K + kof);
    }

    for (int c = 0; c < NC; c++) {
        if (c) __syncthreads();
        *reinterpret_cast<uint4*>(&sA[0][ar][ag])      = pAh[0];
        *reinterpret_cast<uint4*>(&sA[1][ar][ag])      = pAl[0];
        *reinterpret_cast<uint4*>(&sA[0][ar + 64][ag]) = pAh[1];
        *reinterpret_cast<uint4*>(&sA[1][ar + 64][ag]) = pAl[1];
        *reinterpret_cast<uint4*>(&sB[0][ar][ag])      = pBh;
        *reinterpret_cast<uint4*>(&sB[1][ar][ag])      = pBl;
        __syncthreads();

        if (c + 1 < NC) {
            const int kof = (c + 1) * 32 + ag;
            pAh[0] = *reinterpret_cast<const uint4*>(ge.ahi + (size_t)(mBase + ar) * K + kof);
            pAl[0] = *reinterpret_cast<const uint4*>(ge.alo + (size_t)(mBase + ar) * K + kof);
            pAh[1] = *reinterpret_cast<const uint4*>(ge.ahi + (size_t)(mBase + ar + 64) * K + kof);
            pAl[1] = *reinterpret_cast<const uint4*>(ge.alo + (size_t)(mBase + ar + 64) * K + kof);
            pBh    = *reinterpret_cast<const uint4*>(ge.bhi + (size_t)(nBase + ar) * K + kof);
            pBl    = *reinterpret_cast<const uint4*>(ge.blo + (size_t)(nBase + ar) * K + kof);
        }

#pragma unroll
        for (int ks = 0; ks < 2; ks++) {
            const uint32_t off = ks * 32;   // 16 bf16 = 32 bytes
            uint32_t ah[2][4], al[2][4], bh[2][4], bl[2][4];
            ldsm4(ah[0], aAdH[0] + off);  ldsm4(ah[1], aAdH[1] + off);
            ldsm4(al[0], aAdL[0] + off);  ldsm4(al[1], aAdL[1] + off);
            ldsm4(bh[0], bAdH[0] + off);  ldsm4(bh[1], bAdH[1] + off);
            ldsm4(bl[0], bAdL[0] + off);  ldsm4(bl[1], bAdL[1] + off);
#pragma unroll
            for (int i = 0; i < 2; i++)
#pragma unroll
                for (int j = 0; j < 4; j++) {
                    const uint32_t* bhp = &bh[j >> 1][(j & 1) * 2];
                    const uint32_t* blp = &bl[j >> 1][(j & 1) * 2];
                    mma16816(acc[i][j], ah[i], bhp);
                    mma16816(acc[i][j], al[i], bhp);
                    mma16816(acc[i][j], ah[i], blp);
                }
        }
    }

    // ---- epilogue ----
    const int mrow = lane >> 2, ncol = (lane & 3) * 2;
#pragma unroll
    for (int i = 0; i < 2; i++)
#pragma unroll
        for (int j = 0; j < 4; j++) {
            int m0 = mBase + warpM * 32 + i * 16 + mrow;
            int n  = nBase + warpN * 32 + j * 8 + ncol;
#pragma unroll
            for (int half = 0; half < 2; half++) {
                int m = m0 + half * 8;
                float c0 = acc[i][j][half * 2], c1 = acc[i][j][half * 2 + 1];
                if (ge.mode == 1) {
                    int srow = m & (SLEN - 1);
                    int t = (n & 63) >> 1;
                    float cz = args.fc[srow * 32 + t], sz = args.fs[srow * 32 + t];
                    float xr = c0, xi = c1;
                    c0 = xr * cz - xi * sz;
                    c1 = xr * sz + xi * cz;
                }
                if (ge.mode == 2) {
                    __nv_bfloat162 h2, l2;
                    h2.x = __float2bfloat16(c0);
                    h2.y = __float2bfloat16(c1);
                    l2.x = __float2bfloat16(c0 - __bfloat162float(h2.x));
                    l2.y = __float2bfloat16(c1 - __bfloat162float(h2.y));
                    *reinterpret_cast<__nv_bfloat162*>(&ge.yhi[(size_t)m * PROJ + n]) = h2;
                    *reinterpret_cast<__nv_bfloat162*>(&ge.ylo[(size_t)m * PROJ + n]) = l2;
                } else {
                    float2 vv = make_float2(c0, c1);
                    *reinterpret_cast<float2*>(&ge.y[(size_t)m * ge.ldy + ge.col_off + n]) = vv;
                }
            }
        }
}

// ---------------- rel[b,r,i,j] = 0.125 * qr[b,i,r,:]·kr[b,j,r,:] via HMMA --------
// CTA tile 128x64, K=64 (2 chunks of 32). Lower-triangular tiles only.
__global__ __launch_bounds__(256, 2) void rel_mma()
{
    const int mBase = blockIdx.y * 128, nBase = blockIdx.x * 64;
    if (nBase > mBase + 127) return;
    const int br = blockIdx.z;
    const int b = br >> 3, r = br & 7;

    __shared__ __align__(16) __nv_bfloat16 sA[2][128][40];
    __shared__ __align__(16) __nv_bfloat16 sB[2][64][40];

    const int tid = threadIdx.x;
    const int lane = tid & 31, wid = tid >> 5;
    const int warpM = wid & 3, warpN = wid >> 2;

    const __nv_bfloat16* Ah = g_qrhi + ((size_t)(b * SLEN + mBase)) * PROJ + r * 64;
    const __nv_bfloat16* Al = g_qrlo + ((size_t)(b * SLEN + mBase)) * PROJ + r * 64;
    const __nv_bfloat16* Bh = g_krhi + ((size_t)(b * SLEN + nBase)) * PROJ + r * 64;
    const __nv_bfloat16* Bl = g_krlo + ((size_t)(b * SLEN + nBase)) * PROJ + r * 64;

    float acc[2][4][4];
#pragma unroll
    for (int i = 0; i < 2; i++)
#pragma unroll
        for (int j = 0; j < 4; j++)
#pragma unroll
            for (int t = 0; t < 4; t++) acc[i][j][t] = 0.f;

    const int ar = tid >> 2;
    const int ag = (tid & 3) * 8;

    uint32_t aAdH[2], aAdL[2], bAdH[2], bAdL[2];
#pragma unroll
    for (int t = 0; t < 2; t++) {
        int rA = warpM * 32 + t * 16 + (lane & 15);
        int cA = (lane >> 4) * 8;
        aAdH[t] = smem_u32(&sA[0][rA][cA]);
        aAdL[t] = smem_u32(&sA[1][rA][cA]);
        int rB = warpN * 32 + t * 16 + ((lane >> 4) << 3) + (lane & 7);
        int cB = ((lane >> 3) & 1) * 8;
        bAdH[t] = smem_u32(&sB[0][rB][cB]);
        bAdL[t] = smem_u32(&sB[1][rB][cB]);
    }

    for (int c = 0; c < 2; c++) {
        const int kof = c * 32 + ag;
        uint4 v;
        if (c) __syncthreads();
        v = *reinterpret_cast<const uint4*>(Ah + (size_t)ar * PROJ + kof);
        *reinterpret_cast<uint4*>(&sA[0][ar][ag]) = v;
        v = *reinterpret_cast<const uint4*>(Al + (size_t)ar * PROJ + kof);
        *reinterpret_cast<uint4*>(&sA[1][ar][ag]) = v;
        v = *reinterpret_cast<const uint4*>(Ah + (size_t)(ar + 64) * PROJ + kof);
        *reinterpret_cast<uint4*>(&sA[0][ar + 64][ag]) = v;
        v = *reinterpret_cast<const uint4*>(Al + (size_t)(ar + 64) * PROJ + kof);
        *reinterpret_cast<uint4*>(&sA[1][ar + 64][ag]) = v;
        v = *reinterpret_cast<const uint4*>(Bh + (size_t)ar * PROJ + kof);
        *reinterpret_cast<uint4*>(&sB[0][ar][ag]) = v;
        v = *reinterpret_cast<const uint4*>(Bl + (size_t)ar * PROJ + kof);
        *reinterpret_cast<uint4*>(&sB[1][ar][ag]) = v;
        __syncthreads();

#pragma unroll
        for (int ks = 0; ks < 2; ks++) {
            const uint32_t off = ks * 32;
            uint32_t ah[2][4], al[2][4], bh[2][4], bl[2][4];
            ldsm4(ah[0], aAdH[0] + off);  ldsm4(ah[1], aAdH[1] + off);
            ldsm4(al[0], aAdL[0] + off);  ldsm4(al[1], aAdL[1] + off);
            ldsm4(bh[0], bAdH[0] + off);  ldsm4(bh[1], bAdH[1] + off);
            ldsm4(bl[0], bAdL[0] + off);  ldsm4(bl[1], bAdL[1] + off);
#pragma unroll
            for (int i = 0; i < 2; i++)
#pragma unroll
                for (int j = 0; j < 4; j++) {
                    const uint32_t* bhp = &bh[j >> 1][(j & 1) * 2];
                    const uint32_t* blp = &bl[j >> 1][(j & 1) * 2];
                    mma16816(acc[i][j], ah[i], bhp);
                    mma16816(acc[i][j], al[i], bhp);
                    mma16816(acc[i][j], ah[i], blp);
                }
        }
    }

    float* out = g_rel + ((size_t)br * SLEN + mBase) * SLEN + nBase;
    const int mrow = lane >> 2, ncol = (lane & 3) * 2;
#pragma unroll
    for (int i = 0; i < 2; i++)
#pragma unroll
        for (int j = 0; j < 4; j++) {
            int m0 = warpM * 32 + i * 16 + mrow;
            int n  = warpN * 32 + j * 8 + ncol;
#pragma unroll
            for (int half = 0; half < 2; half++) {
                int m = m0 + half * 8;
                float2 vv = make_float2(acc[i][j][half * 2] * 0.125f,
                                        acc[i][j][half * 2 + 1] * 0.125f);
                *reinterpret_cast<float2*>(&out[(size_t)m * SLEN + n]) = vv;
            }
        }
}

// ---------------- flash attention, Q-tile 64, KV-tile 32, causal -----------------
template<bool RA>
__global__ __launch_bounds__(256) void flash_kernel(
    const float* __restrict__ Q, const float* __restrict__ Kx,
    const float* __restrict__ V, const float* __restrict__ WR,
    float* __restrict__ Octx)
{
    __shared__ float Qs[64*64];
    __shared__ float Ks[32*65];   // K tile; reused as P (64x32)
    __shared__ float Vs[32*64];
    __shared__ float wrs[64*8];
    float* Ps = Ks;

    const int bh = blockIdx.y;
    const int b = bh >> 3, h = bh & 7;
    const int it = blockIdx.x;
    const int tid = threadIdx.x;
    const int tx = tid & 15, ty = tid >> 4;

#pragma unroll
    for (int u = 0; u < 16; u++) {
        int e = tid + u * 256;
        int row = e >> 6, col = e & 63;
        Qs[row*64 + col] = Q[((size_t)(b*SLEN + it*64 + row)) * PROJ + h*64 + col];
    }
    if (RA) {
        wrs[tid]       = WR[h*512 + tid];
        wrs[tid + 256] = WR[h*512 + 256 + tid];
    }
    __syncthreads();

    float o[4][4] = {};
    float ar[4][8];
    if (RA) {
#pragma unroll
        for (int i = 0; i < 4; i++)
#pragma unroll
            for (int r = 0; r < 8; r++) ar[i][r] = 0.f;
    }
    float mst[4], lst[4];
#pragma unroll
    for (int i = 0; i < 4; i++) { mst[i] = -1e30f; lst[i] = 0.f; }

    const int njt = (it + 1) * 2;
    for (int jt = 0; jt < njt; jt++) {
#pragma unroll
        for (int u = 0; u < 8; u++) {
            int e = tid + u * 256;
            int row = e >> 6, col = e & 63;
            size_t gidx = ((size_t)(b*SLEN + jt*32 + row)) * PROJ + h*64 + col;
            Ks[row*65 + col] = Kx[gidx];
            Vs[row*64 + col] = V[gidx];
        }
        __syncthreads();

        float s[4][2] = {};
#pragma unroll
        for (int d = 0; d < 64; d++) {
            float a[4], bb[2];
#pragma unroll
            for (int i = 0; i < 4; i++) a[i] = Qs[(ty*4+i)*64 + d];
            bb[0] = Ks[(tx*2+0)*65 + d];
            bb[1] = Ks[(tx*2+1)*65 + d];
#pragma unroll
            for (int i = 0; i < 4; i++) {
                s[i][0] = fmaf(a[i], bb[0], s[i][0]);
                s[i][1] = fmaf(a[i], bb[1], s[i][1]);
            }
        }
        const bool diag = (jt >= it * 2);
#pragma unroll
        for (int i = 0; i < 4; i++)
#pragma unroll
            for (int j = 0; j < 2; j++) {
                s[i][j] *= 0.125f;
                if (diag) {
                    int gi = it*64 + ty*4 + i, gj = jt*32 + tx*2 + j;
                    if (gj > gi) s[i][j] = -1e30f;
                }
            }
        float rm[4];
#pragma unroll
        for (int i = 0; i < 4; i++) rm[i] = fmaxf(s[i][0], s[i][1]);
#pragma unroll
        for (int off = 8; off >= 1; off >>= 1)
#pragma unroll
            for (int i = 0; i < 4; i++)
                rm[i] = fmaxf(rm[i], __shfl_xor_sync(0xffffffffu, rm[i], off));

        float scale[4], rs[4];
#pragma unroll
        for (int i = 0; i < 4; i++) {
            float nm = fmaxf(mst[i], rm[i]);
            scale[i] = __expf(mst[i] - nm);
            mst[i] = nm;
            s[i][0] = __expf(s[i][0] - nm);   // s becomes p
            s[i][1] = __expf(s[i][1] - nm);
            rs[i] = s[i][0] + s[i][1];
        }
#pragma unroll
        for (int off = 8; off >= 1; off >>= 1)
#pragma unroll
            for (int i = 0; i < 4; i++)
                rs[i] += __shfl_xor_sync(0xffffffffu, rs[i], off);
#pragma unroll
        for (int i = 0; i < 4; i++) {
            lst[i] = lst[i] * scale[i] + rs[i];
#pragma unroll
            for (int dd = 0; dd < 4; dd++) o[i][dd] *= scale[i];
        }

        if (RA) {
            const size_t relbase = ((size_t)(b * 8)) * SLEN * SLEN;
#pragma unroll
            for (int i = 0; i < 4; i++) {
#pragma unroll
                for (int r = 0; r < 8; r++) ar[i][r] *= scale[i];
                int gi = it*64 + ty*4 + i;
#pragma unroll
                for (int r = 0; r < 8; r++) {
                    const float2 rv = *reinterpret_cast<const float2*>(
                        &g_rel[relbase + ((size_t)r * SLEN + gi) * SLEN + jt*32 + tx*2]);
                    ar[i][r] = fmaf(s[i][0], rv.x, ar[i][r]);
                    ar[i][r] = fmaf(s[i][1], rv.y, ar[i][r]);
                }
            }
        }
        __syncthreads();              // everyone done reading Ks
#pragma unroll
        for (int i = 0; i < 4; i++) {
            Ps[(ty*4+i)*32 + tx*2 + 0] = s[i][0];
            Ps[(ty*4+i)*32 + tx*2 + 1] = s[i][1];
        }
        __syncthreads();              // P visible
#pragma unroll
        for (int j = 0; j < 32; j++) {
            float pv[4];
#pragma unroll
            for (int i = 0; i < 4; i++) pv[i] = Ps[(ty*4+i)*32 + j];
            float4 v4 = *reinterpret_cast<float4*>(&Vs[j*64 + tx*4]);
            float vv[4] = {v4.x, v4.y, v4.z, v4.w};
#pragma unroll
            for (int i = 0; i < 4; i++)
#pragma unroll
                for (int dd = 0; dd < 4; dd++)
                    o[i][dd] = fmaf(pv[i], vv[dd], o[i][dd]);
        }
        __syncthreads();              // before next K/V load
    }

    if (RA) {
#pragma unroll
        for (int off = 8; off >= 1; off >>= 1)
#pragma unroll
            for (int i = 0; i < 4; i++)
#pragma unroll
                for (int r = 0; r < 8; r++)
                    ar[i][r] += __shfl_xor_sync(0xffffffffu, ar[i][r], off);
    }
#pragma unroll
    for (int i = 0; i < 4; i++) {
        float inv = 1.f / lst[i];
        int m = b*SLEN + it*64 + ty*4 + i;
#pragma unroll
        for (int dd = 0; dd < 4; dd++) {
            int d = tx*4 + dd;
            float val = o[i][dd] * inv;
            if (RA) {
                float ro = 0.f;
#pragma unroll
                for (int r = 0; r < 8; r++)
                    ro = fmaf(ar[i][r] * inv, wrs[d*8 + r], ro);
                val += ro;
            }
            Octx[(size_t)m * PROJ + h*64 + d] = val;
        }
    }
}

// ---------------- host launcher --------------------------------------------------
extern "C" void kernel_launch(void* const* d_in, const int* in_sizes, int n_in,
                              void* d_out, int out_size)
{
    const float* x       = (const float*)d_in[0];
    const float* symbols = (const float*)d_in[1];
    const float* fc      = (const float*)d_in[2];
    const float* fs      = (const float*)d_in[3];
    const float* wsrc[10] = {
        (const float*)d_in[4],   // wq_sa
        (const float*)d_in[5],   // wk_sa
        (const float*)d_in[6],   // wv_sa
        (const float*)d_in[8],   // wq_attn
        (const float*)d_in[9],   // wk_attn
        (const float*)d_in[10],  // wq_rel
        (const float*)d_in[11],  // wk_rel
        (const float*)d_in[13],  // wv_ra
        (const float*)d_in[7],   // wo_sa
        (const float*)d_in[14],  // wo_ra
    };
    const float* wr = (const float*)d_in[12];
    float* out = (float*)d_out;

    float *q, *k, *v, *qa, *ka, *sv, *ctx;
    cudaGetSymbolAddress((void**)&q,  g_q);
    cudaGetSymbolAddress((void**)&k,  g_k);
    cudaGetSymbolAddress((void**)&v,  g_v);
    cudaGetSymbolAddress((void**)&qa, g_qa);
    cudaGetSymbolAddress((void**)&ka, g_ka);
    cudaGetSymbolAddress((void**)&sv, g_sv);
    cudaGetSymbolAddress((void**)&ctx, g_ctx);

    __nv_bfloat16 *xhi, *xlo, *shi, *slo, *whi, *wlo, *chi, *clo;
    __nv_bfloat16 *qrhi, *qrlo, *krhi, *krlo;
    cudaGetSymbolAddress((void**)&xhi, g_xhi);
    cudaGetSymbolAddress((void**)&xlo, g_xlo);
    cudaGetSymbolAddress((void**)&shi, g_shi);
    cudaGetSymbolAddress((void**)&slo, g_slo);
    cudaGetSymbolAddress((void**)&whi, g_whi);
    cudaGetSymbolAddress((void**)&wlo, g_wlo);
    cudaGetSymbolAddress((void**)&chi, g_chi);
    cudaGetSymbolAddress((void**)&clo, g_clo);
    cudaGetSymbolAddress((void**)&qrhi, g_qrhi);
    cudaGetSymbolAddress((void**)&qrlo, g_qrlo);
    cudaGetSymbolAddress((void**)&krhi, g_krhi);
    cudaGetSymbolAddress((void**)&krlo, g_krlo);

    const int wsz[10]  = { PROJ*DMODEL, PROJ*DMODEL, PROJ*DMODEL, PROJ*DMODEL, PROJ*DMODEL,
                           PROJ*DMODEL, PROJ*DMODEL, PROJ*DMODEL, PROJ*PROJ, PROJ*PROJ };
    size_t woff[10];
    { size_t o = 0; for (int i = 0; i < 10; i++) { woff[i] = o; o += wsz[i]; } }

    // splits
    {
        int n = MTOT * DMODEL;
        split_kernel<<<(n + 255) / 256, 256>>>(x, xhi, xlo, n);
        split_kernel<<<(n + 255) / 256, 256>>>(symbols, shi, slo, n);
    }
    for (int i = 0; i < 10; i++)
        split_kernel<<<(wsz[i] + 255) / 256, 256>>>(wsrc[i], whi + woff[i], wlo + woff[i], wsz[i]);

    // projection batch: z = 8 GEMMs, M=4096, N=512, K=1024
    {
        GBatch gb;
        gb.fc = fc; gb.fs = fs; gb.K = DMODEL;
        float* ys[8]   = { q, k, v, qa, ka, nullptr, nullptr, sv };
        int    modes[8]= { 1, 1, 0, 1,  1,  2,       2,       0 };
        for (int i = 0; i < 8; i++) {
            gb.e[i].ahi = (i == 7) ? shi : xhi;
            gb.e[i].alo = (i == 7) ? slo : xlo;
            gb.e[i].bhi = whi + woff[i];
            gb.e[i].blo = wlo + woff[i];
            gb.e[i].y = ys[i]; gb.e[i].ldy = PROJ; gb.e[i].col_off = 0;
            gb.e[i].mode = modes[i];
            gb.e[i].yhi = nullptr; gb.e[i].ylo = nullptr;
        }
        gb.e[5].yhi = qrhi; gb.e[5].ylo = qrlo;
        gb.e[6].yhi = krhi; gb.e[6].ylo = krlo;
        dim3 grid(PROJ / 64, MTOT / 128, 8);
        gemm_mma<<<grid, 256>>>(gb);
    }

    // rel scores (lower-triangular tiles), HMMA
    {
        dim3 grid(SLEN / 64, SLEN / 128, NBATCH * 8);
        rel_mma<<<grid, 256>>>();
    }

    // attentions
    dim3 blk(256);
    dim3 gfl(SLEN / 64, NBATCH * NHEAD);
    flash_kernel<false><<<gfl, blk>>>(q,  k,  v,  nullptr, ctx);
    flash_kernel<true ><<<gfl, blk>>>(qa, ka, sv, wr,      ctx + (size_t)MTOT * PROJ);

    // split contexts, then output projections into the two halves of out
    {
        int n = 2 * MTOT * PROJ;
        split_kernel<<<(n + 255) / 256, 256>>>(ctx, chi, clo, n);
    }
    {
        GBatch gb;
        gb.fc = fc; gb.fs = fs; gb.K = PROJ;
        gb.e[0].ahi = chi; gb.e[0].alo = clo;
        gb.e[0].bhi = whi + woff[8]; gb.e[0].blo = wlo + woff[8];
        gb.e[0].y = out; gb.e[0].ldy = DMODEL; gb.e[0].col_off = 0;   gb.e[0].mode = 0;
        gb.e[0].yhi = nullptr; gb.e[0].ylo = nullptr;
        gb.e[1] = gb.e[0];
        gb.e[1].ahi = chi + (size_t)MTOT * PROJ; gb.e[1].alo = clo + (size_t)MTOT * PROJ;
        gb.e[1].bhi = whi + woff[9]; gb.e[1].blo = wlo + woff[9];
        gb.e[1].col_off = 512;
        for (int i = 2; i < 8; i++) gb.e[i] = gb.e[0];
        dim3 grid(PROJ / 64, MTOT / 128, 2);
        gemm_mma<<<grid, 256>>>(gb);
    }
}

// round 11
// speedup vs baseline: 2.3031x; 1.4865x over previous
#include <cuda_runtime.h>
#include <cuda_bf16.h>
#include <cstdint>

#define SLEN   2048
#define NBATCH 2
#define DMODEL 1024
#define PROJ   512
#define MTOT   (NBATCH*SLEN)

__device__ float g_rel[(size_t)NBATCH*8*SLEN*SLEN];

__device__ __nv_bfloat16 g_xhi[MTOT*DMODEL],  g_xlo[MTOT*DMODEL];
__device__ __nv_bfloat16 g_shi[MTOT*DMODEL],  g_slo[MTOT*DMODEL];
#define WTOT (8*PROJ*DMODEL + 2*PROJ*PROJ)
__device__ __nv_bfloat16 g_whi[WTOT], g_wlo[WTOT];
__device__ __nv_bfloat16 g_chi[2*MTOT*PROJ], g_clo[2*MTOT*PROJ];
__device__ __nv_bfloat16 g_qhi [MTOT*PROJ], g_qlo [MTOT*PROJ];
__device__ __nv_bfloat16 g_khi [MTOT*PROJ], g_klo [MTOT*PROJ];
__device__ __nv_bfloat16 g_qahi[MTOT*PROJ], g_qalo[MTOT*PROJ];
__device__ __nv_bfloat16 g_kahi[MTOT*PROJ], g_kalo[MTOT*PROJ];
__device__ __nv_bfloat16 g_vhi [MTOT*PROJ], g_vlo [MTOT*PROJ];
__device__ __nv_bfloat16 g_svhi[MTOT*PROJ], g_svlo[MTOT*PROJ];
__device__ __nv_bfloat16 g_qrhi[MTOT*PROJ], g_qrlo[MTOT*PROJ];
__device__ __nv_bfloat16 g_krhi[MTOT*PROJ], g_krlo[MTOT*PROJ];

__device__ __forceinline__ uint32_t smem_u32(const void* p) {
    uint32_t a;
    asm("{ .reg .u64 t; cvta.to.shared.u64 t, %1; cvt.u32.u64 %0, t; }" : "=r"(a) : "l"(p));
    return a;
}
__device__ __forceinline__ void ldsm4(uint32_t* r, uint32_t a) {
    asm volatile("ldmatrix.sync.aligned.m8n8.x4.shared.b16 {%0,%1,%2,%3}, [%4];"
        : "=r"(r[0]), "=r"(r[1]), "=r"(r[2]), "=r"(r[3]) : "r"(a));
}
__device__ __forceinline__ void ldsm4t(uint32_t* r, uint32_t a) {
    asm volatile("ldmatrix.sync.aligned.m8n8.x4.trans.shared.b16 {%0,%1,%2,%3}, [%4];"
        : "=r"(r[0]), "=r"(r[1]), "=r"(r[2]), "=r"(r[3]) : "r"(a));
}
__device__ __forceinline__ void mma16816(float* c, const uint32_t* a, const uint32_t* b) {
    asm volatile("mma.sync.aligned.m16n8k16.row.col.f32.bf16.bf16.f32 "
        "{%0,%1,%2,%3}, {%4,%5,%6,%7}, {%8,%9}, {%0,%1,%2,%3};"
        : "+f"(c[0]), "+f"(c[1]), "+f"(c[2]), "+f"(c[3])
        : "r"(a[0]), "r"(a[1]), "r"(a[2]), "r"(a[3]), "r"(b[0]), "r"(b[1]));
}
__device__ __forceinline__ uint32_t cvt2hi(float a, float b) {
    __nv_bfloat162 h; h.x = __float2bfloat16(a); h.y = __float2bfloat16(b);
    return *reinterpret_cast<uint32_t*>(&h);
}
__device__ __forceinline__ uint32_t cvt2lo(float a, float b, uint32_t hp) {
    __nv_bfloat162 h = *reinterpret_cast<__nv_bfloat162*>(&hp);
    return cvt2hi(a - __bfloat162float(h.x), b - __bfloat162float(h.y));
}
#define BARG(id) asm volatile("bar.sync %0, 128;" :: "r"(id))

__global__ __launch_bounds__(256) void split_kernel(
    const float* __restrict__ s, __nv_bfloat16* __restrict__ hi,
    __nv_bfloat16* __restrict__ lo, int n)
{
    int i = blockIdx.x * 256 + threadIdx.x;
    if (i < n) {
        float v = s[i];
        __nv_bfloat16 h = __float2bfloat16(v);
        hi[i] = h;
        lo[i] = __float2bfloat16(v - __bfloat162float(h));
    }
}

// ------------- HMMA batched GEMM; modes: 0 fp32, 2 split, 3 rope+split, 4 rope+scale+split
struct GEntry {
    const __nv_bfloat16 *ahi, *alo, *bhi, *blo;
    float* y;
    __nv_bfloat16 *yhi, *ylo;
    int ldy, col_off, mode;
};
struct GBatch { GEntry e[8]; const float *fc, *fs; int K; };

__global__ __launch_bounds__(256, 2) void gemm_mma(GBatch args)
{
    const GEntry ge = args.e[blockIdx.z];
    const int K = args.K;
    __shared__ __align__(16) __nv_bfloat16 sA[2][128][40];
    __shared__ __align__(16) __nv_bfloat16 sB[2][64][40];

    const int tid = threadIdx.x, lane = tid & 31, wid = tid >> 5;
    const int warpM = wid & 3, warpN = wid >> 2;
    const int mBase = blockIdx.y * 128, nBase = blockIdx.x * 64;

    float acc[2][4][4];
#pragma unroll
    for (int i = 0; i < 2; i++)
#pragma unroll
        for (int j = 0; j < 4; j++)
#pragma unroll
            for (int t = 0; t < 4; t++) acc[i][j][t] = 0.f;

    const int ar = tid >> 2, ag = (tid & 3) * 8;

    uint32_t aAdH[2], aAdL[2], bAdH[2], bAdL[2];
#pragma unroll
    for (int t = 0; t < 2; t++) {
        int rA = warpM * 32 + t * 16 + (lane & 15), cA = (lane >> 4) * 8;
        aAdH[t] = smem_u32(&sA[0][rA][cA]);
        aAdL[t] = smem_u32(&sA[1][rA][cA]);
        int rB = warpN * 32 + t * 16 + ((lane >> 4) << 3) + (lane & 7);
        int cB = ((lane >> 3) & 1) * 8;
        bAdH[t] = smem_u32(&sB[0][rB][cB]);
        bAdL[t] = smem_u32(&sB[1][rB][cB]);
    }

    uint4 pAh[2], pAl[2], pBh, pBl;
    const int NC = K / 32;
    {
        pAh[0] = *reinterpret_cast<const uint4*>(ge.ahi + (size_t)(mBase + ar) * K + ag);
        pAl[0] = *reinterpret_cast<const uint4*>(ge.alo + (size_t)(mBase + ar) * K + ag);
        pAh[1] = *reinterpret_cast<const uint4*>(ge.ahi + (size_t)(mBase + ar + 64) * K + ag);
        pAl[1] = *reinterpret_cast<const uint4*>(ge.alo + (size_t)(mBase + ar + 64) * K + ag);
        pBh    = *reinterpret_cast<const uint4*>(ge.bhi + (size_t)(nBase + ar) * K + ag);
        pBl    = *reinterpret_cast<const uint4*>(ge.blo + (size_t)(nBase + ar) * K + ag);
    }

    for (int c = 0; c < NC; c++) {
        if (c) __syncthreads();
        *reinterpret_cast<uint4*>(&sA[0][ar][ag])      = pAh[0];
        *reinterpret_cast<uint4*>(&sA[1][ar][ag])      = pAl[0];
        *reinterpret_cast<uint4*>(&sA[0][ar + 64][ag]) = pAh[1];
        *reinterpret_cast<uint4*>(&sA[1][ar + 64][ag]) = pAl[1];
        *reinterpret_cast<uint4*>(&sB[0][ar][ag])      = pBh;
        *reinterpret_cast<uint4*>(&sB[1][ar][ag])      = pBl;
        __syncthreads();
        if (c + 1 < NC) {
            const int kof = (c + 1) * 32 + ag;
            pAh[0] = *reinterpret_cast<const uint4*>(ge.ahi + (size_t)(mBase + ar) * K + kof);
            pAl[0] = *reinterpret_cast<const uint4*>(ge.alo + (size_t)(mBase + ar) * K + kof);
            pAh[1] = *reinterpret_cast<const uint4*>(ge.ahi + (size_t)(mBase + ar + 64) * K + kof);
            pAl[1] = *reinterpret_cast<const uint4*>(ge.alo + (size_t)(mBase + ar + 64) * K + kof);
            pBh    = *reinterpret_cast<const uint4*>(ge.bhi + (size_t)(nBase + ar) * K + kof);
            pBl    = *reinterpret_cast<const uint4*>(ge.blo + (size_t)(nBase + ar) * K + kof);
        }
#pragma unroll
        for (int ks = 0; ks < 2; ks++) {
            const uint32_t off = ks * 32;
            uint32_t ah[2][4], al[2][4], bh[2][4], bl[2][4];
            ldsm4(ah[0], aAdH[0] + off);  ldsm4(ah[1], aAdH[1] + off);
            ldsm4(al[0], aAdL[0] + off);  ldsm4(al[1], aAdL[1] + off);
            ldsm4(bh[0], bAdH[0] + off);  ldsm4(bh[1], bAdH[1] + off);
            ldsm4(bl[0], bAdL[0] + off);  ldsm4(bl[1], bAdL[1] + off);
#pragma unroll
            for (int i = 0; i < 2; i++)
#pragma unroll
                for (int j = 0; j < 4; j++) {
                    const uint32_t* bhp = &bh[j >> 1][(j & 1) * 2];
                    const uint32_t* blp = &bl[j >> 1][(j & 1) * 2];
                    mma16816(acc[i][j], ah[i], bhp);
                    mma16816(acc[i][j], al[i], bhp);
                    mma16816(acc[i][j], ah[i], blp);
                }
        }
    }

    const int mrow = lane >> 2, ncol = (lane & 3) * 2;
#pragma unroll
    for (int i = 0; i < 2; i++)
#pragma unroll
        for (int j = 0; j < 4; j++) {
            int m0 = mBase + warpM * 32 + i * 16 + mrow;
            int n  = nBase + warpN * 32 + j * 8 + ncol;
#pragma unroll
            for (int half = 0; half < 2; half++) {
                int m = m0 + half * 8;
                float c0 = acc[i][j][half * 2], c1 = acc[i][j][half * 2 + 1];
                if (ge.mode >= 3) {
                    int srow = m & (SLEN - 1);
                    int t = (n & 63) >> 1;
                    float cz = args.fc[srow * 32 + t], sz = args.fs[srow * 32 + t];
                    float xr = c0, xi = c1;
                    c0 = xr * cz - xi * sz;
                    c1 = xr * sz + xi * cz;
                }
                if (ge.mode == 4) { c0 *= 0.125f; c1 *= 0.125f; }
                if (ge.mode == 0) {
                    *reinterpret_cast<float2*>(&ge.y[(size_t)m * ge.ldy + ge.col_off + n]) =
                        make_float2(c0, c1);
                } else {
                    uint32_t hp = cvt2hi(c0, c1), lp = cvt2lo(c0, c1, hp);
                    *reinterpret_cast<uint32_t*>(&ge.yhi[(size_t)m * PROJ + n]) = hp;
                    *reinterpret_cast<uint32_t*>(&ge.ylo[(size_t)m * PROJ + n]) = lp;
                }
            }
        }
}

// ------------- rel[b,r,i,j] = 0.125 * qr·kr, lower-triangular tiles --------------
__global__ __launch_bounds__(256, 2) void rel_mma()
{
    const int mBase = blockIdx.y * 128, nBase = blockIdx.x * 64;
    if (nBase > mBase + 127) return;
    const int br = blockIdx.z, b = br >> 3, r = br & 7;

    __shared__ __align__(16) __nv_bfloat16 sA[2][128][40];
    __shared__ __align__(16) __nv_bfloat16 sB[2][64][40];
    const int tid = threadIdx.x, lane = tid & 31, wid = tid >> 5;
    const int warpM = wid & 3, warpN = wid >> 2;

    const __nv_bfloat16* Ah = g_qrhi + ((size_t)(b * SLEN + mBase)) * PROJ + r * 64;
    const __nv_bfloat16* Al = g_qrlo + ((size_t)(b * SLEN + mBase)) * PROJ + r * 64;
    const __nv_bfloat16* Bh = g_krhi + ((size_t)(b * SLEN + nBase)) * PROJ + r * 64;
    const __nv_bfloat16* Bl = g_krlo + ((size_t)(b * SLEN + nBase)) * PROJ + r * 64;

    float acc[2][4][4];
#pragma unroll
    for (int i = 0; i < 2; i++)
#pragma unroll
        for (int j = 0; j < 4; j++)
#pragma unroll
            for (int t = 0; t < 4; t++) acc[i][j][t] = 0.f;

    const int ar = tid >> 2, ag = (tid & 3) * 8;
    uint32_t aAdH[2], aAdL[2], bAdH[2], bAdL[2];
#pragma unroll
    for (int t = 0; t < 2; t++) {
        int rA = warpM * 32 + t * 16 + (lane & 15), cA = (lane >> 4) * 8;
        aAdH[t] = smem_u32(&sA[0][rA][cA]);
        aAdL[t] = smem_u32(&sA[1][rA][cA]);
        int rB = warpN * 32 + t * 16 + ((lane >> 4) << 3) + (lane & 7);
        int cB = ((lane >> 3) & 1) * 8;
        bAdH[t] = smem_u32(&sB[0][rB][cB]);
        bAdL[t] = smem_u32(&sB[1][rB][cB]);
    }

    for (int c = 0; c < 2; c++) {
        const int kof = c * 32 + ag;
        if (c) __syncthreads();
        *reinterpret_cast<uint4*>(&sA[0][ar][ag])      = *reinterpret_cast<const uint4*>(Ah + (size_t)ar * PROJ + kof);
        *reinterpret_cast<uint4*>(&sA[1][ar][ag])      = *reinterpret_cast<const uint4*>(Al + (size_t)ar * PROJ + kof);
        *reinterpret_cast<uint4*>(&sA[0][ar + 64][ag]) = *reinterpret_cast<const uint4*>(Ah + (size_t)(ar + 64) * PROJ + kof);
        *reinterpret_cast<uint4*>(&sA[1][ar + 64][ag]) = *reinterpret_cast<const uint4*>(Al + (size_t)(ar + 64) * PROJ + kof);
        *reinterpret_cast<uint4*>(&sB[0][ar][ag])      = *reinterpret_cast<const uint4*>(Bh + (size_t)ar * PROJ + kof);
        *reinterpret_cast<uint4*>(&sB[1][ar][ag])      = *reinterpret_cast<const uint4*>(Bl + (size_t)ar * PROJ + kof);
        __syncthreads();
#pragma unroll
        for (int ks = 0; ks < 2; ks++) {
            const uint32_t off = ks * 32;
            uint32_t ah[2][4], al[2][4], bh[2][4], bl[2][4];
            ldsm4(ah[0], aAdH[0] + off);  ldsm4(ah[1], aAdH[1] + off);
            ldsm4(al[0], aAdL[0] + off);  ldsm4(al[1], aAdL[1] + off);
            ldsm4(bh[0], bAdH[0] + off);  ldsm4(bh[1], bAdH[1] + off);
            ldsm4(bl[0], bAdL[0] + off);  ldsm4(bl[1], bAdL[1] + off);
#pragma unroll
            for (int i = 0; i < 2; i++)
#pragma unroll
                for (int j = 0; j < 4; j++) {
                    const uint32_t* bhp = &bh[j >> 1][(j & 1) * 2];
                    const uint32_t* blp = &bl[j >> 1][(j & 1) * 2];
                    mma16816(acc[i][j], ah[i], bhp);
                    mma16816(acc[i][j], al[i], bhp);
                    mma16816(acc[i][j], ah[i], blp);
                }
        }
    }

    float* out = g_rel + ((size_t)br * SLEN + mBase) * SLEN + nBase;
    const int mrow = lane >> 2, ncol = (lane & 3) * 2;
#pragma unroll
    for (int i = 0; i < 2; i++)
#pragma unroll
        for (int j = 0; j < 4; j++) {
            int m0 = warpM * 32 + i * 16 + mrow;
            int n  = warpN * 32 + j * 8 + ncol;
#pragma unroll
            for (int half = 0; half < 2; half++)
                *reinterpret_cast<float2*>(&out[(size_t)(m0 + half * 8) * SLEN + n]) =
                    make_float2(acc[i][j][half * 2] * 0.125f, acc[i][j][half * 2 + 1] * 0.125f);
        }
}

// ------------- HMMA flash attention: 64x64 tiles, split-KV warp groups -----------
// Per-group smem plane (bf16 elements): Kh @0, Kl @4608, Vh @9216, Vl @13824.
// ldmatrix reads lo planes at +9216 BYTES (= +4608 elements).
template<bool RA>
__global__ __launch_bounds__(256) void flash_mma(
    const __nv_bfloat16* __restrict__ Qh_, const __nv_bfloat16* __restrict__ Ql_,
    const __nv_bfloat16* __restrict__ Kh_, const __nv_bfloat16* __restrict__ Kl_,
    const __nv_bfloat16* __restrict__ Vh_, const __nv_bfloat16* __restrict__ Vl_,
    const float* __restrict__ WR,
    __nv_bfloat16* __restrict__ Ohi, __nv_bfloat16* __restrict__ Olo)
{
    extern __shared__ char smraw[];
    __nv_bfloat16* sm = (__nv_bfloat16*)smraw;
    const int bh = blockIdx.y, b = bh >> 3, h = bh & 7, it = blockIdx.x;
    const int tid = threadIdx.x, lane = tid & 31, wid = tid >> 5;
    const int grp = wid >> 2, wq = wid & 3;
    __nv_bfloat16* sKh = sm + grp * 18432;
    __nv_bfloat16* sVh = sKh + 9216;
    float* wrs = (float*)(smraw + 73728);
    float* mO  = (float*)(sm + 18432);   // merge region = group-1 buffers
    float* mAr = mO + 4096;
    float* mSt = mAr + 512;

    // stage Q (hi @0, lo @4608 elements)
#pragma unroll
    for (int u = 0; u < 2; u++) {
        int e = tid + u * 256, row = e >> 3, gg = e & 7;
        size_t gq = ((size_t)(b * SLEN + it * 64 + row)) * PROJ + h * 64 + gg * 8;
        *reinterpret_cast<uint4*>(&sm[row * 72 + gg * 8])        = *reinterpret_cast<const uint4*>(&Qh_[gq]);
        *reinterpret_cast<uint4*>(&sm[4608 + row * 72 + gg * 8]) = *reinterpret_cast<const uint4*>(&Ql_[gq]);
    }
    if (RA) { wrs[tid] = WR[h * 512 + tid]; wrs[256 + tid] = WR[h * 512 + 256 + tid]; }
    __syncthreads();
    uint32_t qh[4][4], ql[4][4];
    {
        uint32_t ah = smem_u32(&sm[(wq * 16 + (lane & 15)) * 72 + (lane >> 4) * 8]);
#pragma unroll
        for (int ks = 0; ks < 4; ks++) { ldsm4(qh[ks], ah + ks * 32); ldsm4(ql[ks], ah + 9216 + ks * 32); }
    }
    __syncthreads();

    uint32_t kAd[4], vAd[4];
#pragma unroll
    for (int t = 0; t < 4; t++) {
        int rK = t * 16 + ((lane >> 4) << 3) + (lane & 7), cK = ((lane >> 3) & 1) * 8;
        kAd[t] = smem_u32(&sKh[rK * 72 + cK]);
        int rV = t * 16 + ((lane >> 3) & 1) * 8 + (lane & 7), cV = (lane >> 4) * 8;
        vAd[t] = smem_u32(&sVh[rV * 72 + cV]);
    }

    float o[8][4];
#pragma unroll
    for (int nb = 0; nb < 8; nb++)
#pragma unroll
        for (int t = 0; t < 4; t++) o[nb][t] = 0.f;
    float arr[2][8];
    if (RA) {
#pragma unroll
        for (int hh = 0; hh < 2; hh++)
#pragma unroll
            for (int r = 0; r < 8; r++) arr[hh][r] = 0.f;
    }
    float m0 = -1e30f, m1 = -1e30f, l0 = 0.f, l1 = 0.f;
    const int row0 = lane >> 2, c0 = (lane & 3) * 2;
    const int lt = tid & 127;

    for (int jt = grp; jt <= it; jt += 2) {
        BARG(grp + 1);
#pragma unroll
        for (int u = 0; u < 4; u++) {
            int e = lt + u * 128, row = e >> 3, gg = e & 7;
            size_t gi = ((size_t)(b * SLEN + jt * 64 + row)) * PROJ + h * 64 + gg * 8;
            *reinterpret_cast<uint4*>(&sKh[row * 72 + gg * 8])        = *reinterpret_cast<const uint4*>(&Kh_[gi]);
            *reinterpret_cast<uint4*>(&sKh[4608 + row * 72 + gg * 8]) = *reinterpret_cast<const uint4*>(&Kl_[gi]);
            *reinterpret_cast<uint4*>(&sVh[row * 72 + gg * 8])        = *reinterpret_cast<const uint4*>(&Vh_[gi]);
            *reinterpret_cast<uint4*>(&sVh[4608 + row * 72 + gg * 8]) = *reinterpret_cast<const uint4*>(&Vl_[gi]);
        }
        BARG(grp + 1);

        float s[8][4];
#pragma unroll
        for (int nb = 0; nb < 8; nb++)
#pragma unroll
            for (int t = 0; t < 4; t++) s[nb][t] = 0.f;
#pragma unroll
        for (int ks = 0; ks < 4; ks++)
#pragma unroll
            for (int t = 0; t < 4; t++) {
                uint32_t kh2[4], kl2[4];
                ldsm4(kh2, kAd[t] + ks * 32);
                ldsm4(kl2, kAd[t] + 9216 + ks * 32);
#pragma unroll
                for (int half = 0; half < 2; half++) {
                    int nb = t * 2 + half;
                    mma16816(s[nb], qh[ks], &kh2[half * 2]);
                    mma16816(s[nb], ql[ks], &kh2[half * 2]);
                    mma16816(s[nb], qh[ks], &kl2[half * 2]);
                }
            }
        if (jt == it) {
            int gi0 = wq * 16 + row0;
#pragma unroll
            for (int nb = 0; nb < 8; nb++) {
                int gj = nb * 8 + c0;
                if (gj     > gi0)     s[nb][0] = -1e30f;
                if (gj + 1 > gi0)     s[nb][1] = -1e30f;
                if (gj     > gi0 + 8) s[nb][2] = -1e30f;
                if (gj + 1 > gi0 + 8) s[nb][3] = -1e30f;
            }
        }
        float rm0 = -1e30f, rm1 = -1e30f;
#pragma unroll
        for (int nb = 0; nb < 8; nb++) {
            rm0 = fmaxf(rm0, fmaxf(s[nb][0], s[nb][1]));
            rm1 = fmaxf(rm1, fmaxf(s[nb][2], s[nb][3]));
        }
        rm0 = fmaxf(rm0, __shfl_xor_sync(0xffffffffu, rm0, 1));
        rm0 = fmaxf(rm0, __shfl_xor_sync(0xffffffffu, rm0, 2));
        rm1 = fmaxf(rm1, __shfl_xor_sync(0xffffffffu, rm1, 1));
        rm1 = fmaxf(rm1, __shfl_xor_sync(0xffffffffu, rm1, 2));
        float nm0 = fmaxf(m0, rm0), nm1 = fmaxf(m1, rm1);
        float sc0 = __expf(m0 - nm0), sc1 = __expf(m1 - nm1);
        m0 = nm0; m1 = nm1;
        float rs0 = 0.f, rs1 = 0.f;
#pragma unroll
        for (int nb = 0; nb < 8; nb++) {
            s[nb][0] = __expf(s[nb][0] - nm0);
            s[nb][1] = __expf(s[nb][1] - nm0);
            s[nb][2] = __expf(s[nb][2] - nm1);
            s[nb][3] = __expf(s[nb][3] - nm1);
            rs0 += s[nb][0] + s[nb][1];
            rs1 += s[nb][2] + s[nb][3];
        }
        rs0 += __shfl_xor_sync(0xffffffffu, rs0, 1);
        rs0 += __shfl_xor_sync(0xffffffffu, rs0, 2);
        rs1 += __shfl_xor_sync(0xffffffffu, rs1, 1);
        rs1 += __shfl_xor_sync(0xffffffffu, rs1, 2);
        l0 = l0 * sc0 + rs0;
        l1 = l1 * sc1 + rs1;
#pragma unroll
        for (int nb = 0; nb < 8; nb++) {
            o[nb][0] *= sc0; o[nb][1] *= sc0; o[nb][2] *= sc1; o[nb][3] *= sc1;
        }
        if (RA) {
#pragma unroll
            for (int r = 0; r < 8; r++) { arr[0][r] *= sc0; arr[1][r] *= sc1; }
            int gi0 = it * 64 + wq * 16 + row0;
            int gj0 = jt * 64 + c0;
#pragma unroll
            for (int r = 0; r < 8; r++) {
                const float* rp0 = g_rel + (((size_t)(b * 8 + r)) * SLEN + gi0) * SLEN + gj0;
                const float* rp1 = rp0 + (size_t)8 * SLEN;
#pragma unroll
                for (int nb = 0; nb < 8; nb++) {
                    float2 rv0 = *reinterpret_cast<const float2*>(rp0 + nb * 8);
                    float2 rv1 = *reinterpret_cast<const float2*>(rp1 + nb * 8);
                    arr[0][r] = fmaf(s[nb][0], rv0.x, fmaf(s[nb][1], rv0.y, arr[0][r]));
                    arr[1][r] = fmaf(s[nb][2], rv1.x, fmaf(s[nb][3], rv1.y, arr[1][r]));
                }
            }
        }
#pragma unroll
        for (int jk = 0; jk < 4; jk++) {
            uint32_t ph[4], pl[4];
            ph[0] = cvt2hi(s[2*jk][0],   s[2*jk][1]);
            ph[1] = cvt2hi(s[2*jk][2],   s[2*jk][3]);
            ph[2] = cvt2hi(s[2*jk+1][0], s[2*jk+1][1]);
            ph[3] = cvt2hi(s[2*jk+1][2], s[2*jk+1][3]);
            pl[0] = cvt2lo(s[2*jk][0],   s[2*jk][1],   ph[0]);
            pl[1] = cvt2lo(s[2*jk][2],   s[2*jk][3],   ph[1]);
            pl[2] = cvt2lo(s[2*jk+1][0], s[2*jk+1][1], ph[2]);
            pl[3] = cvt2lo(s[2*jk+1][2], s[2*jk+1][3], ph[3]);
#pragma unroll
            for (int db = 0; db < 4; db++) {
                uint32_t vh2[4], vl2[4];
                ldsm4t(vh2, vAd[jk] + db * 32);
                ldsm4t(vl2, vAd[jk] + 9216 + db * 32);
#pragma unroll
                for (int half = 0; half < 2; half++) {
                    int nb = db * 2 + half;
                    mma16816(o[nb], ph, &vh2[half * 2]);
                    mma16816(o[nb], ph, &vl2[half * 2]);
                    mma16816(o[nb], pl, &vh2[half * 2]);
                }
            }
        }
    }

    __syncthreads();
    if (grp == 1) {
#pragma unroll
        for (int nb = 0; nb < 8; nb++) {
            *reinterpret_cast<float2*>(&mO[(wq * 16 + row0) * 64 + nb * 8 + c0])     = make_float2(o[nb][0], o[nb][1]);
            *reinterpret_cast<float2*>(&mO[(wq * 16 + row0 + 8) * 64 + nb * 8 + c0]) = make_float2(o[nb][2], o[nb][3]);
        }
        if ((lane & 3) == 0) {
            mSt[(wq * 16 + row0) * 2]         = m0;
            mSt[(wq * 16 + row0) * 2 + 1]     = l0;
            mSt[(wq * 16 + row0 + 8) * 2]     = m1;
            mSt[(wq * 16 + row0 + 8) * 2 + 1] = l1;
        }
        if (RA) {
#pragma unroll
            for (int hh = 0; hh < 2; hh++)
#pragma unroll
                for (int r = 0; r < 8; r++) {
                    arr[hh][r] += __shfl_xor_sync(0xffffffffu, arr[hh][r], 1);
                    arr[hh][r] += __shfl_xor_sync(0xffffffffu, arr[hh][r], 2);
                }
            if ((lane & 3) == 0)
#pragma unroll
                for (int r = 0; r < 8; r++) {
                    mAr[(wq * 16 + row0) * 8 + r]     = arr[0][r];
                    mAr[(wq * 16 + row0 + 8) * 8 + r] = arr[1][r];
                }
        }
    }
    __syncthreads();
    if (grp == 0) {
        if (RA) {
#pragma unroll
            for (int hh = 0; hh < 2; hh++)
#pragma unroll
                for (int r = 0; r < 8; r++) {
                    arr[hh][r] += __shfl_xor_sync(0xffffffffu, arr[hh][r], 1);
                    arr[hh][r] += __shfl_xor_sync(0xffffffffu, arr[hh][r], 2);
                }
        }
#pragma unroll
        for (int half = 0; half < 2; half++) {
            int rr = wq * 16 + row0 + half * 8;
            float mo = half ? m1 : m0, lo_ = half ? l1 : l0;
            float m2 = mSt[rr * 2], l2 = mSt[rr * 2 + 1];
            float mf = fmaxf(mo, m2);
            float e1 = __expf(mo - mf), e2 = __expf(m2 - mf);
            float inv = 1.f / (lo_ * e1 + l2 * e2);
            float arf[8];
            if (RA)
#pragma unroll
                for (int r = 0; r < 8; r++)
                    arf[r] = (arr[half][r] * e1 + mAr[rr * 8 + r] * e2) * inv;
#pragma unroll
            for (int nb = 0; nb < 8; nb++) {
                float2 o2 = *reinterpret_cast<float2*>(&mO[rr * 64 + nb * 8 + c0]);
                float v0 = (o[nb][half * 2] * e1     + o2.x * e2) * inv;
                float v1 = (o[nb][half * 2 + 1] * e1 + o2.y * e2) * inv;
                if (RA) {
                    int d0 = nb * 8 + c0;
                    float r0s = 0.f, r1s = 0.f;
#pragma unroll
                    for (int r = 0; r < 8; r++) {
                        r0s = fmaf(arf[r], wrs[d0 * 8 + r], r0s);
                        r1s = fmaf(arf[r], wrs[(d0 + 1) * 8 + r], r1s);
                    }
                    v0 += r0s; v1 += r1s;
                }
                size_t oo = ((size_t)(b * SLEN + it * 64 + rr)) * PROJ + h * 64 + nb * 8 + c0;
                uint32_t hp = cvt2hi(v0, v1), lp = cvt2lo(v0, v1, hp);
                *reinterpret_cast<uint32_t*>(&Ohi[oo]) = hp;
                *reinterpret_cast<uint32_t*>(&Olo[oo]) = lp;
            }
        }
    }
}

// ---------------- host launcher --------------------------------------------------
extern "C" void kernel_launch(void* const* d_in, const int* in_sizes, int n_in,
                              void* d_out, int out_size)
{
    const float* x       = (const float*)d_in[0];
    const float* symbols = (const float*)d_in[1];
    const float* fc      = (const float*)d_in[2];
    const float* fs      = (const float*)d_in[3];
    const float* wsrc[10] = {
        (const float*)d_in[4],  (const float*)d_in[5],  (const float*)d_in[6],
        (const float*)d_in[8],  (const float*)d_in[9],  (const float*)d_in[10],
        (const float*)d_in[11], (const float*)d_in[13], (const float*)d_in[7],
        (const float*)d_in[14],
    };
    const float* wr = (const float*)d_in[12];
    float* out = (float*)d_out;

    __nv_bfloat16 *xhi, *xlo, *shi, *slo, *whi, *wlo, *chi, *clo;
    __nv_bfloat16 *qhi, *qlo, *khi, *klo, *qahi, *qalo, *kahi, *kalo;
    __nv_bfloat16 *vhi, *vlo, *svhi, *svlo, *qrhi, *qrlo, *krhi, *krlo;
    cudaGetSymbolAddress((void**)&xhi, g_xhi);   cudaGetSymbolAddress((void**)&xlo, g_xlo);
    cudaGetSymbolAddress((void**)&shi, g_shi);   cudaGetSymbolAddress((void**)&slo, g_slo);
    cudaGetSymbolAddress((void**)&whi, g_whi);   cudaGetSymbolAddress((void**)&wlo, g_wlo);
    cudaGetSymbolAddress((void**)&chi, g_chi);   cudaGetSymbolAddress((void**)&clo, g_clo);
    cudaGetSymbolAddress((void**)&qhi, g_qhi);   cudaGetSymbolAddress((void**)&qlo, g_qlo);
    cudaGetSymbolAddress((void**)&khi, g_khi);   cudaGetSymbolAddress((void**)&klo, g_klo);
    cudaGetSymbolAddress((void**)&qahi, g_qahi); cudaGetSymbolAddress((void**)&qalo, g_qalo);
    cudaGetSymbolAddress((void**)&kahi, g_kahi); cudaGetSymbolAddress((void**)&kalo, g_kalo);
    cudaGetSymbolAddress((void**)&vhi, g_vhi);   cudaGetSymbolAddress((void**)&vlo, g_vlo);
    cudaGetSymbolAddress((void**)&svhi, g_svhi); cudaGetSymbolAddress((void**)&svlo, g_svlo);
    cudaGetSymbolAddress((void**)&qrhi, g_qrhi); cudaGetSymbolAddress((void**)&qrlo, g_qrlo);
    cudaGetSymbolAddress((void**)&krhi, g_krhi); cudaGetSymbolAddress((void**)&krlo, g_krlo);

    const int wsz[10] = { PROJ*DMODEL, PROJ*DMODEL, PROJ*DMODEL, PROJ*DMODEL, PROJ*DMODEL,
                          PROJ*DMODEL, PROJ*DMODEL, PROJ*DMODEL, PROJ*PROJ, PROJ*PROJ };
    size_t woff[10];
    { size_t o = 0; for (int i = 0; i < 10; i++) { woff[i] = o; o += wsz[i]; } }

    {
        int n = MTOT * DMODEL;
        split_kernel<<<(n + 255) / 256, 256>>>(x, xhi, xlo, n);
        split_kernel<<<(n + 255) / 256, 256>>>(symbols, shi, slo, n);
    }
    for (int i = 0; i < 10; i++)
        split_kernel<<<(wsz[i] + 255) / 256, 256>>>(wsrc[i], whi + woff[i], wlo + woff[i], wsz[i]);

    // projections -> bf16 hi/lo (rope on q/k/qa/ka, scale on q/qa)
    {
        GBatch gb;
        gb.fc = fc; gb.fs = fs; gb.K = DMODEL;
        __nv_bfloat16* yh[8] = { qhi, khi, vhi, qahi, kahi, qrhi, krhi, svhi };
        __nv_bfloat16* yl[8] = { qlo, klo, vlo, qalo, kalo, qrlo, krlo, svlo };
        int modes[8] = { 4, 3, 2, 4, 3, 2, 2, 2 };
        for (int i = 0; i < 8; i++) {
            gb.e[i].ahi = (i == 7) ? shi : xhi;
            gb.e[i].alo = (i == 7) ? slo : xlo;
            gb.e[i].bhi = whi + woff[i];
            gb.e[i].blo = wlo + woff[i];
            gb.e[i].y = nullptr; gb.e[i].ldy = PROJ; gb.e[i].col_off = 0;
            gb.e[i].mode = modes[i]; gb.e[i].yhi = yh[i]; gb.e[i].ylo = yl[i];
        }
        dim3 grid(PROJ / 64, MTOT / 128, 8);
        gemm_mma<<<grid, 256>>>(gb);
    }

    { dim3 grid(SLEN / 64, SLEN / 128, NBATCH * 8); rel_mma<<<grid, 256>>>(); }

    // flash attentions (HMMA)
    {
        const int SM = 75776;
        cudaFuncSetAttribute(flash_mma<false>, cudaFuncAttributeMaxDynamicSharedMemorySize, SM);
        cudaFuncSetAttribute(flash_mma<true>,  cudaFuncAttributeMaxDynamicSharedMemorySize, SM);
        dim3 gfl(SLEN / 64, NBATCH * 8);
        flash_mma<false><<<gfl, 256, SM>>>(qhi, qlo, khi, klo, vhi, vlo, nullptr, chi, clo);
        flash_mma<true ><<<gfl, 256, SM>>>(qahi, qalo, kahi, kalo, svhi, svlo, wr,
                                           chi + (size_t)MTOT * PROJ, clo + (size_t)MTOT * PROJ);
    }

    // output projections -> fp32 halves of out
    {
        GBatch gb;
        gb.fc = fc; gb.fs = fs; gb.K = PROJ;
        gb.e[0].ahi = chi; gb.e[0].alo = clo;
        gb.e[0].bhi = whi + woff[8]; gb.e[0].blo = wlo + woff[8];
        gb.e[0].y = out; gb.e[0].ldy = DMODEL; gb.e[0].col_off = 0; gb.e[0].mode = 0;
        gb.e[0].yhi = nullptr; gb.e[0].ylo = nullptr;
        gb.e[1] = gb.e[0];
        gb.e[1].ahi = chi + (size_t)MTOT * PROJ; gb.e[1].alo = clo + (size_t)MTOT * PROJ;
        gb.e[1].bhi = whi + woff[9]; gb.e[1].blo = wlo + woff[9];
        gb.e[1].col_off = 512;
        for (int i = 2; i < 8; i++) gb.e[i] = gb.e[0];
        dim3 grid(PROJ / 64, MTOT / 128, 2);
        gemm_mma<<<grid, 256>>>(gb);
    }
}

// round 12
// speedup vs baseline: 2.4105x; 1.0467x over previous
#include <cuda_runtime.h>
#include <cuda_bf16.h>
#include <cuda_fp16.h>
#include <cstdint>

#define SLEN   2048
#define NBATCH 2
#define DMODEL 1024
#define PROJ   512
#define MTOT   (NBATCH*SLEN)

__device__ __half g_rel[(size_t)NBATCH*8*SLEN*SLEN];   // fp16 rel, 134 MB

__device__ __nv_bfloat16 g_xhi[MTOT*DMODEL],  g_xlo[MTOT*DMODEL];
__device__ __nv_bfloat16 g_shi[MTOT*DMODEL],  g_slo[MTOT*DMODEL];
#define WTOT (8*PROJ*DMODEL + 2*PROJ*PROJ)
__device__ __nv_bfloat16 g_whi[WTOT], g_wlo[WTOT];
__device__ __nv_bfloat16 g_chi[2*MTOT*PROJ], g_clo[2*MTOT*PROJ];
__device__ __nv_bfloat16 g_qhi [MTOT*PROJ], g_qlo [MTOT*PROJ];
__device__ __nv_bfloat16 g_khi [MTOT*PROJ], g_klo [MTOT*PROJ];
__device__ __nv_bfloat16 g_qahi[MTOT*PROJ], g_qalo[MTOT*PROJ];
__device__ __nv_bfloat16 g_kahi[MTOT*PROJ], g_kalo[MTOT*PROJ];
__device__ __nv_bfloat16 g_vhi [MTOT*PROJ], g_vlo [MTOT*PROJ];
__device__ __nv_bfloat16 g_svhi[MTOT*PROJ], g_svlo[MTOT*PROJ];
__device__ __nv_bfloat16 g_qrhi[MTOT*PROJ], g_qrlo[MTOT*PROJ];
__device__ __nv_bfloat16 g_krhi[MTOT*PROJ], g_krlo[MTOT*PROJ];

__device__ __forceinline__ uint32_t smem_u32(const void* p) {
    uint32_t a;
    asm("{ .reg .u64 t; cvta.to.shared.u64 t, %1; cvt.u32.u64 %0, t; }" : "=r"(a) : "l"(p));
    return a;
}
__device__ __forceinline__ void ldsm4(uint32_t* r, uint32_t a) {
    asm volatile("ldmatrix.sync.aligned.m8n8.x4.shared.b16 {%0,%1,%2,%3}, [%4];"
        : "=r"(r[0]), "=r"(r[1]), "=r"(r[2]), "=r"(r[3]) : "r"(a));
}
__device__ __forceinline__ void ldsm4t(uint32_t* r, uint32_t a) {
    asm volatile("ldmatrix.sync.aligned.m8n8.x4.trans.shared.b16 {%0,%1,%2,%3}, [%4];"
        : "=r"(r[0]), "=r"(r[1]), "=r"(r[2]), "=r"(r[3]) : "r"(a));
}
__device__ __forceinline__ void mma16816(float* c, const uint32_t* a, const uint32_t* b) {
    asm volatile("mma.sync.aligned.m16n8k16.row.col.f32.bf16.bf16.f32 "
        "{%0,%1,%2,%3}, {%4,%5,%6,%7}, {%8,%9}, {%0,%1,%2,%3};"
        : "+f"(c[0]), "+f"(c[1]), "+f"(c[2]), "+f"(c[3])
        : "r"(a[0]), "r"(a[1]), "r"(a[2]), "r"(a[3]), "r"(b[0]), "r"(b[1]));
}
__device__ __forceinline__ uint32_t cvt2hi(float a, float b) {
    __nv_bfloat162 h; h.x = __float2bfloat16(a); h.y = __float2bfloat16(b);
    return *reinterpret_cast<uint32_t*>(&h);
}
__device__ __forceinline__ uint32_t cvt2lo(float a, float b, uint32_t hp) {
    __nv_bfloat162 h = *reinterpret_cast<__nv_bfloat162*>(&hp);
    return cvt2hi(a - __bfloat162float(h.x), b - __bfloat162float(h.y));
}
#define BARG(id) asm volatile("bar.sync %0, 128;" :: "r"(id))

// ------------- batched fp32 -> bf16 hi/lo split ----------------------------------
struct SEntry { const float* s; __nv_bfloat16 *hi, *lo; int n; };
struct SBatch { SEntry e[10]; };
__global__ __launch_bounds__(256) void split_multi(SBatch sb)
{
    SEntry en = sb.e[blockIdx.y];
    int i = blockIdx.x * 256 + threadIdx.x;
    if (i < en.n) {
        float v = en.s[i];
        __nv_bfloat16 h = __float2bfloat16(v);
        en.hi[i] = h;
        en.lo[i] = __float2bfloat16(v - __bfloat162float(h));
    }
}

// ------------- HMMA batched GEMM; modes: 0 fp32, 2 split, 3 rope+split, 4 rope+scale+split
struct GEntry {
    const __nv_bfloat16 *ahi, *alo, *bhi, *blo;
    float* y;
    __nv_bfloat16 *yhi, *ylo;
    int ldy, col_off, mode;
};
struct GBatch { GEntry e[8]; const float *fc, *fs; int K; };

__global__ __launch_bounds__(256, 2) void gemm_mma(GBatch args)
{
    const GEntry ge = args.e[blockIdx.z];
    const int K = args.K;
    __shared__ __align__(16) __nv_bfloat16 sA[2][128][40];
    __shared__ __align__(16) __nv_bfloat16 sB[2][64][40];

    const int tid = threadIdx.x, lane = tid & 31, wid = tid >> 5;
    const int warpM = wid & 3, warpN = wid >> 2;
    const int mBase = blockIdx.y * 128, nBase = blockIdx.x * 64;

    float acc[2][4][4];
#pragma unroll
    for (int i = 0; i < 2; i++)
#pragma unroll
        for (int j = 0; j < 4; j++)
#pragma unroll
            for (int t = 0; t < 4; t++) acc[i][j][t] = 0.f;

    const int ar = tid >> 2, ag = (tid & 3) * 8;

    uint32_t aAdH[2], aAdL[2], bAdH[2], bAdL[2];
#pragma unroll
    for (int t = 0; t < 2; t++) {
        int rA = warpM * 32 + t * 16 + (lane & 15), cA = (lane >> 4) * 8;
        aAdH[t] = smem_u32(&sA[0][rA][cA]);
        aAdL[t] = smem_u32(&sA[1][rA][cA]);
        int rB = warpN * 32 + t * 16 + ((lane >> 4) << 3) + (lane & 7);
        int cB = ((lane >> 3) & 1) * 8;
        bAdH[t] = smem_u32(&sB[0][rB][cB]);
        bAdL[t] = smem_u32(&sB[1][rB][cB]);
    }

    uint4 pAh[2], pAl[2], pBh, pBl;
    const int NC = K / 32;
    {
        pAh[0] = *reinterpret_cast<const uint4*>(ge.ahi + (size_t)(mBase + ar) * K + ag);
        pAl[0] = *reinterpret_cast<const uint4*>(ge.alo + (size_t)(mBase + ar) * K + ag);
        pAh[1] = *reinterpret_cast<const uint4*>(ge.ahi + (size_t)(mBase + ar + 64) * K + ag);
        pAl[1] = *reinterpret_cast<const uint4*>(ge.alo + (size_t)(mBase + ar + 64) * K + ag);
        pBh    = *reinterpret_cast<const uint4*>(ge.bhi + (size_t)(nBase + ar) * K + ag);
        pBl    = *reinterpret_cast<const uint4*>(ge.blo + (size_t)(nBase + ar) * K + ag);
    }

    for (int c = 0; c < NC; c++) {
        if (c) __syncthreads();
        *reinterpret_cast<uint4*>(&sA[0][ar][ag])      = pAh[0];
        *reinterpret_cast<uint4*>(&sA[1][ar][ag])      = pAl[0];
        *reinterpret_cast<uint4*>(&sA[0][ar + 64][ag]) = pAh[1];
        *reinterpret_cast<uint4*>(&sA[1][ar + 64][ag]) = pAl[1];
        *reinterpret_cast<uint4*>(&sB[0][ar][ag])      = pBh;
        *reinterpret_cast<uint4*>(&sB[1][ar][ag])      = pBl;
        __syncthreads();
        if (c + 1 < NC) {
            const int kof = (c + 1) * 32 + ag;
            pAh[0] = *reinterpret_cast<const uint4*>(ge.ahi + (size_t)(mBase + ar) * K + kof);
            pAl[0] = *reinterpret_cast<const uint4*>(ge.alo + (size_t)(mBase + ar) * K + kof);
            pAh[1] = *reinterpret_cast<const uint4*>(ge.ahi + (size_t)(mBase + ar + 64) * K + kof);
            pAl[1] = *reinterpret_cast<const uint4*>(ge.alo + (size_t)(mBase + ar + 64) * K + kof);
            pBh    = *reinterpret_cast<const uint4*>(ge.bhi + (size_t)(nBase + ar) * K + kof);
            pBl    = *reinterpret_cast<const uint4*>(ge.blo + (size_t)(nBase + ar) * K + kof);
        }
#pragma unroll
        for (int ks = 0; ks < 2; ks++) {
            const uint32_t off = ks * 32;
            uint32_t ah[2][4], al[2][4], bh[2][4], bl[2][4];
            ldsm4(ah[0], aAdH[0] + off);  ldsm4(ah[1], aAdH[1] + off);
            ldsm4(al[0], aAdL[0] + off);  ldsm4(al[1], aAdL[1] + off);
            ldsm4(bh[0], bAdH[0] + off);  ldsm4(bh[1], bAdH[1] + off);
            ldsm4(bl[0], bAdL[0] + off);  ldsm4(bl[1], bAdL[1] + off);
#pragma unroll
            for (int i = 0; i < 2; i++)
#pragma unroll
                for (int j = 0; j < 4; j++) {
                    const uint32_t* bhp = &bh[j >> 1][(j & 1) * 2];
                    const uint32_t* blp = &bl[j >> 1][(j & 1) * 2];
                    mma16816(acc[i][j], ah[i], bhp);
                    mma16816(acc[i][j], al[i], bhp);
                    mma16816(acc[i][j], ah[i], blp);
                }
        }
    }

    const int mrow = lane >> 2, ncol = (lane & 3) * 2;
#pragma unroll
    for (int i = 0; i < 2; i++)
#pragma unroll
        for (int j = 0; j < 4; j++) {
            int m0 = mBase + warpM * 32 + i * 16 + mrow;
            int n  = nBase + warpN * 32 + j * 8 + ncol;
#pragma unroll
            for (int half = 0; half < 2; half++) {
                int m = m0 + half * 8;
                float c0 = acc[i][j][half * 2], c1 = acc[i][j][half * 2 + 1];
                if (ge.mode >= 3) {
                    int srow = m & (SLEN - 1);
                    int t = (n & 63) >> 1;
                    float cz = args.fc[srow * 32 + t], sz = args.fs[srow * 32 + t];
                    float xr = c0, xi = c1;
                    c0 = xr * cz - xi * sz;
                    c1 = xr * sz + xi * cz;
                }
                if (ge.mode == 4) { c0 *= 0.125f; c1 *= 0.125f; }
                if (ge.mode == 0) {
                    *reinterpret_cast<float2*>(&ge.y[(size_t)m * ge.ldy + ge.col_off + n]) =
                        make_float2(c0, c1);
                } else {
                    uint32_t hp = cvt2hi(c0, c1), lp = cvt2lo(c0, c1, hp);
                    *reinterpret_cast<uint32_t*>(&ge.yhi[(size_t)m * PROJ + n]) = hp;
                    *reinterpret_cast<uint32_t*>(&ge.ylo[(size_t)m * PROJ + n]) = lp;
                }
            }
        }
}

// ------------- rel[b,r,i,j] = 0.125 * qr·kr -> fp16, lower-triangular tiles ------
__global__ __launch_bounds__(256, 2) void rel_mma()
{
    const int mBase = blockIdx.y * 128, nBase = blockIdx.x * 64;
    if (nBase > mBase + 127) return;
    const int br = blockIdx.z, b = br >> 3, r = br & 7;

    __shared__ __align__(16) __nv_bfloat16 sA[2][128][40];
    __shared__ __align__(16) __nv_bfloat16 sB[2][64][40];
    const int tid = threadIdx.x, lane = tid & 31, wid = tid >> 5;
    const int warpM = wid & 3, warpN = wid >> 2;

    const __nv_bfloat16* Ah = g_qrhi + ((size_t)(b * SLEN + mBase)) * PROJ + r * 64;
    const __nv_bfloat16* Al = g_qrlo + ((size_t)(b * SLEN + mBase)) * PROJ + r * 64;
    const __nv_bfloat16* Bh = g_krhi + ((size_t)(b * SLEN + nBase)) * PROJ + r * 64;
    const __nv_bfloat16* Bl = g_krlo + ((size_t)(b * SLEN + nBase)) * PROJ + r * 64;

    float acc[2][4][4];
#pragma unroll
    for (int i = 0; i < 2; i++)
#pragma unroll
        for (int j = 0; j < 4; j++)
#pragma unroll
            for (int t = 0; t < 4; t++) acc[i][j][t] = 0.f;

    const int ar = tid >> 2, ag = (tid & 3) * 8;
    uint32_t aAdH[2], aAdL[2], bAdH[2], bAdL[2];
#pragma unroll
    for (int t = 0; t < 2; t++) {
        int rA = warpM * 32 + t * 16 + (lane & 15), cA = (lane >> 4) * 8;
        aAdH[t] = smem_u32(&sA[0][rA][cA]);
        aAdL[t] = smem_u32(&sA[1][rA][cA]);
        int rB = warpN * 32 + t * 16 + ((lane >> 4) << 3) + (lane & 7);
        int cB = ((lane >> 3) & 1) * 8;
        bAdH[t] = smem_u32(&sB[0][rB][cB]);
        bAdL[t] = smem_u32(&sB[1][rB][cB]);
    }

    for (int c = 0; c < 2; c++) {
        const int kof = c * 32 + ag;
        if (c) __syncthreads();
        *reinterpret_cast<uint4*>(&sA[0][ar][ag])      = *reinterpret_cast<const uint4*>(Ah + (size_t)ar * PROJ + kof);
        *reinterpret_cast<uint4*>(&sA[1][ar][ag])      = *reinterpret_cast<const uint4*>(Al + (size_t)ar * PROJ + kof);
        *reinterpret_cast<uint4*>(&sA[0][ar + 64][ag]) = *reinterpret_cast<const uint4*>(Ah + (size_t)(ar + 64) * PROJ + kof);
        *reinterpret_cast<uint4*>(&sA[1][ar + 64][ag]) = *reinterpret_cast<const uint4*>(Al + (size_t)(ar + 64) * PROJ + kof);
        *reinterpret_cast<uint4*>(&sB[0][ar][ag])      = *reinterpret_cast<const uint4*>(Bh + (size_t)ar * PROJ + kof);
        *reinterpret_cast<uint4*>(&sB[1][ar][ag])      = *reinterpret_cast<const uint4*>(Bl + (size_t)ar * PROJ + kof);
        __syncthreads();
#pragma unroll
        for (int ks = 0; ks < 2; ks++) {
            const uint32_t off = ks * 32;
            uint32_t ah[2][4], al[2][4], bh[2][4], bl[2][4];
            ldsm4(ah[0], aAdH[0] + off);  ldsm4(ah[1], aAdH[1] + off);
            ldsm4(al[0], aAdL[0] + off);  ldsm4(al[1], aAdL[1] + off);
            ldsm4(bh[0], bAdH[0] + off);  ldsm4(bh[1], bAdH[1] + off);
            ldsm4(bl[0], bAdL[0] + off);  ldsm4(bl[1], bAdL[1] + off);
#pragma unroll
            for (int i = 0; i < 2; i++)
#pragma unroll
                for (int j = 0; j < 4; j++) {
                    const uint32_t* bhp = &bh[j >> 1][(j & 1) * 2];
                    const uint32_t* blp = &bl[j >> 1][(j & 1) * 2];
                    mma16816(acc[i][j], ah[i], bhp);
                    mma16816(acc[i][j], al[i], bhp);
                    mma16816(acc[i][j], ah[i], blp);
                }
        }
    }

    __half* out = g_rel + ((size_t)br * SLEN + mBase) * SLEN + nBase;
    const int mrow = lane >> 2, ncol = (lane & 3) * 2;
#pragma unroll
    for (int i = 0; i < 2; i++)
#pragma unroll
        for (int j = 0; j < 4; j++) {
            int m0 = warpM * 32 + i * 16 + mrow;
            int n  = warpN * 32 + j * 8 + ncol;
#pragma unroll
            for (int half = 0; half < 2; half++) {
                __half2 hv = __floats2half2_rn(acc[i][j][half * 2] * 0.125f,
                                               acc[i][j][half * 2 + 1] * 0.125f);
                *reinterpret_cast<__half2*>(&out[(size_t)(m0 + half * 8) * SLEN + n]) = hv;
            }
        }
}

// ------------- HMMA flash attention: 64x64 tiles, split-KV warp groups -----------
// Per-group smem plane (bf16 elements): Kh @0, Kl @4608, Vh @9216, Vl @13824.
// ldmatrix reads lo planes at +9216 BYTES (= +4608 elements).
template<bool RA>
__global__ __launch_bounds__(256) void flash_mma(
    const __nv_bfloat16* __restrict__ Qh_, const __nv_bfloat16* __restrict__ Ql_,
    const __nv_bfloat16* __restrict__ Kh_, const __nv_bfloat16* __restrict__ Kl_,
    const __nv_bfloat16* __restrict__ Vh_, const __nv_bfloat16* __restrict__ Vl_,
    const float* __restrict__ WR,
    __nv_bfloat16* __restrict__ Ohi, __nv_bfloat16* __restrict__ Olo)
{
    extern __shared__ char smraw[];
    __nv_bfloat16* sm = (__nv_bfloat16*)smraw;
    const int bh = blockIdx.y, b = bh >> 3, h = bh & 7, it = blockIdx.x;
    const int tid = threadIdx.x, lane = tid & 31, wid = tid >> 5;
    const int grp = wid >> 2, wq = wid & 3;
    __nv_bfloat16* sKh = sm + grp * 18432;
    __nv_bfloat16* sVh = sKh + 9216;
    float* wrs = (float*)(smraw + 73728);
    float* mO  = (float*)(sm + 18432);   // merge region = group-1 buffers
    float* mAr = mO + 4096;
    float* mSt = mAr + 512;

    // stage Q (hi @0, lo @4608 elements)
#pragma unroll
    for (int u = 0; u < 2; u++) {
        int e = tid + u * 256, row = e >> 3, gg = e & 7;
        size_t gq = ((size_t)(b * SLEN + it * 64 + row)) * PROJ + h * 64 + gg * 8;
        *reinterpret_cast<uint4*>(&sm[row * 72 + gg * 8])        = *reinterpret_cast<const uint4*>(&Qh_[gq]);
        *reinterpret_cast<uint4*>(&sm[4608 + row * 72 + gg * 8]) = *reinterpret_cast<const uint4*>(&Ql_[gq]);
    }
    if (RA) { wrs[tid] = WR[h * 512 + tid]; wrs[256 + tid] = WR[h * 512 + 256 + tid]; }
    __syncthreads();
    uint32_t qh[4][4], ql[4][4];
    {
        uint32_t ah = smem_u32(&sm[(wq * 16 + (lane & 15)) * 72 + (lane >> 4) * 8]);
#pragma unroll
        for (int ks = 0; ks < 4; ks++) { ldsm4(qh[ks], ah + ks * 32); ldsm4(ql[ks], ah + 9216 + ks * 32); }
    }
    __syncthreads();

    uint32_t kAd[4], vAd[4];
#pragma unroll
    for (int t = 0; t < 4; t++) {
        int rK = t * 16 + ((lane >> 4) << 3) + (lane & 7), cK = ((lane >> 3) & 1) * 8;
        kAd[t] = smem_u32(&sKh[rK * 72 + cK]);
        int rV = t * 16 + ((lane >> 3) & 1) * 8 + (lane & 7), cV = (lane >> 4) * 8;
        vAd[t] = smem_u32(&sVh[rV * 72 + cV]);
    }

    float o[8][4];
#pragma unroll
    for (int nb = 0; nb < 8; nb++)
#pragma unroll
        for (int t = 0; t < 4; t++) o[nb][t] = 0.f;
    float arr[2][8];
    if (RA) {
#pragma unroll
        for (int hh = 0; hh < 2; hh++)
#pragma unroll
            for (int r = 0; r < 8; r++) arr[hh][r] = 0.f;
    }
    float m0 = -1e30f, m1 = -1e30f, l0 = 0.f, l1 = 0.f;
    const int row0 = lane >> 2, c0 = (lane & 3) * 2;
    const int lt = tid & 127;

    for (int jt = grp; jt <= it; jt += 2) {
        BARG(grp + 1);
#pragma unroll
        for (int u = 0; u < 4; u++) {
            int e = lt + u * 128, row = e >> 3, gg = e & 7;
            size_t gi = ((size_t)(b * SLEN + jt * 64 + row)) * PROJ + h * 64 + gg * 8;
            *reinterpret_cast<uint4*>(&sKh[row * 72 + gg * 8])        = *reinterpret_cast<const uint4*>(&Kh_[gi]);
            *reinterpret_cast<uint4*>(&sKh[4608 + row * 72 + gg * 8]) = *reinterpret_cast<const uint4*>(&Kl_[gi]);
            *reinterpret_cast<uint4*>(&sVh[row * 72 + gg * 8])        = *reinterpret_cast<const uint4*>(&Vh_[gi]);
            *reinterpret_cast<uint4*>(&sVh[4608 + row * 72 + gg * 8]) = *reinterpret_cast<const uint4*>(&Vl_[gi]);
        }
        BARG(grp + 1);

        float s[8][4];
#pragma unroll
        for (int nb = 0; nb < 8; nb++)
#pragma unroll
            for (int t = 0; t < 4; t++) s[nb][t] = 0.f;
#pragma unroll
        for (int ks = 0; ks < 4; ks++)
#pragma unroll
            for (int t = 0; t < 4; t++) {
                uint32_t kh2[4], kl2[4];
                ldsm4(kh2, kAd[t] + ks * 32);
                ldsm4(kl2, kAd[t] + 9216 + ks * 32);
#pragma unroll
                for (int half = 0; half < 2; half++) {
                    int nb = t * 2 + half;
                    mma16816(s[nb], qh[ks], &kh2[half * 2]);
                    mma16816(s[nb], ql[ks], &kh2[half * 2]);
                    mma16816(s[nb], qh[ks], &kl2[half * 2]);
                }
            }
        if (jt == it) {
            int gi0 = wq * 16 + row0;
#pragma unroll
            for (int nb = 0; nb < 8; nb++) {
                int gj = nb * 8 + c0;
                if (gj     > gi0)     s[nb][0] = -1e30f;
                if (gj + 1 > gi0)     s[nb][1] = -1e30f;
                if (gj     > gi0 + 8) s[nb][2] = -1e30f;
                if (gj + 1 > gi0 + 8) s[nb][3] = -1e30f;
            }
        }
        float rm0 = -1e30f, rm1 = -1e30f;
#pragma unroll
        for (int nb = 0; nb < 8; nb++) {
            rm0 = fmaxf(rm0, fmaxf(s[nb][0], s[nb][1]));
            rm1 = fmaxf(rm1, fmaxf(s[nb][2], s[nb][3]));
        }
        rm0 = fmaxf(rm0, __shfl_xor_sync(0xffffffffu, rm0, 1));
        rm0 = fmaxf(rm0, __shfl_xor_sync(0xffffffffu, rm0, 2));
        rm1 = fmaxf(rm1, __shfl_xor_sync(0xffffffffu, rm1, 1));
        rm1 = fmaxf(rm1, __shfl_xor_sync(0xffffffffu, rm1, 2));
        float nm0 = fmaxf(m0, rm0), nm1 = fmaxf(m1, rm1);
        float sc0 = __expf(m0 - nm0), sc1 = __expf(m1 - nm1);
        m0 = nm0; m1 = nm1;
        float rs0 = 0.f, rs1 = 0.f;
#pragma unroll
        for (int nb = 0; nb < 8; nb++) {
            s[nb][0] = __expf(s[nb][0] - nm0);
            s[nb][1] = __expf(s[nb][1] - nm0);
            s[nb][2] = __expf(s[nb][2] - nm1);
            s[nb][3] = __expf(s[nb][3] - nm1);
            rs0 += s[nb][0] + s[nb][1];
            rs1 += s[nb][2] + s[nb][3];
        }
        rs0 += __shfl_xor_sync(0xffffffffu, rs0, 1);
        rs0 += __shfl_xor_sync(0xffffffffu, rs0, 2);
        rs1 += __shfl_xor_sync(0xffffffffu, rs1, 1);
        rs1 += __shfl_xor_sync(0xffffffffu, rs1, 2);
        l0 = l0 * sc0 + rs0;
        l1 = l1 * sc1 + rs1;
#pragma unroll
        for (int nb = 0; nb < 8; nb++) {
            o[nb][0] *= sc0; o[nb][1] *= sc0; o[nb][2] *= sc1; o[nb][3] *= sc1;
        }
        if (RA) {
#pragma unroll
            for (int r = 0; r < 8; r++) { arr[0][r] *= sc0; arr[1][r] *= sc1; }
            int gi0 = it * 64 + wq * 16 + row0;
            int gj0 = jt * 64 + c0;
#pragma unroll
            for (int r = 0; r < 8; r++) {
                const __half2* rp0 = reinterpret_cast<const __half2*>(
                    g_rel + (((size_t)(b * 8 + r)) * SLEN + gi0) * SLEN + gj0);
                const __half2* rp1 = reinterpret_cast<const __half2*>(
                    g_rel + (((size_t)(b * 8 + r)) * SLEN + gi0 + 8) * SLEN + gj0);
#pragma unroll
                for (int nb = 0; nb < 8; nb++) {
                    float2 rv0 = __half22float2(rp0[nb * 4]);
                    float2 rv1 = __half22float2(rp1[nb * 4]);
                    arr[0][r] = fmaf(s[nb][0], rv0.x, fmaf(s[nb][1], rv0.y, arr[0][r]));
                    arr[1][r] = fmaf(s[nb][2], rv1.x, fmaf(s[nb][3], rv1.y, arr[1][r]));
                }
            }
        }
#pragma unroll
        for (int jk = 0; jk < 4; jk++) {
            uint32_t ph[4], pl[4];
            ph[0] = cvt2hi(s[2*jk][0],   s[2*jk][1]);
            ph[1] = cvt2hi(s[2*jk][2],   s[2*jk][3]);
            ph[2] = cvt2hi(s[2*jk+1][0], s[2*jk+1][1]);
            ph[3] = cvt2hi(s[2*jk+1][2], s[2*jk+1][3]);
            pl[0] = cvt2lo(s[2*jk][0],   s[2*jk][1],   ph[0]);
            pl[1] = cvt2lo(s[2*jk][2],   s[2*jk][3],   ph[1]);
            pl[2] = cvt2lo(s[2*jk+1][0], s[2*jk+1][1], ph[2]);
            pl[3] = cvt2lo(s[2*jk+1][2], s[2*jk+1][3], ph[3]);
#pragma unroll
            for (int db = 0; db < 4; db++) {
                uint32_t vh2[4], vl2[4];
                ldsm4t(vh2, vAd[jk] + db * 32);
                ldsm4t(vl2, vAd[jk] + 9216 + db * 32);
#pragma unroll
                for (int half = 0; half < 2; half++) {
                    int nb = db * 2 + half;
                    mma16816(o[nb], ph, &vh2[half * 2]);
                    mma16816(o[nb], ph, &vl2[half * 2]);
                    mma16816(o[nb], pl, &vh2[half * 2]);
                }
            }
        }
    }

    __syncthreads();
    if (grp == 1) {
#pragma unroll
        for (int nb = 0; nb < 8; nb++) {
            *reinterpret_cast<float2*>(&mO[(wq * 16 + row0) * 64 + nb * 8 + c0])     = make_float2(o[nb][0], o[nb][1]);
            *reinterpret_cast<float2*>(&mO[(wq * 16 + row0 + 8) * 64 + nb * 8 + c0]) = make_float2(o[nb][2], o[nb][3]);
        }
        if ((lane & 3) == 0) {
            mSt[(wq * 16 + row0) * 2]         = m0;
            mSt[(wq * 16 + row0) * 2 + 1]     = l0;
            mSt[(wq * 16 + row0 + 8) * 2]     = m1;
            mSt[(wq * 16 + row0 + 8) * 2 + 1] = l1;
        }
        if (RA) {
#pragma unroll
            for (int hh = 0; hh < 2; hh++)
#pragma unroll
                for (int r = 0; r < 8; r++) {
                    arr[hh][r] += __shfl_xor_sync(0xffffffffu, arr[hh][r], 1);
                    arr[hh][r] += __shfl_xor_sync(0xffffffffu, arr[hh][r], 2);
                }
            if ((lane & 3) == 0)
#pragma unroll
                for (int r = 0; r < 8; r++) {
                    mAr[(wq * 16 + row0) * 8 + r]     = arr[0][r];
                    mAr[(wq * 16 + row0 + 8) * 8 + r] = arr[1][r];
                }
        }
    }
    __syncthreads();
    if (grp == 0) {
        if (RA) {
#pragma unroll
            for (int hh = 0; hh < 2; hh++)
#pragma unroll
                for (int r = 0; r < 8; r++) {
                    arr[hh][r] += __shfl_xor_sync(0xffffffffu, arr[hh][r], 1);
                    arr[hh][r] += __shfl_xor_sync(0xffffffffu, arr[hh][r], 2);
                }
        }
#pragma unroll
        for (int half = 0; half < 2; half++) {
            int rr = wq * 16 + row0 + half * 8;
            float mo = half ? m1 : m0, lo_ = half ? l1 : l0;
            float m2 = mSt[rr * 2], l2 = mSt[rr * 2 + 1];
            float mf = fmaxf(mo, m2);
            float e1 = __expf(mo - mf), e2 = __expf(m2 - mf);
            float inv = 1.f / (lo_ * e1 + l2 * e2);
            float arf[8];
            if (RA)
#pragma unroll
                for (int r = 0; r < 8; r++)
                    arf[r] = (arr[half][r] * e1 + mAr[rr * 8 + r] * e2) * inv;
#pragma unroll
            for (int nb = 0; nb < 8; nb++) {
                float2 o2 = *reinterpret_cast<float2*>(&mO[rr * 64 + nb * 8 + c0]);
                float v0 = (o[nb][half * 2] * e1     + o2.x * e2) * inv;
                float v1 = (o[nb][half * 2 + 1] * e1 + o2.y * e2) * inv;
                if (RA) {
                    int d0 = nb * 8 + c0;
                    float r0s = 0.f, r1s = 0.f;
#pragma unroll
                    for (int r = 0; r < 8; r++) {
                        r0s = fmaf(arf[r], wrs[d0 * 8 + r], r0s);
                        r1s = fmaf(arf[r], wrs[(d0 + 1) * 8 + r], r1s);
                    }
                    v0 += r0s; v1 += r1s;
                }
                size_t oo = ((size_t)(b * SLEN + it * 64 + rr)) * PROJ + h * 64 + nb * 8 + c0;
                uint32_t hp = cvt2hi(v0, v1), lp = cvt2lo(v0, v1, hp);
                *reinterpret_cast<uint32_t*>(&Ohi[oo]) = hp;
                *reinterpret_cast<uint32_t*>(&Olo[oo]) = lp;
            }
        }
    }
}

// ---------------- host launcher --------------------------------------------------
extern "C" void kernel_launch(void* const* d_in, const int* in_sizes, int n_in,
                              void* d_out, int out_size)
{
    const float* x       = (const float*)d_in[0];
    const float* symbols = (const float*)d_in[1];
    const float* fc      = (const float*)d_in[2];
    const float* fs      = (const float*)d_in[3];
    const float* wsrc[10] = {
        (const float*)d_in[4],  (const float*)d_in[5],  (const float*)d_in[6],
        (const float*)d_in[8],  (const float*)d_in[9],  (const float*)d_in[10],
        (const float*)d_in[11], (const float*)d_in[13], (const float*)d_in[7],
        (const float*)d_in[14],
    };
    const float* wr = (const float*)d_in[12];
    float* out = (float*)d_out;

    __nv_bfloat16 *xhi, *xlo, *shi, *slo, *whi, *wlo, *chi, *clo;
    __nv_bfloat16 *qhi, *qlo, *khi, *klo, *qahi, *qalo, *kahi, *kalo;
    __nv_bfloat16 *vhi, *vlo, *svhi, *svlo, *qrhi, *qrlo, *krhi, *krlo;
    cudaGetSymbolAddress((void**)&xhi, g_xhi);   cudaGetSymbolAddress((void**)&xlo, g_xlo);
    cudaGetSymbolAddress((void**)&shi, g_shi);   cudaGetSymbolAddress((void**)&slo, g_slo);
    cudaGetSymbolAddress((void**)&whi, g_whi);   cudaGetSymbolAddress((void**)&wlo, g_wlo);
    cudaGetSymbolAddress((void**)&chi, g_chi);   cudaGetSymbolAddress((void**)&clo, g_clo);
    cudaGetSymbolAddress((void**)&qhi, g_qhi);   cudaGetSymbolAddress((void**)&qlo, g_qlo);
    cudaGetSymbolAddress((void**)&khi, g_khi);   cudaGetSymbolAddress((void**)&klo, g_klo);
    cudaGetSymbolAddress((void**)&qahi, g_qahi); cudaGetSymbolAddress((void**)&qalo, g_qalo);
    cudaGetSymbolAddress((void**)&kahi, g_kahi); cudaGetSymbolAddress((void**)&kalo, g_kalo);
    cudaGetSymbolAddress((void**)&vhi, g_vhi);   cudaGetSymbolAddress((void**)&vlo, g_vlo);
    cudaGetSymbolAddress((void**)&svhi, g_svhi); cudaGetSymbolAddress((void**)&svlo, g_svlo);
    cudaGetSymbolAddress((void**)&qrhi, g_qrhi); cudaGetSymbolAddress((void**)&qrlo, g_qrlo);
    cudaGetSymbolAddress((void**)&krhi, g_krhi); cudaGetSymbolAddress((void**)&krlo, g_krlo);

    const int wsz[10] = { PROJ*DMODEL, PROJ*DMODEL, PROJ*DMODEL, PROJ*DMODEL, PROJ*DMODEL,
                          PROJ*DMODEL, PROJ*DMODEL, PROJ*DMODEL, PROJ*PROJ, PROJ*PROJ };
    size_t woff[10];
    { size_t o = 0; for (int i = 0; i < 10; i++) { woff[i] = o; o += wsz[i]; } }

    // split launch A: x + symbols (2 entries)
    {
        SBatch sb;
        sb.e[0] = { x,       xhi, xlo, MTOT * DMODEL };
        sb.e[1] = { symbols, shi, slo, MTOT * DMODEL };
        for (int i = 2; i < 10; i++) sb.e[i] = sb.e[0];
        dim3 grid((MTOT * DMODEL + 255) / 256, 2);
        split_multi<<<grid, 256>>>(sb);
    }
    // split launch B: 10 weights
    {
        SBatch sb;
        for (int i = 0; i < 10; i++)
            sb.e[i] = { wsrc[i], whi + woff[i], wlo + woff[i], wsz[i] };
        dim3 grid((PROJ * DMODEL + 255) / 256, 10);
        split_multi<<<grid, 256>>>(sb);
    }

    // projections -> bf16 hi/lo (rope on q/k/qa/ka, scale on q/qa)
    {
        GBatch gb;
        gb.fc = fc; gb.fs = fs; gb.K = DMODEL;
        __nv_bfloat16* yh[8] = { qhi, khi, vhi, qahi, kahi, qrhi, krhi, svhi };
        __nv_bfloat16* yl[8] = { qlo, klo, vlo, qalo, kalo, qrlo, krlo, svlo };
        int modes[8] = { 4, 3, 2, 4, 3, 2, 2, 2 };
        for (int i = 0; i < 8; i++) {
            gb.e[i].ahi = (i == 7) ? shi : xhi;
            gb.e[i].alo = (i == 7) ? slo : xlo;
            gb.e[i].bhi = whi + woff[i];
            gb.e[i].blo = wlo + woff[i];
            gb.e[i].y = nullptr; gb.e[i].ldy = PROJ; gb.e[i].col_off = 0;
            gb.e[i].mode = modes[i]; gb.e[i].yhi = yh[i]; gb.e[i].ylo = yl[i];
        }
        dim3 grid(PROJ / 64, MTOT / 128, 8);
        gemm_mma<<<grid, 256>>>(gb);
    }

    { dim3 grid(SLEN / 64, SLEN / 128, NBATCH * 8); rel_mma<<<grid, 256>>>(); }

    // flash attentions (HMMA); flash RA is launch #6 -> ncu -s 5 -c 1 captures it
    {
        const int SM = 75776;
        cudaFuncSetAttribute(flash_mma<false>, cudaFuncAttributeMaxDynamicSharedMemorySize, SM);
        cudaFuncSetAttribute(flash_mma<true>,  cudaFuncAttributeMaxDynamicSharedMemorySize, SM);
        dim3 gfl(SLEN / 64, NBATCH * 8);
        flash_mma<false><<<gfl, 256, SM>>>(qhi, qlo, khi, klo, vhi, vlo, nullptr, chi, clo);
        flash_mma<true ><<<gfl, 256, SM>>>(qahi, qalo, kahi, kalo, svhi, svlo, wr,
                                           chi + (size_t)MTOT * PROJ, clo + (size_t)MTOT * PROJ);
    }

    // output projections -> fp32 halves of out
    {
        GBatch gb;
        gb.fc = fc; gb.fs = fs; gb.K = PROJ;
        gb.e[0].ahi = chi; gb.e[0].alo = clo;
        gb.e[0].bhi = whi + woff[8]; gb.e[0].blo = wlo + woff[8];
        gb.e[0].y = out; gb.e[0].ldy = DMODEL; gb.e[0].col_off = 0; gb.e[0].mode = 0;
        gb.e[0].yhi = nullptr; gb.e[0].ylo = nullptr;
        gb.e[1] = gb.e[0];
        gb.e[1].ahi = chi + (size_t)MTOT * PROJ; gb.e[1].alo = clo + (size_t)MTOT * PROJ;
        gb.e[1].bhi = whi + woff[9]; gb.e[1].blo = wlo + woff[9];
        gb.e[1].col_off = 512;
        for (int i = 2; i < 8; i++) gb.e[i] = gb.e[0];
        dim3 grid(PROJ / 64, MTOT / 128, 2);
        gemm_mma<<<grid, 256>>>(gb);
    }
}

// round 14
// speedup vs baseline: 2.9622x; 1.2288x over previous
#include <cuda_runtime.h>
#include <cuda_fp16.h>
#include <cstdint>

#define SLEN   2048
#define NBATCH 2
#define DMODEL 1024
#define PROJ   512
#define MTOT   (NBATCH*SLEN)

__device__ __half g_rel[(size_t)NBATCH*8*SLEN*SLEN];   // fp16 rel, 134 MB

__device__ __half g_xhi[MTOT*DMODEL], g_xlo[MTOT*DMODEL];
__device__ __half g_shi[MTOT*DMODEL], g_slo[MTOT*DMODEL];
#define WTOT (8*PROJ*DMODEL + 2*PROJ*PROJ)
__device__ __half g_w[WTOT];                            // weights single fp16
__device__ __half g_chi[2*MTOT*PROJ], g_clo[2*MTOT*PROJ];
__device__ __half g_qhi [MTOT*PROJ], g_qlo [MTOT*PROJ];
__device__ __half g_qahi[MTOT*PROJ], g_qalo[MTOT*PROJ];
__device__ __half g_qrhi[MTOT*PROJ], g_qrlo[MTOT*PROJ];
__device__ __half g_k [MTOT*PROJ];
__device__ __half g_ka[MTOT*PROJ];
__device__ __half g_v [MTOT*PROJ];
__device__ __half g_sv[MTOT*PROJ];
__device__ __half g_kr[MTOT*PROJ];

__device__ __forceinline__ uint32_t smem_u32(const void* p) {
    uint32_t a;
    asm("{ .reg .u64 t; cvta.to.shared.u64 t, %1; cvt.u32.u64 %0, t; }" : "=r"(a) : "l"(p));
    return a;
}
__device__ __forceinline__ void ldsm4(uint32_t* r, uint32_t a) {
    asm volatile("ldmatrix.sync.aligned.m8n8.x4.shared.b16 {%0,%1,%2,%3}, [%4];"
        : "=r"(r[0]), "=r"(r[1]), "=r"(r[2]), "=r"(r[3]) : "r"(a));
}
__device__ __forceinline__ void ldsm4t(uint32_t* r, uint32_t a) {
    asm volatile("ldmatrix.sync.aligned.m8n8.x4.trans.shared.b16 {%0,%1,%2,%3}, [%4];"
        : "=r"(r[0]), "=r"(r[1]), "=r"(r[2]), "=r"(r[3]) : "r"(a));
}
__device__ __forceinline__ void mma16816(float* c, const uint32_t* a, const uint32_t* b) {
    asm volatile("mma.sync.aligned.m16n8k16.row.col.f32.f16.f16.f32 "
        "{%0,%1,%2,%3}, {%4,%5,%6,%7}, {%8,%9}, {%0,%1,%2,%3};"
        : "+f"(c[0]), "+f"(c[1]), "+f"(c[2]), "+f"(c[3])
        : "r"(a[0]), "r"(a[1]), "r"(a[2]), "r"(a[3]), "r"(b[0]), "r"(b[1]));
}
__device__ __forceinline__ uint32_t hcvt2hi(float a, float b) {
    __half2 h = __floats2half2_rn(a, b);
    return *reinterpret_cast<uint32_t*>(&h);
}
__device__ __forceinline__ uint32_t hcvt2lo(float a, float b, uint32_t hp) {
    __half2 h = *reinterpret_cast<__half2*>(&hp);
    return hcvt2hi(a - __half2float(h.x), b - __half2float(h.y));
}
#define BARG(id) asm volatile("bar.sync %0, 128;" :: "r"(id))

// ------------- batched fp32 -> fp16 convert / split ------------------------------
struct SEntry { const float* s; __half *hi, *lo; int n; };
struct SBatch { SEntry e[10]; };
__global__ __launch_bounds__(256) void split_multi(SBatch sb)
{
    SEntry en = sb.e[blockIdx.y];
    int i = blockIdx.x * 256 + threadIdx.x;
    if (i < en.n) {
        float v = en.s[i];
        __half h = __float2half(v);
        en.hi[i] = h;
        if (en.lo) en.lo[i] = __float2half(v - __half2float(h));
    }
}

// ------------- HMMA batched GEMM (A split fp16, B single fp16) -------------------
// modes: 0 fp32 out, 1 single fp16, 2 split fp16, 3 rope+single, 4 rope+scale+split
struct GEntry {
    const __half *ahi, *alo, *b;
    float* y;
    __half *yhi, *ylo;
    int ldy, col_off, mode;
};
struct GBatch { GEntry e[8]; const float *fc, *fs; int K; };

__global__ __launch_bounds__(256, 2) void gemm_mma(GBatch args)
{
    const GEntry ge = args.e[blockIdx.z];
    const int K = args.K;
    __shared__ __align__(16) __half sA[2][128][40];
    __shared__ __align__(16) __half sB[64][40];

    const int tid = threadIdx.x, lane = tid & 31, wid = tid >> 5;
    const int warpM = wid & 3, warpN = wid >> 2;
    const int mBase = blockIdx.y * 128, nBase = blockIdx.x * 64;

    float acc[2][4][4];
#pragma unroll
    for (int i = 0; i < 2; i++)
#pragma unroll
        for (int j = 0; j < 4; j++)
#pragma unroll
            for (int t = 0; t < 4; t++) acc[i][j][t] = 0.f;

    const int ar = tid >> 2, ag = (tid & 3) * 8;

    uint32_t aAdH[2], aAdL[2], bAd[2];
#pragma unroll
    for (int t = 0; t < 2; t++) {
        int rA = warpM * 32 + t * 16 + (lane & 15), cA = (lane >> 4) * 8;
        aAdH[t] = smem_u32(&sA[0][rA][cA]);
        aAdL[t] = smem_u32(&sA[1][rA][cA]);
        int rB = warpN * 32 + t * 16 + ((lane >> 4) << 3) + (lane & 7);
        int cB = ((lane >> 3) & 1) * 8;
        bAd[t] = smem_u32(&sB[rB][cB]);
    }

    uint4 pAh[2], pAl[2], pB;
    const int NC = K / 32;
    {
        pAh[0] = *reinterpret_cast<const uint4*>(ge.ahi + (size_t)(mBase + ar) * K + ag);
        pAl[0] = *reinterpret_cast<const uint4*>(ge.alo + (size_t)(mBase + ar) * K + ag);
        pAh[1] = *reinterpret_cast<const uint4*>(ge.ahi + (size_t)(mBase + ar + 64) * K + ag);
        pAl[1] = *reinterpret_cast<const uint4*>(ge.alo + (size_t)(mBase + ar + 64) * K + ag);
        pB     = *reinterpret_cast<const uint4*>(ge.b   + (size_t)(nBase + ar) * K + ag);
    }

    for (int c = 0; c < NC; c++) {
        if (c) __syncthreads();
        *reinterpret_cast<uint4*>(&sA[0][ar][ag])      = pAh[0];
        *reinterpret_cast<uint4*>(&sA[1][ar][ag])      = pAl[0];
        *reinterpret_cast<uint4*>(&sA[0][ar + 64][ag]) = pAh[1];
        *reinterpret_cast<uint4*>(&sA[1][ar + 64][ag]) = pAl[1];
        *reinterpret_cast<uint4*>(&sB[ar][ag])         = pB;
        __syncthreads();
        if (c + 1 < NC) {
            const int kof = (c + 1) * 32 + ag;
            pAh[0] = *reinterpret_cast<const uint4*>(ge.ahi + (size_t)(mBase + ar) * K + kof);
            pAl[0] = *reinterpret_cast<const uint4*>(ge.alo + (size_t)(mBase + ar) * K + kof);
            pAh[1] = *reinterpret_cast<const uint4*>(ge.ahi + (size_t)(mBase + ar + 64) * K + kof);
            pAl[1] = *reinterpret_cast<const uint4*>(ge.alo + (size_t)(mBase + ar + 64) * K + kof);
            pB     = *reinterpret_cast<const uint4*>(ge.b   + (size_t)(nBase + ar) * K + kof);
        }
#pragma unroll
        for (int ks = 0; ks < 2; ks++) {
            const uint32_t off = ks * 32;
            uint32_t ah[2][4], al[2][4], bh[2][4];
            ldsm4(ah[0], aAdH[0] + off);  ldsm4(ah[1], aAdH[1] + off);
            ldsm4(al[0], aAdL[0] + off);  ldsm4(al[1], aAdL[1] + off);
            ldsm4(bh[0], bAd[0] + off);   ldsm4(bh[1], bAd[1] + off);
#pragma unroll
            for (int i = 0; i < 2; i++)
#pragma unroll
                for (int j = 0; j < 4; j++) {
                    const uint32_t* bhp = &bh[j >> 1][(j & 1) * 2];
                    mma16816(acc[i][j], ah[i], bhp);
                    mma16816(acc[i][j], al[i], bhp);
                }
        }
    }

    const int mrow = lane >> 2, ncol = (lane & 3) * 2;
#pragma unroll
    for (int i = 0; i < 2; i++)
#pragma unroll
        for (int j = 0; j < 4; j++) {
            int m0 = mBase + warpM * 32 + i * 16 + mrow;
            int n  = nBase + warpN * 32 + j * 8 + ncol;
#pragma unroll
            for (int half = 0; half < 2; half++) {
                int m = m0 + half * 8;
                float c0 = acc[i][j][half * 2], c1 = acc[i][j][half * 2 + 1];
                if (ge.mode >= 3) {
                    int srow = m & (SLEN - 1);
                    int t = (n & 63) >> 1;
                    float cz = args.fc[srow * 32 + t], sz = args.fs[srow * 32 + t];
                    float xr = c0, xi = c1;
                    c0 = xr * cz - xi * sz;
                    c1 = xr * sz + xi * cz;
                }
                if (ge.mode == 4) { c0 *= 0.125f; c1 *= 0.125f; }
                if (ge.mode == 0) {
                    *reinterpret_cast<float2*>(&ge.y[(size_t)m * ge.ldy + ge.col_off + n]) =
                        make_float2(c0, c1);
                } else {
                    uint32_t hp = hcvt2hi(c0, c1);
                    *reinterpret_cast<uint32_t*>(&ge.yhi[(size_t)m * PROJ + n]) = hp;
                    if (ge.mode == 2 || ge.mode == 4) {
                        uint32_t lp = hcvt2lo(c0, c1, hp);
                        *reinterpret_cast<uint32_t*>(&ge.ylo[(size_t)m * PROJ + n]) = lp;
                    }
                }
            }
        }
}

// ------------- rel[b,r,i,j] = 0.125 * qr·kr -> fp16, lower-triangular tiles ------
__global__ __launch_bounds__(256, 2) void rel_mma()
{
    const int mBase = blockIdx.y * 128, nBase = blockIdx.x * 64;
    if (nBase > mBase + 127) return;
    const int br = blockIdx.z, b = br >> 3, r = br & 7;

    __shared__ __align__(16) __half sA[2][128][40];
    __shared__ __align__(16) __half sB[64][40];
    const int tid = threadIdx.x, lane = tid & 31, wid = tid >> 5;
    const int warpM = wid & 3, warpN = wid >> 2;

    const __half* Ah = g_qrhi + ((size_t)(b * SLEN + mBase)) * PROJ + r * 64;
    const __half* Al = g_qrlo + ((size_t)(b * SLEN + mBase)) * PROJ + r * 64;
    const __half* Bh = g_kr   + ((size_t)(b * SLEN + nBase)) * PROJ + r * 64;

    float acc[2][4][4];
#pragma unroll
    for (int i = 0; i < 2; i++)
#pragma unroll
        for (int j = 0; j < 4; j++)
#pragma unroll
            for (int t = 0; t < 4; t++) acc[i][j][t] = 0.f;

    const int ar = tid >> 2, ag = (tid & 3) * 8;
    uint32_t aAdH[2], aAdL[2], bAd[2];
#pragma unroll
    for (int t = 0; t < 2; t++) {
        int rA = warpM * 32 + t * 16 + (lane & 15), cA = (lane >> 4) * 8;
        aAdH[t] = smem_u32(&sA[0][rA][cA]);
        aAdL[t] = smem_u32(&sA[1][rA][cA]);
        int rB = warpN * 32 + t * 16 + ((lane >> 4) << 3) + (lane & 7);
        int cB = ((lane >> 3) & 1) * 8;
        bAd[t] = smem_u32(&sB[rB][cB]);
    }

    for (int c = 0; c < 2; c++) {
        const int kof = c * 32 + ag;
        if (c) __syncthreads();
        *reinterpret_cast<uint4*>(&sA[0][ar][ag])      = *reinterpret_cast<const uint4*>(Ah + (size_t)ar * PROJ + kof);
        *reinterpret_cast<uint4*>(&sA[1][ar][ag])      = *reinterpret_cast<const uint4*>(Al + (size_t)ar * PROJ + kof);
        *reinterpret_cast<uint4*>(&sA[0][ar + 64][ag]) = *reinterpret_cast<const uint4*>(Ah + (size_t)(ar + 64) * PROJ + kof);
        *reinterpret_cast<uint4*>(&sA[1][ar + 64][ag]) = *reinterpret_cast<const uint4*>(Al + (size_t)(ar + 64) * PROJ + kof);
        *reinterpret_cast<uint4*>(&sB[ar][ag])         = *reinterpret_cast<const uint4*>(Bh + (size_t)ar * PROJ + kof);
        __syncthreads();
#pragma unroll
        for (int ks = 0; ks < 2; ks++) {
            const uint32_t off = ks * 32;
            uint32_t ah[2][4], al[2][4], bh[2][4];
            ldsm4(ah[0], aAdH[0] + off);  ldsm4(ah[1], aAdH[1] + off);
            ldsm4(al[0], aAdL[0] + off);  ldsm4(al[1], aAdL[1] + off);
            ldsm4(bh[0], bAd[0] + off);   ldsm4(bh[1], bAd[1] + off);
#pragma unroll
            for (int i = 0; i < 2; i++)
#pragma unroll
                for (int j = 0; j < 4; j++) {
                    const uint32_t* bhp = &bh[j >> 1][(j & 1) * 2];
                    mma16816(acc[i][j], ah[i], bhp);
                    mma16816(acc[i][j], al[i], bhp);
                }
        }
    }

    __half* out = g_rel + ((size_t)br * SLEN + mBase) * SLEN + nBase;
    const int mrow = lane >> 2, ncol = (lane & 3) * 2;
#pragma unroll
    for (int i = 0; i < 2; i++)
#pragma unroll
        for (int j = 0; j < 4; j++) {
            int m0 = warpM * 32 + i * 16 + mrow;
            int n  = warpN * 32 + j * 8 + ncol;
#pragma unroll
            for (int half = 0; half < 2; half++) {
                __half2 hv = __floats2half2_rn(acc[i][j][half * 2] * 0.125f,
                                               acc[i][j][half * 2 + 1] * 0.125f);
                *reinterpret_cast<__half2*>(&out[(size_t)(m0 + half * 8) * SLEN + n]) = hv;
            }
        }
}

// ------------- HMMA flash attention: 64x64 tiles, split-KV warp groups -----------
// Static smem: sKV[grp] = K plane (4608 halves) + V plane (4608 halves).
// Q staged in sKV[0] (hi @0, lo @4608 halves = +9216 bytes).
// Merge: mO = (float*)sKV[1], mAr = (float*)sKV[0].
template<bool RA>
__global__ __launch_bounds__(256) void flash_mma(
    const __half* __restrict__ Qh_, const __half* __restrict__ Ql_,
    const __half* __restrict__ Kh_, const __half* __restrict__ Vh_,
    const float* __restrict__ WR,
    __half* __restrict__ Ohi, __half* __restrict__ Olo)
{
    __shared__ __align__(16) __half sKV[2][9216];
    __shared__ float s_wrs[512];
    __shared__ float s_mSt[128];

    const int bh = blockIdx.y, b = bh >> 3, h = bh & 7, it = blockIdx.x;
    const int tid = threadIdx.x, lane = tid & 31, wid = tid >> 5;
    const int grp = wid >> 2, wq = wid & 3;
    __half* sK = sKV[grp];
    __half* sV = sK + 4608;
    float* mO  = (float*)sKV[1];
    float* mAr = (float*)sKV[0];

    // stage Q (hi @0, lo @4608 halves)
    {
        __half* sQ = sKV[0];
#pragma unroll
        for (int u = 0; u < 2; u++) {
            int e = tid + u * 256, row = e >> 3, gg = e & 7;
            size_t gq = ((size_t)(b * SLEN + it * 64 + row)) * PROJ + h * 64 + gg * 8;
            *reinterpret_cast<uint4*>(&sQ[row * 72 + gg * 8])        = *reinterpret_cast<const uint4*>(&Qh_[gq]);
            *reinterpret_cast<uint4*>(&sQ[4608 + row * 72 + gg * 8]) = *reinterpret_cast<const uint4*>(&Ql_[gq]);
        }
    }
    if (RA) { s_wrs[tid] = WR[h * 512 + tid]; s_wrs[256 + tid] = WR[h * 512 + 256 + tid]; }
    __syncthreads();
    uint32_t qh[4][4], ql[4][4];
    {
        uint32_t ah = smem_u32(&sKV[0][(wq * 16 + (lane & 15)) * 72 + (lane >> 4) * 8]);
#pragma unroll
        for (int ks = 0; ks < 4; ks++) { ldsm4(qh[ks], ah + ks * 32); ldsm4(ql[ks], ah + 9216 + ks * 32); }
    }
    __syncthreads();

    uint32_t kAd[4], vAd[4];
#pragma unroll
    for (int t = 0; t < 4; t++) {
        int rK = t * 16 + ((lane >> 4) << 3) + (lane & 7), cK = ((lane >> 3) & 1) * 8;
        kAd[t] = smem_u32(&sK[rK * 72 + cK]);
        int rV = t * 16 + ((lane >> 3) & 1) * 8 + (lane & 7), cV = (lane >> 4) * 8;
        vAd[t] = smem_u32(&sV[rV * 72 + cV]);
    }

    float o[8][4];
#pragma unroll
    for (int nb = 0; nb < 8; nb++)
#pragma unroll
        for (int t = 0; t < 4; t++) o[nb][t] = 0.f;
    float arr[2][8];
    if (RA) {
#pragma unroll
        for (int hh = 0; hh < 2; hh++)
#pragma unroll
            for (int r = 0; r < 8; r++) arr[hh][r] = 0.f;
    }
    float m0 = -1e30f, m1 = -1e30f, l0 = 0.f, l1 = 0.f;
    const int row0 = lane >> 2, c0 = (lane & 3) * 2;
    const int lt = tid & 127;

    for (int jt = grp; jt <= it; jt += 2) {
        BARG(grp + 1);
#pragma unroll
        for (int u = 0; u < 4; u++) {
            int e = lt + u * 128, row = e >> 3, gg = e & 7;
            size_t gi = ((size_t)(b * SLEN + jt * 64 + row)) * PROJ + h * 64 + gg * 8;
            *reinterpret_cast<uint4*>(&sK[row * 72 + gg * 8]) = *reinterpret_cast<const uint4*>(&Kh_[gi]);
            *reinterpret_cast<uint4*>(&sV[row * 72 + gg * 8]) = *reinterpret_cast<const uint4*>(&Vh_[gi]);
        }
        BARG(grp + 1);

        float s[8][4];
#pragma unroll
        for (int nb = 0; nb < 8; nb++)
#pragma unroll
            for (int t = 0; t < 4; t++) s[nb][t] = 0.f;
#pragma unroll
        for (int ks = 0; ks < 4; ks++)
#pragma unroll
            for (int t = 0; t < 4; t++) {
                uint32_t kh2[4];
                ldsm4(kh2, kAd[t] + ks * 32);
#pragma unroll
                for (int half = 0; half < 2; half++) {
                    int nb = t * 2 + half;
                    mma16816(s[nb], qh[ks], &kh2[half * 2]);
                    mma16816(s[nb], ql[ks], &kh2[half * 2]);
                }
            }
        if (jt == it) {
            int gi0 = wq * 16 + row0;
#pragma unroll
            for (int nb = 0; nb < 8; nb++) {
                int gj = nb * 8 + c0;
                if (gj     > gi0)     s[nb][0] = -1e30f;
                if (gj + 1 > gi0)     s[nb][1] = -1e30f;
                if (gj     > gi0 + 8) s[nb][2] = -1e30f;
                if (gj + 1 > gi0 + 8) s[nb][3] = -1e30f;
            }
        }
        float rm0 = -1e30f, rm1 = -1e30f;
#pragma unroll
        for (int nb = 0; nb < 8; nb++) {
            rm0 = fmaxf(rm0, fmaxf(s[nb][0], s[nb][1]));
            rm1 = fmaxf(rm1, fmaxf(s[nb][2], s[nb][3]));
        }
        rm0 = fmaxf(rm0, __shfl_xor_sync(0xffffffffu, rm0, 1));
        rm0 = fmaxf(rm0, __shfl_xor_sync(0xffffffffu, rm0, 2));
        rm1 = fmaxf(rm1, __shfl_xor_sync(0xffffffffu, rm1, 1));
        rm1 = fmaxf(rm1, __shfl_xor_sync(0xffffffffu, rm1, 2));
        float nm0 = fmaxf(m0, rm0), nm1 = fmaxf(m1, rm1);
        float sc0 = __expf(m0 - nm0), sc1 = __expf(m1 - nm1);
        m0 = nm0; m1 = nm1;
        float rs0 = 0.f, rs1 = 0.f;
#pragma unroll
        for (int nb = 0; nb < 8; nb++) {
            s[nb][0] = __expf(s[nb][0] - nm0);
            s[nb][1] = __expf(s[nb][1] - nm0);
            s[nb][2] = __expf(s[nb][2] - nm1);
            s[nb][3] = __expf(s[nb][3] - nm1);
            rs0 += s[nb][0] + s[nb][1];
            rs1 += s[nb][2] + s[nb][3];
        }
        rs0 += __shfl_xor_sync(0xffffffffu, rs0, 1);
        rs0 += __shfl_xor_sync(0xffffffffu, rs0, 2);
        rs1 += __shfl_xor_sync(0xffffffffu, rs1, 1);
        rs1 += __shfl_xor_sync(0xffffffffu, rs1, 2);
        l0 = l0 * sc0 + rs0;
        l1 = l1 * sc1 + rs1;
#pragma unroll
        for (int nb = 0; nb < 8; nb++) {
            o[nb][0] *= sc0; o[nb][1] *= sc0; o[nb][2] *= sc1; o[nb][3] *= sc1;
        }
        if (RA) {
#pragma unroll
            for (int r = 0; r < 8; r++) { arr[0][r] *= sc0; arr[1][r] *= sc1; }
            int gi0 = it * 64 + wq * 16 + row0;
            int gj0 = jt * 64 + c0;
#pragma unroll
            for (int r = 0; r < 8; r++) {
                const __half2* rp0 = reinterpret_cast<const __half2*>(
                    g_rel + (((size_t)(b * 8 + r)) * SLEN + gi0) * SLEN + gj0);
                const __half2* rp1 = reinterpret_cast<const __half2*>(
                    g_rel + (((size_t)(b * 8 + r)) * SLEN + gi0 + 8) * SLEN + gj0);
#pragma unroll
                for (int nb = 0; nb < 8; nb++) {
                    float2 rv0 = __half22float2(rp0[nb * 4]);
                    float2 rv1 = __half22float2(rp1[nb * 4]);
                    arr[0][r] = fmaf(s[nb][0], rv0.x, fmaf(s[nb][1], rv0.y, arr[0][r]));
                    arr[1][r] = fmaf(s[nb][2], rv1.x, fmaf(s[nb][3], rv1.y, arr[1][r]));
                }
            }
        }
#pragma unroll
        for (int jk = 0; jk < 4; jk++) {
            uint32_t ph[4], pl[4];
            ph[0] = hcvt2hi(s[2*jk][0],   s[2*jk][1]);
            ph[1] = hcvt2hi(s[2*jk][2],   s[2*jk][3]);
            ph[2] = hcvt2hi(s[2*jk+1][0], s[2*jk+1][1]);
            ph[3] = hcvt2hi(s[2*jk+1][2], s[2*jk+1][3]);
            pl[0] = hcvt2lo(s[2*jk][0],   s[2*jk][1],   ph[0]);
            pl[1] = hcvt2lo(s[2*jk][2],   s[2*jk][3],   ph[1]);
            pl[2] = hcvt2lo(s[2*jk+1][0], s[2*jk+1][1], ph[2]);
            pl[3] = hcvt2lo(s[2*jk+1][2], s[2*jk+1][3], ph[3]);
#pragma unroll
            for (int db = 0; db < 4; db++) {
                uint32_t vh2[4];
                ldsm4t(vh2, vAd[jk] + db * 32);
#pragma unroll
                for (int half = 0; half < 2; half++) {
                    int nb = db * 2 + half;
                    mma16816(o[nb], ph, &vh2[half * 2]);
                    mma16816(o[nb], pl, &vh2[half * 2]);
                }
            }
        }
    }

    __syncthreads();
    if (grp == 1) {
#pragma unroll
        for (int nb = 0; nb < 8; nb++) {
            *reinterpret_cast<float2*>(&mO[(wq * 16 + row0) * 64 + nb * 8 + c0])     = make_float2(o[nb][0], o[nb][1]);
            *reinterpret_cast<float2*>(&mO[(wq * 16 + row0 + 8) * 64 + nb * 8 + c0]) = make_float2(o[nb][2], o[nb][3]);
        }
        if ((lane & 3) == 0) {
            s_mSt[(wq * 16 + row0) * 2]         = m0;
            s_mSt[(wq * 16 + row0) * 2 + 1]     = l0;
            s_mSt[(wq * 16 + row0 + 8) * 2]     = m1;
            s_mSt[(wq * 16 + row0 + 8) * 2 + 1] = l1;
        }
        if (RA) {
#pragma unroll
            for (int hh = 0; hh < 2; hh++)
#pragma unroll
                for (int r = 0; r < 8; r++) {
                    arr[hh][r] += __shfl_xor_sync(0xffffffffu, arr[hh][r], 1);
                    arr[hh][r] += __shfl_xor_sync(0xffffffffu, arr[hh][r], 2);
                }
            if ((lane & 3) == 0)
#pragma unroll
                for (int r = 0; r < 8; r++) {
                    mAr[(wq * 16 + row0) * 8 + r]     = arr[0][r];
                    mAr[(wq * 16 + row0 + 8) * 8 + r] = arr[1][r];
                }
        }
    }
    __syncthreads();
    if (grp == 0) {
        if (RA) {
#pragma unroll
            for (int hh = 0; hh < 2; hh++)
#pragma unroll
                for (int r = 0; r < 8; r++) {
                    arr[hh][r] += __shfl_xor_sync(0xffffffffu, arr[hh][r], 1);
                    arr[hh][r] += __shfl_xor_sync(0xffffffffu, arr[hh][r], 2);
                }
        }
#pragma unroll
        for (int half = 0; half < 2; half++) {
            int rr = wq * 16 + row0 + half * 8;
            float mo = half ? m1 : m0, lo_ = half ? l1 : l0;
            float m2 = s_mSt[rr * 2], l2 = s_mSt[rr * 2 + 1];
            float mf = fmaxf(mo, m2);
            float e1 = __expf(mo - mf), e2 = __expf(m2 - mf);
            float inv = 1.f / (lo_ * e1 + l2 * e2);
            float arf[8];
            if (RA)
#pragma unroll
                for (int r = 0; r < 8; r++)
                    arf[r] = (arr[half][r] * e1 + mAr[rr * 8 + r] * e2) * inv;
#pragma unroll
            for (int nb = 0; nb < 8; nb++) {
                float2 o2 = *reinterpret_cast<float2*>(&mO[rr * 64 + nb * 8 + c0]);
                float v0 = (o[nb][half * 2] * e1     + o2.x * e2) * inv;
                float v1 = (o[nb][half * 2 + 1] * e1 + o2.y * e2) * inv;
                if (RA) {
                    int d0 = nb * 8 + c0;
                    float r0s = 0.f, r1s = 0.f;
#pragma unroll
                    for (int r = 0; r < 8; r++) {
                        r0s = fmaf(arf[r], s_wrs[d0 * 8 + r], r0s);
                        r1s = fmaf(arf[r], s_wrs[(d0 + 1) * 8 + r], r1s);
                    }
                    v0 += r0s; v1 += r1s;
                }
                size_t oo = ((size_t)(b * SLEN + it * 64 + rr)) * PROJ + h * 64 + nb * 8 + c0;
                uint32_t hp = hcvt2hi(v0, v1), lp = hcvt2lo(v0, v1, hp);
                *reinterpret_cast<uint32_t*>(&Ohi[oo]) = hp;
                *reinterpret_cast<uint32_t*>(&Olo[oo]) = lp;
            }
        }
    }
}

// ---------------- host launcher --------------------------------------------------
extern "C" void kernel_launch(void* const* d_in, const int* in_sizes, int n_in,
                              void* d_out, int out_size)
{
    const float* x       = (const float*)d_in[0];
    const float* symbols = (const float*)d_in[1];
    const float* fc      = (const float*)d_in[2];
    const float* fs      = (const float*)d_in[3];
    const float* wsrc[10] = {
        (const float*)d_in[4],  (const float*)d_in[5],  (const float*)d_in[6],
        (const float*)d_in[8],  (const float*)d_in[9],  (const float*)d_in[10],
        (const float*)d_in[11], (const float*)d_in[13], (const float*)d_in[7],
        (const float*)d_in[14],
    };
    const float* wr = (const float*)d_in[12];
    float* out = (float*)d_out;

    __half *xhi, *xlo, *shi, *slo, *w, *chi, *clo;
    __half *qhi, *qlo, *qahi, *qalo, *qrhi, *qrlo;
    __half *k, *ka, *v, *sv, *kr;
    cudaGetSymbolAddress((void**)&xhi, g_xhi);   cudaGetSymbolAddress((void**)&xlo, g_xlo);
    cudaGetSymbolAddress((void**)&shi, g_shi);   cudaGetSymbolAddress((void**)&slo, g_slo);
    cudaGetSymbolAddress((void**)&w,   g_w);
    cudaGetSymbolAddress((void**)&chi, g_chi);   cudaGetSymbolAddress((void**)&clo, g_clo);
    cudaGetSymbolAddress((void**)&qhi, g_qhi);   cudaGetSymbolAddress((void**)&qlo, g_qlo);
    cudaGetSymbolAddress((void**)&qahi, g_qahi); cudaGetSymbolAddress((void**)&qalo, g_qalo);
    cudaGetSymbolAddress((void**)&qrhi, g_qrhi); cudaGetSymbolAddress((void**)&qrlo, g_qrlo);
    cudaGetSymbolAddress((void**)&k,  g_k);
    cudaGetSymbolAddress((void**)&ka, g_ka);
    cudaGetSymbolAddress((void**)&v,  g_v);
    cudaGetSymbolAddress((void**)&sv, g_sv);
    cudaGetSymbolAddress((void**)&kr, g_kr);

    const int wsz[10] = { PROJ*DMODEL, PROJ*DMODEL, PROJ*DMODEL, PROJ*DMODEL, PROJ*DMODEL,
                          PROJ*DMODEL, PROJ*DMODEL, PROJ*DMODEL, PROJ*PROJ, PROJ*PROJ };
    size_t woff[10];
    { size_t o = 0; for (int i = 0; i < 10; i++) { woff[i] = o; o += wsz[i]; } }

    // split launch A: x + symbols (hi/lo)
    {
        SBatch sb;
        sb.e[0] = { x,       xhi, xlo, MTOT * DMODEL };
        sb.e[1] = { symbols, shi, slo, MTOT * DMODEL };
        for (int i = 2; i < 10; i++) sb.e[i] = sb.e[0];
        dim3 grid((MTOT * DMODEL + 255) / 256, 2);
        split_multi<<<grid, 256>>>(sb);
    }
    // split launch B: 10 weights, single fp16
    {
        SBatch sb;
        for (int i = 0; i < 10; i++)
            sb.e[i] = { wsrc[i], w + woff[i], nullptr, wsz[i] };
        dim3 grid((PROJ * DMODEL + 255) / 256, 10);
        split_multi<<<grid, 256>>>(sb);
    }

    // projections
    // modes: q 4, k 3, v 1, qa 4, ka 3, qr 2, kr 1, sv 1
    {
        GBatch gb;
        gb.fc = fc; gb.fs = fs; gb.K = DMODEL;
        __half* yh[8] = { qhi, k, v, qahi, ka, qrhi, kr, sv };
        __half* yl[8] = { qlo, nullptr, nullptr, qalo, nullptr, qrlo, nullptr, nullptr };
        int modes[8] = { 4, 3, 1, 4, 3, 2, 1, 1 };
        for (int i = 0; i < 8; i++) {
            gb.e[i].ahi = (i == 7) ? shi : xhi;
            gb.e[i].alo = (i == 7) ? slo : xlo;
            gb.e[i].b = w + woff[i];
            gb.e[i].y = nullptr; gb.e[i].ldy = PROJ; gb.e[i].col_off = 0;
            gb.e[i].mode = modes[i]; gb.e[i].yhi = yh[i]; gb.e[i].ylo = yl[i];
        }
        dim3 grid(PROJ / 64, MTOT / 128, 8);
        gemm_mma<<<grid, 256>>>(gb);
    }

    { dim3 grid(SLEN / 64, SLEN / 128, NBATCH * 8); rel_mma<<<grid, 256>>>(); }

    // flash attentions
    {
        dim3 gfl(SLEN / 64, NBATCH * 8);
        flash_mma<false><<<gfl, 256>>>(qhi, qlo, k, v, nullptr, chi, clo);
        flash_mma<true ><<<gfl, 256>>>(qahi, qalo, ka, sv, wr,
                                       chi + (size_t)MTOT * PROJ, clo + (size_t)MTOT * PROJ);
    }

    // output projections -> fp32 halves of out
    {
        GBatch gb;
        gb.fc = fc; gb.fs = fs; gb.K = PROJ;
        gb.e[0].ahi = chi; gb.e[0].alo = clo;
        gb.e[0].b = w + woff[8];
        gb.e[0].y = out; gb.e[0].ldy = DMODEL; gb.e[0].col_off = 0; gb.e[0].mode = 0;
        gb.e[0].yhi = nullptr; gb.e[0].ylo = nullptr;
        gb.e[1] = gb.e[0];
        gb.e[1].ahi = chi + (size_t)MTOT * PROJ; gb.e[1].alo = clo + (size_t)MTOT * PROJ;
        gb.e[1].b = w + woff[9];
        gb.e[1].col_off = 512;
        for (int i = 2; i < 8; i++) gb.e[i] = gb.e[0];
        dim3 grid(PROJ / 64, MTOT / 128, 2);
        gemm_mma<<<grid, 256>>>(gb);
    }
}

// round 16
// speedup vs baseline: 3.3175x; 1.1199x over previous
#include <cuda_runtime.h>
#include <cuda_fp16.h>
#include <cstdint>

#define SLEN   2048
#define NBATCH 2
#define DMODEL 1024
#define PROJ   512
#define MTOT   (NBATCH*SLEN)

// rel stored TRANSPOSED: [b][i][j][r], 8 fp16 r-values contiguous per (i,j)
__device__ __half g_rel[(size_t)NBATCH*SLEN*SLEN*8];

__device__ __half g_xhi[MTOT*DMODEL], g_xlo[MTOT*DMODEL];
__device__ __half g_shi[MTOT*DMODEL], g_slo[MTOT*DMODEL];
#define WTOT (8*PROJ*DMODEL + 2*PROJ*PROJ)
__device__ __half g_w[WTOT];
__device__ __half g_chi[2*MTOT*PROJ], g_clo[2*MTOT*PROJ];
__device__ __half g_qhi [MTOT*PROJ], g_qlo [MTOT*PROJ];
__device__ __half g_qahi[MTOT*PROJ], g_qalo[MTOT*PROJ];
__device__ __half g_qrhi[MTOT*PROJ], g_qrlo[MTOT*PROJ];
__device__ __half g_k [MTOT*PROJ];
__device__ __half g_ka[MTOT*PROJ];
__device__ __half g_v [MTOT*PROJ];
__device__ __half g_sv[MTOT*PROJ];
__device__ __half g_kr[MTOT*PROJ];

__device__ __forceinline__ uint32_t smem_u32(const void* p) {
    uint32_t a;
    asm("{ .reg .u64 t; cvta.to.shared.u64 t, %1; cvt.u32.u64 %0, t; }" : "=r"(a) : "l"(p));
    return a;
}
__device__ __forceinline__ void ldsm4(uint32_t* r, uint32_t a) {
    asm volatile("ldmatrix.sync.aligned.m8n8.x4.shared.b16 {%0,%1,%2,%3}, [%4];"
        : "=r"(r[0]), "=r"(r[1]), "=r"(r[2]), "=r"(r[3]) : "r"(a));
}
__device__ __forceinline__ void ldsm4t(uint32_t* r, uint32_t a) {
    asm volatile("ldmatrix.sync.aligned.m8n8.x4.trans.shared.b16 {%0,%1,%2,%3}, [%4];"
        : "=r"(r[0]), "=r"(r[1]), "=r"(r[2]), "=r"(r[3]) : "r"(a));
}
__device__ __forceinline__ void mma16816(float* c, const uint32_t* a, const uint32_t* b) {
    asm volatile("mma.sync.aligned.m16n8k16.row.col.f32.f16.f16.f32 "
        "{%0,%1,%2,%3}, {%4,%5,%6,%7}, {%8,%9}, {%0,%1,%2,%3};"
        : "+f"(c[0]), "+f"(c[1]), "+f"(c[2]), "+f"(c[3])
        : "r"(a[0]), "r"(a[1]), "r"(a[2]), "r"(a[3]), "r"(b[0]), "r"(b[1]));
}
__device__ __forceinline__ uint32_t hcvt2hi(float a, float b) {
    __half2 h = __floats2half2_rn(a, b);
    return *reinterpret_cast<uint32_t*>(&h);
}
__device__ __forceinline__ uint32_t hcvt2lo(float a, float b, uint32_t hp) {
    __half2 h = *reinterpret_cast<__half2*>(&hp);
    return hcvt2hi(a - __half2float(h.x), b - __half2float(h.y));
}
#define BARG(id) asm volatile("bar.sync %0, 128;" :: "r"(id))

// ------------- batched fp32 -> fp16 convert / split ------------------------------
struct SEntry { const float* s; __half *hi, *lo; int n; };
struct SBatch { SEntry e[10]; };
__global__ __launch_bounds__(256) void split_multi(SBatch sb)
{
    SEntry en = sb.e[blockIdx.y];
    int i = blockIdx.x * 256 + threadIdx.x;
    if (i < en.n) {
        float v = en.s[i];
        __half h = __float2half(v);
        en.hi[i] = h;
        if (en.lo) en.lo[i] = __float2half(v - __half2float(h));
    }
}

// ------------- HMMA batched GEMM (A split fp16, B single fp16) -------------------
// modes: 0 fp32 out, 1 single fp16, 2 split fp16, 3 rope+single, 4 rope+scale+split
struct GEntry {
    const __half *ahi, *alo, *b;
    float* y;
    __half *yhi, *ylo;
    int ldy, col_off, mode;
};
struct GBatch { GEntry e[8]; const float *fc, *fs; int K; };

__global__ __launch_bounds__(256, 2) void gemm_mma(GBatch args)
{
    const GEntry ge = args.e[blockIdx.z];
    const int K = args.K;
    __shared__ __align__(16) __half sA[2][128][40];
    __shared__ __align__(16) __half sB[64][40];

    const int tid = threadIdx.x, lane = tid & 31, wid = tid >> 5;
    const int warpM = wid & 3, warpN = wid >> 2;
    const int mBase = blockIdx.y * 128, nBase = blockIdx.x * 64;

    float acc[2][4][4];
#pragma unroll
    for (int i = 0; i < 2; i++)
#pragma unroll
        for (int j = 0; j < 4; j++)
#pragma unroll
            for (int t = 0; t < 4; t++) acc[i][j][t] = 0.f;

    const int ar = tid >> 2, ag = (tid & 3) * 8;

    uint32_t aAdH[2], aAdL[2], bAd[2];
#pragma unroll
    for (int t = 0; t < 2; t++) {
        int rA = warpM * 32 + t * 16 + (lane & 15), cA = (lane >> 4) * 8;
        aAdH[t] = smem_u32(&sA[0][rA][cA]);
        aAdL[t] = smem_u32(&sA[1][rA][cA]);
        int rB = warpN * 32 + t * 16 + ((lane >> 4) << 3) + (lane & 7);
        int cB = ((lane >> 3) & 1) * 8;
        bAd[t] = smem_u32(&sB[rB][cB]);
    }

    uint4 pAh[2], pAl[2], pB;
    const int NC = K / 32;
    {
        pAh[0] = *reinterpret_cast<const uint4*>(ge.ahi + (size_t)(mBase + ar) * K + ag);
        pAl[0] = *reinterpret_cast<const uint4*>(ge.alo + (size_t)(mBase + ar) * K + ag);
        pAh[1] = *reinterpret_cast<const uint4*>(ge.ahi + (size_t)(mBase + ar + 64) * K + ag);
        pAl[1] = *reinterpret_cast<const uint4*>(ge.alo + (size_t)(mBase + ar + 64) * K + ag);
        pB     = *reinterpret_cast<const uint4*>(ge.b   + (size_t)(nBase + ar) * K + ag);
    }

    for (int c = 0; c < NC; c++) {
        if (c) __syncthreads();
        *reinterpret_cast<uint4*>(&sA[0][ar][ag])      = pAh[0];
        *reinterpret_cast<uint4*>(&sA[1][ar][ag])      = pAl[0];
        *reinterpret_cast<uint4*>(&sA[0][ar + 64][ag]) = pAh[1];
        *reinterpret_cast<uint4*>(&sA[1][ar + 64][ag]) = pAl[1];
        *reinterpret_cast<uint4*>(&sB[ar][ag])         = pB;
        __syncthreads();
        if (c + 1 < NC) {
            const int kof = (c + 1) * 32 + ag;
            pAh[0] = *reinterpret_cast<const uint4*>(ge.ahi + (size_t)(mBase + ar) * K + kof);
            pAl[0] = *reinterpret_cast<const uint4*>(ge.alo + (size_t)(mBase + ar) * K + kof);
            pAh[1] = *reinterpret_cast<const uint4*>(ge.ahi + (size_t)(mBase + ar + 64) * K + kof);
            pAl[1] = *reinterpret_cast<const uint4*>(ge.alo + (size_t)(mBase + ar + 64) * K + kof);
            pB     = *reinterpret_cast<const uint4*>(ge.b   + (size_t)(nBase + ar) * K + kof);
        }
#pragma unroll
        for (int ks = 0; ks < 2; ks++) {
            const uint32_t off = ks * 32;
            uint32_t ah[2][4], al[2][4], bh[2][4];
            ldsm4(ah[0], aAdH[0] + off);  ldsm4(ah[1], aAdH[1] + off);
            ldsm4(al[0], aAdL[0] + off);  ldsm4(al[1], aAdL[1] + off);
            ldsm4(bh[0], bAd[0] + off);   ldsm4(bh[1], bAd[1] + off);
#pragma unroll
            for (int i = 0; i < 2; i++)
#pragma unroll
                for (int j = 0; j < 4; j++) {
                    const uint32_t* bhp = &bh[j >> 1][(j & 1) * 2];
                    mma16816(acc[i][j], ah[i], bhp);
                    mma16816(acc[i][j], al[i], bhp);
                }
        }
    }

    const int mrow = lane >> 2, ncol = (lane & 3) * 2;
#pragma unroll
    for (int i = 0; i < 2; i++)
#pragma unroll
        for (int j = 0; j < 4; j++) {
            int m0 = mBase + warpM * 32 + i * 16 + mrow;
            int n  = nBase + warpN * 32 + j * 8 + ncol;
#pragma unroll
            for (int half = 0; half < 2; half++) {
                int m = m0 + half * 8;
                float c0 = acc[i][j][half * 2], c1 = acc[i][j][half * 2 + 1];
                if (ge.mode >= 3) {
                    int srow = m & (SLEN - 1);
                    int t = (n & 63) >> 1;
                    float cz = args.fc[srow * 32 + t], sz = args.fs[srow * 32 + t];
                    float xr = c0, xi = c1;
                    c0 = xr * cz - xi * sz;
                    c1 = xr * sz + xi * cz;
                }
                if (ge.mode == 4) { c0 *= 0.125f; c1 *= 0.125f; }
                if (ge.mode == 0) {
                    *reinterpret_cast<float2*>(&ge.y[(size_t)m * ge.ldy + ge.col_off + n]) =
                        make_float2(c0, c1);
                } else {
                    uint32_t hp = hcvt2hi(c0, c1);
                    *reinterpret_cast<uint32_t*>(&ge.yhi[(size_t)m * PROJ + n]) = hp;
                    if (ge.mode == 2 || ge.mode == 4) {
                        uint32_t lp = hcvt2lo(c0, c1, hp);
                        *reinterpret_cast<uint32_t*>(&ge.ylo[(size_t)m * PROJ + n]) = lp;
                    }
                }
            }
        }
}

// ------------- rel transposed: g_rel[b][i][j][r] = 0.125 * qr[b,i,r,:]·kr[b,j,r,:]
// CTA = 64x64 (i,j) tile, loops r=0..7 internally, stages output tile in smem,
// then writes fully-coalesced uint4 rows. Lower-triangular tiles only.
// Dynamic smem: sAhi[64*72] | sAlo[64*72] | sB[64*72] | stg[64*520] halves.
__global__ __launch_bounds__(256) void rel_mma_t()
{
    const int jt = blockIdx.x, it = blockIdx.y, b = blockIdx.z;
    if (jt > it) return;
    extern __shared__ __half sm[];
    __half* sAhi = sm;
    __half* sAlo = sm + 4608;
    __half* sB   = sm + 9216;
    __half* stg  = sm + 13824;   // [64][520]

    const int tid = threadIdx.x, lane = tid & 31, wid = tid >> 5;
    const int warpM = wid & 3, warpN = wid >> 2;
    const int iBase = it * 64, jBase = jt * 64;

    const __half* Ah = g_qrhi + ((size_t)(b * SLEN + iBase)) * PROJ;
    const __half* Al = g_qrlo + ((size_t)(b * SLEN + iBase)) * PROJ;
    const __half* Bh = g_kr   + ((size_t)(b * SLEN + jBase)) * PROJ;

    uint32_t aH, aL, bAd[2];
    {
        int rA = warpM * 16 + (lane & 15), cA = (lane >> 4) * 8;
        aH = smem_u32(&sAhi[rA * 72 + cA]);
        aL = smem_u32(&sAlo[rA * 72 + cA]);
#pragma unroll
        for (int t = 0; t < 2; t++) {
            int rB = warpN * 32 + t * 16 + ((lane >> 4) << 3) + (lane & 7);
            int cB = ((lane >> 3) & 1) * 8;
            bAd[t] = smem_u32(&sB[rB * 72 + cB]);
        }
    }

    const int lr = tid >> 2;          // row 0..63
    const int lc = (tid & 3) * 16;    // halves; two uint4 at lc, lc+8
    const int mrow = lane >> 2, ncol = (lane & 3) * 2;

    for (int r = 0; r < 8; r++) {
        if (r) __syncthreads();
        const size_t co = (size_t)r * 64 + lc;
        *reinterpret_cast<uint4*>(&sAhi[lr * 72 + lc])     = *reinterpret_cast<const uint4*>(Ah + (size_t)lr * PROJ + co);
        *reinterpret_cast<uint4*>(&sAhi[lr * 72 + lc + 8]) = *reinterpret_cast<const uint4*>(Ah + (size_t)lr * PROJ + co + 8);
        *reinterpret_cast<uint4*>(&sAlo[lr * 72 + lc])     = *reinterpret_cast<const uint4*>(Al + (size_t)lr * PROJ + co);
        *reinterpret_cast<uint4*>(&sAlo[lr * 72 + lc + 8]) = *reinterpret_cast<const uint4*>(Al + (size_t)lr * PROJ + co + 8);
        *reinterpret_cast<uint4*>(&sB[lr * 72 + lc])       = *reinterpret_cast<const uint4*>(Bh + (size_t)lr * PROJ + co);
        *reinterpret_cast<uint4*>(&sB[lr * 72 + lc + 8])   = *reinterpret_cast<const uint4*>(Bh + (size_t)lr * PROJ + co + 8);
        __syncthreads();

        float acc[4][4];
#pragma unroll
        for (int j = 0; j < 4; j++)
#pragma unroll
            for (int t = 0; t < 4; t++) acc[j][t] = 0.f;

#pragma unroll
        for (int ks = 0; ks < 4; ks++) {
            const uint32_t off = ks * 32;
            uint32_t a_hi[4], a_lo[4], bb[2][4];
            ldsm4(a_hi, aH + off);
            ldsm4(a_lo, aL + off);
            ldsm4(bb[0], bAd[0] + off);
            ldsm4(bb[1], bAd[1] + off);
#pragma unroll
            for (int j = 0; j < 4; j++) {
                const uint32_t* bp = &bb[j >> 1][(j & 1) * 2];
                mma16816(acc[j], a_hi, bp);
                mma16816(acc[j], a_lo, bp);
            }
        }

        // stash into transposed staging
#pragma unroll
        for (int j = 0; j < 4; j++) {
            int m0 = warpM * 16 + mrow;
            int n  = warpN * 32 + j * 8 + ncol;
            stg[m0 * 520 + n * 8 + r]           = __float2half(acc[j][0] * 0.125f);
            stg[m0 * 520 + (n + 1) * 8 + r]     = __float2half(acc[j][1] * 0.125f);
            stg[(m0 + 8) * 520 + n * 8 + r]     = __float2half(acc[j][2] * 0.125f);
            stg[(m0 + 8) * 520 + (n + 1) * 8 + r] = __float2half(acc[j][3] * 0.125f);
        }
    }
    __syncthreads();

    // coalesced write-out: 64 rows x 64 uint4 (each uint4 = 8 r for one (i,j))
    uint4* dst = reinterpret_cast<uint4*>(g_rel);
#pragma unroll
    for (int u = 0; u < 16; u++) {
        int id = tid + u * 256;
        int row = id >> 6, cu = id & 63;
        uint4 v = *reinterpret_cast<uint4*>(&stg[row * 520 + cu * 8]);
        dst[((size_t)(b * SLEN + iBase + row)) * SLEN + jBase + cu] = v;
    }
}

// ------------- HMMA flash attention, SA+RA merged (blockIdx.z selects) -----------
__global__ __launch_bounds__(256) void flash_mma(
    const __half* __restrict__ qh_, const __half* __restrict__ ql_,
    const __half* __restrict__ k_,  const __half* __restrict__ v_,
    const __half* __restrict__ qah_, const __half* __restrict__ qal_,
    const __half* __restrict__ ka_, const __half* __restrict__ sv_,
    const float* __restrict__ WR,
    __half* __restrict__ chi_, __half* __restrict__ clo_)
{
    __shared__ __align__(16) __half sKV[2][9216];
    __shared__ float s_wrs[512];
    __shared__ float s_mSt[128];

    const bool RA = (blockIdx.z == 1);
    const __half* Qh_ = RA ? qah_ : qh_;
    const __half* Ql_ = RA ? qal_ : ql_;
    const __half* Kh_ = RA ? ka_ : k_;
    const __half* Vh_ = RA ? sv_ : v_;
    __half* Ohi = chi_ + (RA ? (size_t)MTOT * PROJ : 0);
    __half* Olo = clo_ + (RA ? (size_t)MTOT * PROJ : 0);

    const int bh = blockIdx.y, b = bh >> 3, h = bh & 7, it = blockIdx.x;
    const int tid = threadIdx.x, lane = tid & 31, wid = tid >> 5;
    const int grp = wid >> 3 ? 0 : 0; // placeholder (unused)
    const int g2 = wid >> 2, wq = wid & 3;
    __half* sK = sKV[g2];
    __half* sV = sK + 4608;
    float* mO  = (float*)sKV[1];
    float* mAr = (float*)sKV[0];

    // stage Q (hi @0, lo @4608 halves)
    {
        __half* sQ = sKV[0];
#pragma unroll
        for (int u = 0; u < 2; u++) {
            int e = tid + u * 256, row = e >> 3, gg = e & 7;
            size_t gq = ((size_t)(b * SLEN + it * 64 + row)) * PROJ + h * 64 + gg * 8;
            *reinterpret_cast<uint4*>(&sQ[row * 72 + gg * 8])        = *reinterpret_cast<const uint4*>(&Qh_[gq]);
            *reinterpret_cast<uint4*>(&sQ[4608 + row * 72 + gg * 8]) = *reinterpret_cast<const uint4*>(&Ql_[gq]);
        }
    }
    if (RA) { s_wrs[tid] = WR[h * 512 + tid]; s_wrs[256 + tid] = WR[h * 512 + 256 + tid]; }
    __syncthreads();
    uint32_t qh[4][4], ql[4][4];
    {
        uint32_t ah = smem_u32(&sKV[0][(wq * 16 + (lane & 15)) * 72 + (lane >> 4) * 8]);
#pragma unroll
        for (int ks = 0; ks < 4; ks++) { ldsm4(qh[ks], ah + ks * 32); ldsm4(ql[ks], ah + 9216 + ks * 32); }
    }
    __syncthreads();

    uint32_t kAd[4], vAd[4];
#pragma unroll
    for (int t = 0; t < 4; t++) {
        int rK = t * 16 + ((lane >> 4) << 3) + (lane & 7), cK = ((lane >> 3) & 1) * 8;
        kAd[t] = smem_u32(&sK[rK * 72 + cK]);
        int rV = t * 16 + ((lane >> 3) & 1) * 8 + (lane & 7), cV = (lane >> 4) * 8;
        vAd[t] = smem_u32(&sV[rV * 72 + cV]);
    }

    float o[8][4];
#pragma unroll
    for (int nb = 0; nb < 8; nb++)
#pragma unroll
        for (int t = 0; t < 4; t++) o[nb][t] = 0.f;
    float arr[2][8];
#pragma unroll
    for (int hh = 0; hh < 2; hh++)
#pragma unroll
        for (int r = 0; r < 8; r++) arr[hh][r] = 0.f;
    float m0 = -1e30f, m1 = -1e30f, l0 = 0.f, l1 = 0.f;
    const int row0 = lane >> 2, c0 = (lane & 3) * 2;
    const int lt = tid & 127;
    const uint4* rbase = reinterpret_cast<const uint4*>(g_rel);

    for (int jt = g2; jt <= it; jt += 2) {
        BARG(g2 + 1);
#pragma unroll
        for (int u = 0; u < 4; u++) {
            int e = lt + u * 128, row = e >> 3, gg = e & 7;
            size_t gi = ((size_t)(b * SLEN + jt * 64 + row)) * PROJ + h * 64 + gg * 8;
            *reinterpret_cast<uint4*>(&sK[row * 72 + gg * 8]) = *reinterpret_cast<const uint4*>(&Kh_[gi]);
            *reinterpret_cast<uint4*>(&sV[row * 72 + gg * 8]) = *reinterpret_cast<const uint4*>(&Vh_[gi]);
        }
        BARG(g2 + 1);

        float s[8][4];
#pragma unroll
        for (int nb = 0; nb < 8; nb++)
#pragma unroll
            for (int t = 0; t < 4; t++) s[nb][t] = 0.f;
#pragma unroll
        for (int ks = 0; ks < 4; ks++)
#pragma unroll
            for (int t = 0; t < 4; t++) {
                uint32_t kh2[4];
                ldsm4(kh2, kAd[t] + ks * 32);
#pragma unroll
                for (int half = 0; half < 2; half++) {
                    int nb = t * 2 + half;
                    mma16816(s[nb], qh[ks], &kh2[half * 2]);
                    mma16816(s[nb], ql[ks], &kh2[half * 2]);
                }
            }
        if (jt == it) {
            int gi0 = wq * 16 + row0;
#pragma unroll
            for (int nb = 0; nb < 8; nb++) {
                int gj = nb * 8 + c0;
                if (gj     > gi0)     s[nb][0] = -1e30f;
                if (gj + 1 > gi0)     s[nb][1] = -1e30f;
                if (gj     > gi0 + 8) s[nb][2] = -1e30f;
                if (gj + 1 > gi0 + 8) s[nb][3] = -1e30f;
            }
        }
        float rm0 = -1e30f, rm1 = -1e30f;
#pragma unroll
        for (int nb = 0; nb < 8; nb++) {
            rm0 = fmaxf(rm0, fmaxf(s[nb][0], s[nb][1]));
            rm1 = fmaxf(rm1, fmaxf(s[nb][2], s[nb][3]));
        }
        rm0 = fmaxf(rm0, __shfl_xor_sync(0xffffffffu, rm0, 1));
        rm0 = fmaxf(rm0, __shfl_xor_sync(0xffffffffu, rm0, 2));
        rm1 = fmaxf(rm1, __shfl_xor_sync(0xffffffffu, rm1, 1));
        rm1 = fmaxf(rm1, __shfl_xor_sync(0xffffffffu, rm1, 2));
        float nm0 = fmaxf(m0, rm0), nm1 = fmaxf(m1, rm1);
        float sc0 = __expf(m0 - nm0), sc1 = __expf(m1 - nm1);
        m0 = nm0; m1 = nm1;
        float rs0 = 0.f, rs1 = 0.f;
#pragma unroll
        for (int nb = 0; nb < 8; nb++) {
            s[nb][0] = __expf(s[nb][0] - nm0);
            s[nb][1] = __expf(s[nb][1] - nm0);
            s[nb][2] = __expf(s[nb][2] - nm1);
            s[nb][3] = __expf(s[nb][3] - nm1);
            rs0 += s[nb][0] + s[nb][1];
            rs1 += s[nb][2] + s[nb][3];
        }
        rs0 += __shfl_xor_sync(0xffffffffu, rs0, 1);
        rs0 += __shfl_xor_sync(0xffffffffu, rs0, 2);
        rs1 += __shfl_xor_sync(0xffffffffu, rs1, 1);
        rs1 += __shfl_xor_sync(0xffffffffu, rs1, 2);
        l0 = l0 * sc0 + rs0;
        l1 = l1 * sc1 + rs1;
#pragma unroll
        for (int nb = 0; nb < 8; nb++) {
            o[nb][0] *= sc0; o[nb][1] *= sc0; o[nb][2] *= sc1; o[nb][3] *= sc1;
        }
        if (RA) {
#pragma unroll
            for (int r = 0; r < 8; r++) { arr[0][r] *= sc0; arr[1][r] *= sc1; }
            int gi0 = it * 64 + wq * 16 + row0;
            size_t p0 = ((size_t)(b * SLEN) + gi0) * SLEN + jt * 64 + c0;
            const uint4* rp0 = rbase + p0;
            const uint4* rp1 = rbase + p0 + (size_t)8 * SLEN;
#pragma unroll
            for (int nb = 0; nb < 8; nb++) {
                uint4 va = rp0[nb * 8];
                uint4 vb = rp0[nb * 8 + 1];
                uint4 vc = rp1[nb * 8];
                uint4 vd = rp1[nb * 8 + 1];
                const __half2* ha = reinterpret_cast<const __half2*>(&va);
                const __half2* hb = reinterpret_cast<const __half2*>(&vb);
                const __half2* hc = reinterpret_cast<const __half2*>(&vc);
                const __half2* hd = reinterpret_cast<const __half2*>(&vd);
#pragma unroll
                for (int q = 0; q < 4; q++) {
                    float2 fa = __half22float2(ha[q]);
                    float2 fb = __half22float2(hb[q]);
                    float2 fc = __half22float2(hc[q]);
                    float2 fd = __half22float2(hd[q]);
                    arr[0][2*q]   = fmaf(s[nb][0], fa.x, fmaf(s[nb][1], fb.x, arr[0][2*q]));
                    arr[0][2*q+1] = fmaf(s[nb][0], fa.y, fmaf(s[nb][1], fb.y, arr[0][2*q+1]));
                    arr[1][2*q]   = fmaf(s[nb][2], fc.x, fmaf(s[nb][3], fd.x, arr[1][2*q]));
                    arr[1][2*q+1] = fmaf(s[nb][2], fc.y, fmaf(s[nb][3], fd.y, arr[1][2*q+1]));
                }
            }
        }
#pragma unroll
        for (int jk = 0; jk < 4; jk++) {
            uint32_t ph[4], pl[4];
            ph[0] = hcvt2hi(s[2*jk][0],   s[2*jk][1]);
            ph[1] = hcvt2hi(s[2*jk][2],   s[2*jk][3]);
            ph[2] = hcvt2hi(s[2*jk+1][0], s[2*jk+1][1]);
            ph[3] = hcvt2hi(s[2*jk+1][2], s[2*jk+1][3]);
            pl[0] = hcvt2lo(s[2*jk][0],   s[2*jk][1],   ph[0]);
            pl[1] = hcvt2lo(s[2*jk][2],   s[2*jk][3],   ph[1]);
            pl[2] = hcvt2lo(s[2*jk+1][0], s[2*jk+1][1], ph[2]);
            pl[3] = hcvt2lo(s[2*jk+1][2], s[2*jk+1][3], ph[3]);
#pragma unroll
            for (int db = 0; db < 4; db++) {
                uint32_t vh2[4];
                ldsm4t(vh2, vAd[jk] + db * 32);
#pragma unroll
                for (int half = 0; half < 2; half++) {
                    int nb = db * 2 + half;
                    mma16816(o[nb], ph, &vh2[half * 2]);
                    mma16816(o[nb], pl, &vh2[half * 2]);
                }
            }
        }
    }

    __syncthreads();
    if (g2 == 1) {
#pragma unroll
        for (int nb = 0; nb < 8; nb++) {
            *reinterpret_cast<float2*>(&mO[(wq * 16 + row0) * 64 + nb * 8 + c0])     = make_float2(o[nb][0], o[nb][1]);
            *reinterpret_cast<float2*>(&mO[(wq * 16 + row0 + 8) * 64 + nb * 8 + c0]) = make_float2(o[nb][2], o[nb][3]);
        }
        if ((lane & 3) == 0) {
            s_mSt[(wq * 16 + row0) * 2]         = m0;
            s_mSt[(wq * 16 + row0) * 2 + 1]     = l0;
            s_mSt[(wq * 16 + row0 + 8) * 2]     = m1;
            s_mSt[(wq * 16 + row0 + 8) * 2 + 1] = l1;
        }
        if (RA) {
#pragma unroll
            for (int hh = 0; hh < 2; hh++)
#pragma unroll
                for (int r = 0; r < 8; r++) {
                    arr[hh][r] += __shfl_xor_sync(0xffffffffu, arr[hh][r], 1);
                    arr[hh][r] += __shfl_xor_sync(0xffffffffu, arr[hh][r], 2);
                }
            if ((lane & 3) == 0)
#pragma unroll
                for (int r = 0; r < 8; r++) {
                    mAr[(wq * 16 + row0) * 8 + r]     = arr[0][r];
                    mAr[(wq * 16 + row0 + 8) * 8 + r] = arr[1][r];
                }
        }
    }
    __syncthreads();
    if (g2 == 0) {
        if (RA) {
#pragma unroll
            for (int hh = 0; hh < 2; hh++)
#pragma unroll
                for (int r = 0; r < 8; r++) {
                    arr[hh][r] += __shfl_xor_sync(0xffffffffu, arr[hh][r], 1);
                    arr[hh][r] += __shfl_xor_sync(0xffffffffu, arr[hh][r], 2);
                }
        }
#pragma unroll
        for (int half = 0; half < 2; half++) {
            int rr = wq * 16 + row0 + half * 8;
            float mo = half ? m1 : m0, lo_ = half ? l1 : l0;
            float m2 = s_mSt[rr * 2], l2 = s_mSt[rr * 2 + 1];
            float mf = fmaxf(mo, m2);
            float e1 = __expf(mo - mf), e2 = __expf(m2 - mf);
            float inv = 1.f / (lo_ * e1 + l2 * e2);
            float arf[8];
            if (RA)
#pragma unroll
                for (int r = 0; r < 8; r++)
                    arf[r] = (arr[half][r] * e1 + mAr[rr * 8 + r] * e2) * inv;
#pragma unroll
            for (int nb = 0; nb < 8; nb++) {
                float2 o2 = *reinterpret_cast<float2*>(&mO[rr * 64 + nb * 8 + c0]);
                float v0 = (o[nb][half * 2] * e1     + o2.x * e2) * inv;
                float v1 = (o[nb][half * 2 + 1] * e1 + o2.y * e2) * inv;
                if (RA) {
                    int d0 = nb * 8 + c0;
                    float r0s = 0.f, r1s = 0.f;
#pragma unroll
                    for (int r = 0; r < 8; r++) {
                        r0s = fmaf(arf[r], s_wrs[d0 * 8 + r], r0s);
                        r1s = fmaf(arf[r], s_wrs[(d0 + 1) * 8 + r], r1s);
                    }
                    v0 += r0s; v1 += r1s;
                }
                size_t oo = ((size_t)(b * SLEN + it * 64 + rr)) * PROJ + h * 64 + nb * 8 + c0;
                uint32_t hp = hcvt2hi(v0, v1), lp = hcvt2lo(v0, v1, hp);
                *reinterpret_cast<uint32_t*>(&Ohi[oo]) = hp;
                *reinterpret_cast<uint32_t*>(&Olo[oo]) = lp;
            }
        }
    }
}

// ---------------- host launcher --------------------------------------------------
extern "C" void kernel_launch(void* const* d_in, const int* in_sizes, int n_in,
                              void* d_out, int out_size)
{
    const float* x       = (const float*)d_in[0];
    const float* symbols = (const float*)d_in[1];
    const float* fc      = (const float*)d_in[2];
    const float* fs      = (const float*)d_in[3];
    const float* wsrc[10] = {
        (const float*)d_in[4],  (const float*)d_in[5],  (const float*)d_in[6],
        (const float*)d_in[8],  (const float*)d_in[9],  (const float*)d_in[10],
        (const float*)d_in[11], (const float*)d_in[13], (const float*)d_in[7],
        (const float*)d_in[14],
    };
    const float* wr = (const float*)d_in[12];
    float* out = (float*)d_out;

    __half *xhi, *xlo, *shi, *slo, *w, *chi, *clo;
    __half *qhi, *qlo, *qahi, *qalo, *qrhi, *qrlo;
    __half *k, *ka, *v, *sv, *kr;
    cudaGetSymbolAddress((void**)&xhi, g_xhi);   cudaGetSymbolAddress((void**)&xlo, g_xlo);
    cudaGetSymbolAddress((void**)&shi, g_shi);   cudaGetSymbolAddress((void**)&slo, g_slo);
    cudaGetSymbolAddress((void**)&w,   g_w);
    cudaGetSymbolAddress((void**)&chi, g_chi);   cudaGetSymbolAddress((void**)&clo, g_clo);
    cudaGetSymbolAddress((void**)&qhi, g_qhi);   cudaGetSymbolAddress((void**)&qlo, g_qlo);
    cudaGetSymbolAddress((void**)&qahi, g_qahi); cudaGetSymbolAddress((void**)&qalo, g_qalo);
    cudaGetSymbolAddress((void**)&qrhi, g_qrhi); cudaGetSymbolAddress((void**)&qrlo, g_qrlo);
    cudaGetSymbolAddress((void**)&k,  g_k);
    cudaGetSymbolAddress((void**)&ka, g_ka);
    cudaGetSymbolAddress((void**)&v,  g_v);
    cudaGetSymbolAddress((void**)&sv, g_sv);
    cudaGetSymbolAddress((void**)&kr, g_kr);

    const int wsz[10] = { PROJ*DMODEL, PROJ*DMODEL, PROJ*DMODEL, PROJ*DMODEL, PROJ*DMODEL,
                          PROJ*DMODEL, PROJ*DMODEL, PROJ*DMODEL, PROJ*PROJ, PROJ*PROJ };
    size_t woff[10];
    { size_t o = 0; for (int i = 0; i < 10; i++) { woff[i] = o; o += wsz[i]; } }

    // split launch A: x + symbols (hi/lo)
    {
        SBatch sb;
        sb.e[0] = { x,       xhi, xlo, MTOT * DMODEL };
        sb.e[1] = { symbols, shi, slo, MTOT * DMODEL };
        for (int i = 2; i < 10; i++) sb.e[i] = sb.e[0];
        dim3 grid((MTOT * DMODEL + 255) / 256, 2);
        split_multi<<<grid, 256>>>(sb);
    }
    // split launch B: 10 weights, single fp16
    {
        SBatch sb;
        for (int i = 0; i < 10; i++)
            sb.e[i] = { wsrc[i], w + woff[i], nullptr, wsz[i] };
        dim3 grid((PROJ * DMODEL + 255) / 256, 10);
        split_multi<<<grid, 256>>>(sb);
    }

    // projections: q 4, k 3, v 1, qa 4, ka 3, qr 2, kr 1, sv 1
    {
        GBatch gb;
        gb.fc = fc; gb.fs = fs; gb.K = DMODEL;
        __half* yh[8] = { qhi, k, v, qahi, ka, qrhi, kr, sv };
        __half* yl[8] = { qlo, nullptr, nullptr, qalo, nullptr, qrlo, nullptr, nullptr };
        int modes[8] = { 4, 3, 1, 4, 3, 2, 1, 1 };
        for (int i = 0; i < 8; i++) {
            gb.e[i].ahi = (i == 7) ? shi : xhi;
            gb.e[i].alo = (i == 7) ? slo : xlo;
            gb.e[i].b = w + woff[i];
            gb.e[i].y = nullptr; gb.e[i].ldy = PROJ; gb.e[i].col_off = 0;
            gb.e[i].mode = modes[i]; gb.e[i].yhi = yh[i]; gb.e[i].ylo = yl[i];
        }
        dim3 grid(PROJ / 64, MTOT / 128, 8);
        gemm_mma<<<grid, 256>>>(gb);
    }

    // rel transposed
    {
        const int RSM = 94208;   // (3*4608 + 64*520) halves * 2B
        cudaFuncSetAttribute(rel_mma_t, cudaFuncAttributeMaxDynamicSharedMemorySize, RSM);
        dim3 grid(SLEN / 64, SLEN / 64, NBATCH);
        rel_mma_t<<<grid, 256, RSM>>>();
    }

    // flash attentions merged (z=0 SA, z=1 RA)
    {
        dim3 gfl(SLEN / 64, NBATCH * 8, 2);
        flash_mma<<<gfl, 256>>>(qhi, qlo, k, v, qahi, qalo, ka, sv, wr, chi, clo);
    }

    // output projections -> fp32 halves of out
    {
        GBatch gb;
        gb.fc = fc; gb.fs = fs; gb.K = PROJ;
        gb.e[0].ahi = chi; gb.e[0].alo = clo;
        gb.e[0].b = w + woff[8];
        gb.e[0].y = out; gb.e[0].ldy = DMODEL; gb.e[0].col_off = 0; gb.e[0].mode = 0;
        gb.e[0].yhi = nullptr; gb.e[0].ylo = nullptr;
        gb.e[1] = gb.e[0];
        gb.e[1].ahi = chi + (size_t)MTOT * PROJ; gb.e[1].alo = clo + (size_t)MTOT * PROJ;
        gb.e[1].b = w + woff[9];
        gb.e[1].col_off = 512;
        for (int i = 2; i < 8; i++) gb.e[i] = gb.e[0];
        dim3 grid(PROJ / 64, MTOT / 128, 2);
        gemm_mma<<<grid, 256>>>(gb);
    }
}

// round 17
// speedup vs baseline: 3.5334x; 1.0651x over previous
#include <cuda_runtime.h>
#include <cuda_fp16.h>
#include <cstdint>

#define SLEN   2048
#define NBATCH 2
#define DMODEL 1024
#define PROJ   512
#define MTOT   (NBATCH*SLEN)

// rel stored TRANSPOSED: [b][i][j][r], 8 fp16 r-values contiguous per (i,j)
__device__ __half g_rel[(size_t)NBATCH*SLEN*SLEN*8];

__device__ __half g_xhi[MTOT*DMODEL], g_xlo[MTOT*DMODEL];
__device__ __half g_shi[MTOT*DMODEL], g_slo[MTOT*DMODEL];
#define WTOT (8*PROJ*DMODEL + 2*PROJ*PROJ)
__device__ __half g_w[WTOT];
__device__ __half g_chi[2*MTOT*PROJ], g_clo[2*MTOT*PROJ];
__device__ __half g_qhi [MTOT*PROJ], g_qlo [MTOT*PROJ];
__device__ __half g_qahi[MTOT*PROJ], g_qalo[MTOT*PROJ];
__device__ __half g_qrhi[MTOT*PROJ], g_qrlo[MTOT*PROJ];
__device__ __half g_k [MTOT*PROJ];
__device__ __half g_ka[MTOT*PROJ];
__device__ __half g_v [MTOT*PROJ];
__device__ __half g_sv[MTOT*PROJ];
__device__ __half g_kr[MTOT*PROJ];

__device__ __forceinline__ uint32_t smem_u32(const void* p) {
    uint32_t a;
    asm("{ .reg .u64 t; cvta.to.shared.u64 t, %1; cvt.u32.u64 %0, t; }" : "=r"(a) : "l"(p));
    return a;
}
__device__ __forceinline__ void ldsm4(uint32_t* r, uint32_t a) {
    asm volatile("ldmatrix.sync.aligned.m8n8.x4.shared.b16 {%0,%1,%2,%3}, [%4];"
        : "=r"(r[0]), "=r"(r[1]), "=r"(r[2]), "=r"(r[3]) : "r"(a));
}
__device__ __forceinline__ void ldsm4t(uint32_t* r, uint32_t a) {
    asm volatile("ldmatrix.sync.aligned.m8n8.x4.trans.shared.b16 {%0,%1,%2,%3}, [%4];"
        : "=r"(r[0]), "=r"(r[1]), "=r"(r[2]), "=r"(r[3]) : "r"(a));
}
__device__ __forceinline__ void mma16816(float* c, const uint32_t* a, const uint32_t* b) {
    asm volatile("mma.sync.aligned.m16n8k16.row.col.f32.f16.f16.f32 "
        "{%0,%1,%2,%3}, {%4,%5,%6,%7}, {%8,%9}, {%0,%1,%2,%3};"
        : "+f"(c[0]), "+f"(c[1]), "+f"(c[2]), "+f"(c[3])
        : "r"(a[0]), "r"(a[1]), "r"(a[2]), "r"(a[3]), "r"(b[0]), "r"(b[1]));
}
__device__ __forceinline__ uint32_t hcvt2hi(float a, float b) {
    __half2 h = __floats2half2_rn(a, b);
    return *reinterpret_cast<uint32_t*>(&h);
}
__device__ __forceinline__ uint32_t hcvt2lo(float a, float b, uint32_t hp) {
    __half2 h = *reinterpret_cast<__half2*>(&hp);
    return hcvt2hi(a - __half2float(h.x), b - __half2float(h.y));
}
#define BARG(id) asm volatile("bar.sync %0, 128;" :: "r"(id))

// ------------- batched fp32 -> fp16 convert / split ------------------------------
struct SEntry { const float* s; __half *hi, *lo; int n; };
struct SBatch { SEntry e[10]; };
__global__ __launch_bounds__(256) void split_multi(SBatch sb)
{
    SEntry en = sb.e[blockIdx.y];
    int i = blockIdx.x * 256 + threadIdx.x;
    if (i < en.n) {
        float v = en.s[i];
        __half h = __float2half(v);
        en.hi[i] = h;
        if (en.lo) en.lo[i] = __float2half(v - __half2float(h));
    }
}

// ------------- HMMA batched GEMM, CTA tile 128x128 (A split fp16, B single) ------
// 8 warps = 4 (M) x 2 (N); warp tile 32x64.
// modes: 0 fp32 out, 1 single fp16, 2 split fp16, 3 rope+single, 4 rope+scale+split
struct GEntry {
    const __half *ahi, *alo, *b;
    float* y;
    __half *yhi, *ylo;
    int ldy, col_off, mode;
};
struct GBatch { GEntry e[8]; const float *fc, *fs; int K; };

__global__ __launch_bounds__(256) void gemm_mma(GBatch args)
{
    const GEntry ge = args.e[blockIdx.z];
    const int K = args.K;
    __shared__ __align__(16) __half sA[2][128][40];
    __shared__ __align__(16) __half sB[128][40];

    const int tid = threadIdx.x, lane = tid & 31, wid = tid >> 5;
    const int warpM = wid & 3, warpN = wid >> 2;
    const int mBase = blockIdx.y * 128, nBase = blockIdx.x * 128;

    float acc[2][8][4];
#pragma unroll
    for (int i = 0; i < 2; i++)
#pragma unroll
        for (int j = 0; j < 8; j++)
#pragma unroll
            for (int t = 0; t < 4; t++) acc[i][j][t] = 0.f;

    const int ar = tid >> 2, ag = (tid & 3) * 8;

    uint32_t aAdH[2], aAdL[2], bAd[4];
#pragma unroll
    for (int t = 0; t < 2; t++) {
        int rA = warpM * 32 + t * 16 + (lane & 15), cA = (lane >> 4) * 8;
        aAdH[t] = smem_u32(&sA[0][rA][cA]);
        aAdL[t] = smem_u32(&sA[1][rA][cA]);
    }
#pragma unroll
    for (int t = 0; t < 4; t++) {
        int rB = warpN * 64 + t * 16 + ((lane >> 4) << 3) + (lane & 7);
        int cB = ((lane >> 3) & 1) * 8;
        bAd[t] = smem_u32(&sB[rB][cB]);
    }

    uint4 pAh[2], pAl[2], pB[2];
    const int NC = K / 32;
    {
        pAh[0] = *reinterpret_cast<const uint4*>(ge.ahi + (size_t)(mBase + ar) * K + ag);
        pAl[0] = *reinterpret_cast<const uint4*>(ge.alo + (size_t)(mBase + ar) * K + ag);
        pAh[1] = *reinterpret_cast<const uint4*>(ge.ahi + (size_t)(mBase + ar + 64) * K + ag);
        pAl[1] = *reinterpret_cast<const uint4*>(ge.alo + (size_t)(mBase + ar + 64) * K + ag);
        pB[0]  = *reinterpret_cast<const uint4*>(ge.b   + (size_t)(nBase + ar) * K + ag);
        pB[1]  = *reinterpret_cast<const uint4*>(ge.b   + (size_t)(nBase + ar + 64) * K + ag);
    }

    for (int c = 0; c < NC; c++) {
        if (c) __syncthreads();
        *reinterpret_cast<uint4*>(&sA[0][ar][ag])      = pAh[0];
        *reinterpret_cast<uint4*>(&sA[1][ar][ag])      = pAl[0];
        *reinterpret_cast<uint4*>(&sA[0][ar + 64][ag]) = pAh[1];
        *reinterpret_cast<uint4*>(&sA[1][ar + 64][ag]) = pAl[1];
        *reinterpret_cast<uint4*>(&sB[ar][ag])         = pB[0];
        *reinterpret_cast<uint4*>(&sB[ar + 64][ag])    = pB[1];
        __syncthreads();
        if (c + 1 < NC) {
            const int kof = (c + 1) * 32 + ag;
            pAh[0] = *reinterpret_cast<const uint4*>(ge.ahi + (size_t)(mBase + ar) * K + kof);
            pAl[0] = *reinterpret_cast<const uint4*>(ge.alo + (size_t)(mBase + ar) * K + kof);
            pAh[1] = *reinterpret_cast<const uint4*>(ge.ahi + (size_t)(mBase + ar + 64) * K + kof);
            pAl[1] = *reinterpret_cast<const uint4*>(ge.alo + (size_t)(mBase + ar + 64) * K + kof);
            pB[0]  = *reinterpret_cast<const uint4*>(ge.b   + (size_t)(nBase + ar) * K + kof);
            pB[1]  = *reinterpret_cast<const uint4*>(ge.b   + (size_t)(nBase + ar + 64) * K + kof);
        }
#pragma unroll
        for (int ks = 0; ks < 2; ks++) {
            const uint32_t off = ks * 32;
            uint32_t ah[2][4], al[2][4], bh[4][4];
            ldsm4(ah[0], aAdH[0] + off);  ldsm4(ah[1], aAdH[1] + off);
            ldsm4(al[0], aAdL[0] + off);  ldsm4(al[1], aAdL[1] + off);
            ldsm4(bh[0], bAd[0] + off);   ldsm4(bh[1], bAd[1] + off);
            ldsm4(bh[2], bAd[2] + off);   ldsm4(bh[3], bAd[3] + off);
#pragma unroll
            for (int i = 0; i < 2; i++)
#pragma unroll
                for (int j = 0; j < 8; j++) {
                    const uint32_t* bhp = &bh[j >> 1][(j & 1) * 2];
                    mma16816(acc[i][j], ah[i], bhp);
                    mma16816(acc[i][j], al[i], bhp);
                }
        }
    }

    const int mrow = lane >> 2, ncol = (lane & 3) * 2;
#pragma unroll
    for (int i = 0; i < 2; i++)
#pragma unroll
        for (int j = 0; j < 8; j++) {
            int m0 = mBase + warpM * 32 + i * 16 + mrow;
            int n  = nBase + warpN * 64 + j * 8 + ncol;
#pragma unroll
            for (int half = 0; half < 2; half++) {
                int m = m0 + half * 8;
                float c0 = acc[i][j][half * 2], c1 = acc[i][j][half * 2 + 1];
                if (ge.mode >= 3) {
                    int srow = m & (SLEN - 1);
                    int t = (n & 63) >> 1;
                    float cz = args.fc[srow * 32 + t], sz = args.fs[srow * 32 + t];
                    float xr = c0, xi = c1;
                    c0 = xr * cz - xi * sz;
                    c1 = xr * sz + xi * cz;
                }
                if (ge.mode == 4) { c0 *= 0.125f; c1 *= 0.125f; }
                if (ge.mode == 0) {
                    *reinterpret_cast<float2*>(&ge.y[(size_t)m * ge.ldy + ge.col_off + n]) =
                        make_float2(c0, c1);
                } else {
                    uint32_t hp = hcvt2hi(c0, c1);
                    *reinterpret_cast<uint32_t*>(&ge.yhi[(size_t)m * PROJ + n]) = hp;
                    if (ge.mode == 2 || ge.mode == 4) {
                        uint32_t lp = hcvt2lo(c0, c1, hp);
                        *reinterpret_cast<uint32_t*>(&ge.ylo[(size_t)m * PROJ + n]) = lp;
                    }
                }
            }
        }
}

// ------------- rel transposed: g_rel[b][i][j][r] = 0.125 * qr[b,i,r,:]·kr[b,j,r,:]
__global__ __launch_bounds__(256) void rel_mma_t()
{
    const int jt = blockIdx.x, it = blockIdx.y, b = blockIdx.z;
    if (jt > it) return;
    extern __shared__ __half sm[];
    __half* sAhi = sm;
    __half* sAlo = sm + 4608;
    __half* sB   = sm + 9216;
    __half* stg  = sm + 13824;   // [64][520]

    const int tid = threadIdx.x, lane = tid & 31, wid = tid >> 5;
    const int warpM = wid & 3, warpN = wid >> 2;
    const int iBase = it * 64, jBase = jt * 64;

    const __half* Ah = g_qrhi + ((size_t)(b * SLEN + iBase)) * PROJ;
    const __half* Al = g_qrlo + ((size_t)(b * SLEN + iBase)) * PROJ;
    const __half* Bh = g_kr   + ((size_t)(b * SLEN + jBase)) * PROJ;

    uint32_t aH, aL, bAd[2];
    {
        int rA = warpM * 16 + (lane & 15), cA = (lane >> 4) * 8;
        aH = smem_u32(&sAhi[rA * 72 + cA]);
        aL = smem_u32(&sAlo[rA * 72 + cA]);
#pragma unroll
        for (int t = 0; t < 2; t++) {
            int rB = warpN * 32 + t * 16 + ((lane >> 4) << 3) + (lane & 7);
            int cB = ((lane >> 3) & 1) * 8;
            bAd[t] = smem_u32(&sB[rB * 72 + cB]);
        }
    }

    const int lr = tid >> 2;
    const int lc = (tid & 3) * 16;
    const int mrow = lane >> 2, ncol = (lane & 3) * 2;

    for (int r = 0; r < 8; r++) {
        if (r) __syncthreads();
        const size_t co = (size_t)r * 64 + lc;
        *reinterpret_cast<uint4*>(&sAhi[lr * 72 + lc])     = *reinterpret_cast<const uint4*>(Ah + (size_t)lr * PROJ + co);
        *reinterpret_cast<uint4*>(&sAhi[lr * 72 + lc + 8]) = *reinterpret_cast<const uint4*>(Ah + (size_t)lr * PROJ + co + 8);
        *reinterpret_cast<uint4*>(&sAlo[lr * 72 + lc])     = *reinterpret_cast<const uint4*>(Al + (size_t)lr * PROJ + co);
        *reinterpret_cast<uint4*>(&sAlo[lr * 72 + lc + 8]) = *reinterpret_cast<const uint4*>(Al + (size_t)lr * PROJ + co + 8);
        *reinterpret_cast<uint4*>(&sB[lr * 72 + lc])       = *reinterpret_cast<const uint4*>(Bh + (size_t)lr * PROJ + co);
        *reinterpret_cast<uint4*>(&sB[lr * 72 + lc + 8])   = *reinterpret_cast<const uint4*>(Bh + (size_t)lr * PROJ + co + 8);
        __syncthreads();

        float acc[4][4];
#pragma unroll
        for (int j = 0; j < 4; j++)
#pragma unroll
            for (int t = 0; t < 4; t++) acc[j][t] = 0.f;

#pragma unroll
        for (int ks = 0; ks < 4; ks++) {
            const uint32_t off = ks * 32;
            uint32_t a_hi[4], a_lo[4], bb[2][4];
            ldsm4(a_hi, aH + off);
            ldsm4(a_lo, aL + off);
            ldsm4(bb[0], bAd[0] + off);
            ldsm4(bb[1], bAd[1] + off);
#pragma unroll
            for (int j = 0; j < 4; j++) {
                const uint32_t* bp = &bb[j >> 1][(j & 1) * 2];
                mma16816(acc[j], a_hi, bp);
                mma16816(acc[j], a_lo, bp);
            }
        }

#pragma unroll
        for (int j = 0; j < 4; j++) {
            int m0 = warpM * 16 + mrow;
            int n  = warpN * 32 + j * 8 + ncol;
            stg[m0 * 520 + n * 8 + r]             = __float2half(acc[j][0] * 0.125f);
            stg[m0 * 520 + (n + 1) * 8 + r]       = __float2half(acc[j][1] * 0.125f);
            stg[(m0 + 8) * 520 + n * 8 + r]       = __float2half(acc[j][2] * 0.125f);
            stg[(m0 + 8) * 520 + (n + 1) * 8 + r] = __float2half(acc[j][3] * 0.125f);
        }
    }
    __syncthreads();

    uint4* dst = reinterpret_cast<uint4*>(g_rel);
#pragma unroll
    for (int u = 0; u < 16; u++) {
        int id = tid + u * 256;
        int row = id >> 6, cu = id & 63;
        uint4 v = *reinterpret_cast<uint4*>(&stg[row * 520 + cu * 8]);
        dst[((size_t)(b * SLEN + iBase + row)) * SLEN + jBase + cu] = v;
    }
}

// ------------- HMMA flash attention, SA+RA merged (blockIdx.z selects) -----------
__global__ __launch_bounds__(256) void flash_mma(
    const __half* __restrict__ qh_, const __half* __restrict__ ql_,
    const __half* __restrict__ k_,  const __half* __restrict__ v_,
    const __half* __restrict__ qah_, const __half* __restrict__ qal_,
    const __half* __restrict__ ka_, const __half* __restrict__ sv_,
    const float* __restrict__ WR,
    __half* __restrict__ chi_, __half* __restrict__ clo_)
{
    __shared__ __align__(16) __half sKV[2][9216];
    __shared__ float s_wrs[512];
    __shared__ float s_mSt[128];

    const bool RA = (blockIdx.z == 1);
    const __half* Qh_ = RA ? qah_ : qh_;
    const __half* Ql_ = RA ? qal_ : ql_;
    const __half* Kh_ = RA ? ka_ : k_;
    const __half* Vh_ = RA ? sv_ : v_;
    __half* Ohi = chi_ + (RA ? (size_t)MTOT * PROJ : 0);
    __half* Olo = clo_ + (RA ? (size_t)MTOT * PROJ : 0);

    const int bh = blockIdx.y, b = bh >> 3, h = bh & 7, it = blockIdx.x;
    const int tid = threadIdx.x, lane = tid & 31, wid = tid >> 5;
    const int g2 = wid >> 2, wq = wid & 3;
    __half* sK = sKV[g2];
    __half* sV = sK + 4608;
    float* mO  = (float*)sKV[1];
    float* mAr = (float*)sKV[0];

    {
        __half* sQ = sKV[0];
#pragma unroll
        for (int u = 0; u < 2; u++) {
            int e = tid + u * 256, row = e >> 3, gg = e & 7;
            size_t gq = ((size_t)(b * SLEN + it * 64 + row)) * PROJ + h * 64 + gg * 8;
            *reinterpret_cast<uint4*>(&sQ[row * 72 + gg * 8])        = *reinterpret_cast<const uint4*>(&Qh_[gq]);
            *reinterpret_cast<uint4*>(&sQ[4608 + row * 72 + gg * 8]) = *reinterpret_cast<const uint4*>(&Ql_[gq]);
        }
    }
    if (RA) { s_wrs[tid] = WR[h * 512 + tid]; s_wrs[256 + tid] = WR[h * 512 + 256 + tid]; }
    __syncthreads();
    uint32_t qh[4][4], ql[4][4];
    {
        uint32_t ah = smem_u32(&sKV[0][(wq * 16 + (lane & 15)) * 72 + (lane >> 4) * 8]);
#pragma unroll
        for (int ks = 0; ks < 4; ks++) { ldsm4(qh[ks], ah + ks * 32); ldsm4(ql[ks], ah + 9216 + ks * 32); }
    }
    __syncthreads();

    uint32_t kAd[4], vAd[4];
#pragma unroll
    for (int t = 0; t < 4; t++) {
        int rK = t * 16 + ((lane >> 4) << 3) + (lane & 7), cK = ((lane >> 3) & 1) * 8;
        kAd[t] = smem_u32(&sK[rK * 72 + cK]);
        int rV = t * 16 + ((lane >> 3) & 1) * 8 + (lane & 7), cV = (lane >> 4) * 8;
        vAd[t] = smem_u32(&sV[rV * 72 + cV]);
    }

    float o[8][4];
#pragma unroll
    for (int nb = 0; nb < 8; nb++)
#pragma unroll
        for (int t = 0; t < 4; t++) o[nb][t] = 0.f;
    float arr[2][8];
#pragma unroll
    for (int hh = 0; hh < 2; hh++)
#pragma unroll
        for (int r = 0; r < 8; r++) arr[hh][r] = 0.f;
    float m0 = -1e30f, m1 = -1e30f, l0 = 0.f, l1 = 0.f;
    const int row0 = lane >> 2, c0 = (lane & 3) * 2;
    const int lt = tid & 127;
    const uint4* rbase = reinterpret_cast<const uint4*>(g_rel);

    for (int jt = g2; jt <= it; jt += 2) {
        BARG(g2 + 1);
#pragma unroll
        for (int u = 0; u < 4; u++) {
            int e = lt + u * 128, row = e >> 3, gg = e & 7;
            size_t gi = ((size_t)(b * SLEN + jt * 64 + row)) * PROJ + h * 64 + gg * 8;
            *reinterpret_cast<uint4*>(&sK[row * 72 + gg * 8]) = *reinterpret_cast<const uint4*>(&Kh_[gi]);
            *reinterpret_cast<uint4*>(&sV[row * 72 + gg * 8]) = *reinterpret_cast<const uint4*>(&Vh_[gi]);
        }
        BARG(g2 + 1);

        float s[8][4];
#pragma unroll
        for (int nb = 0; nb < 8; nb++)
#pragma unroll
            for (int t = 0; t < 4; t++) s[nb][t] = 0.f;
#pragma unroll
        for (int ks = 0; ks < 4; ks++)
#pragma unroll
            for (int t = 0; t < 4; t++) {
                uint32_t kh2[4];
                ldsm4(kh2, kAd[t] + ks * 32);
#pragma unroll
                for (int half = 0; half < 2; half++) {
                    int nb = t * 2 + half;
                    mma16816(s[nb], qh[ks], &kh2[half * 2]);
                    mma16816(s[nb], ql[ks], &kh2[half * 2]);
                }
            }
        if (jt == it) {
            int gi0 = wq * 16 + row0;
#pragma unroll
            for (int nb = 0; nb < 8; nb++) {
                int gj = nb * 8 + c0;
                if (gj     > gi0)     s[nb][0] = -1e30f;
                if (gj + 1 > gi0)     s[nb][1] = -1e30f;
                if (gj     > gi0 + 8) s[nb][2] = -1e30f;
                if (gj + 1 > gi0 + 8) s[nb][3] = -1e30f;
            }
        }
        float rm0 = -1e30f, rm1 = -1e30f;
#pragma unroll
        for (int nb = 0; nb < 8; nb++) {
            rm0 = fmaxf(rm0, fmaxf(s[nb][0], s[nb][1]));
            rm1 = fmaxf(rm1, fmaxf(s[nb][2], s[nb][3]));
        }
        rm0 = fmaxf(rm0, __shfl_xor_sync(0xffffffffu, rm0, 1));
        rm0 = fmaxf(rm0, __shfl_xor_sync(0xffffffffu, rm0, 2));
        rm1 = fmaxf(rm1, __shfl_xor_sync(0xffffffffu, rm1, 1));
        rm1 = fmaxf(rm1, __shfl_xor_sync(0xffffffffu, rm1, 2));
        float nm0 = fmaxf(m0, rm0), nm1 = fmaxf(m1, rm1);
        float sc0 = __expf(m0 - nm0), sc1 = __expf(m1 - nm1);
        m0 = nm0; m1 = nm1;
        float rs0 = 0.f, rs1 = 0.f;
#pragma unroll
        for (int nb = 0; nb < 8; nb++) {
            s[nb][0] = __expf(s[nb][0] - nm0);
            s[nb][1] = __expf(s[nb][1] - nm0);
            s[nb][2] = __expf(s[nb][2] - nm1);
            s[nb][3] = __expf(s[nb][3] - nm1);
            rs0 += s[nb][0] + s[nb][1];
            rs1 += s[nb][2] + s[nb][3];
        }
        rs0 += __shfl_xor_sync(0xffffffffu, rs0, 1);
        rs0 += __shfl_xor_sync(0xffffffffu, rs0, 2);
        rs1 += __shfl_xor_sync(0xffffffffu, rs1, 1);
        rs1 += __shfl_xor_sync(0xffffffffu, rs1, 2);
        l0 = l0 * sc0 + rs0;
        l1 = l1 * sc1 + rs1;
#pragma unroll
        for (int nb = 0; nb < 8; nb++) {
            o[nb][0] *= sc0; o[nb][1] *= sc0; o[nb][2] *= sc1; o[nb][3] *= sc1;
        }
        if (RA) {
#pragma unroll
            for (int r = 0; r < 8; r++) { arr[0][r] *= sc0; arr[1][r] *= sc1; }
            int gi0 = it * 64 + wq * 16 + row0;
            size_t p0 = ((size_t)(b * SLEN) + gi0) * SLEN + jt * 64 + c0;
            const uint4* rp0 = rbase + p0;
            const uint4* rp1 = rbase + p0 + (size_t)8 * SLEN;
#pragma unroll
            for (int nb = 0; nb < 8; nb++) {
                uint4 va = rp0[nb * 8];
                uint4 vb = rp0[nb * 8 + 1];
                uint4 vc = rp1[nb * 8];
                uint4 vd = rp1[nb * 8 + 1];
                const __half2* ha = reinterpret_cast<const __half2*>(&va);
                const __half2* hb = reinterpret_cast<const __half2*>(&vb);
                const __half2* hc = reinterpret_cast<const __half2*>(&vc);
                const __half2* hd = reinterpret_cast<const __half2*>(&vd);
#pragma unroll
                for (int q = 0; q < 4; q++) {
                    float2 fa = __half22float2(ha[q]);
                    float2 fb = __half22float2(hb[q]);
                    float2 fc = __half22float2(hc[q]);
                    float2 fd = __half22float2(hd[q]);
                    arr[0][2*q]   = fmaf(s[nb][0], fa.x, fmaf(s[nb][1], fb.x, arr[0][2*q]));
                    arr[0][2*q+1] = fmaf(s[nb][0], fa.y, fmaf(s[nb][1], fb.y, arr[0][2*q+1]));
                    arr[1][2*q]   = fmaf(s[nb][2], fc.x, fmaf(s[nb][3], fd.x, arr[1][2*q]));
                    arr[1][2*q+1] = fmaf(s[nb][2], fc.y, fmaf(s[nb][3], fd.y, arr[1][2*q+1]));
                }
            }
        }
#pragma unroll
        for (int jk = 0; jk < 4; jk++) {
            uint32_t ph[4], pl[4];
            ph[0] = hcvt2hi(s[2*jk][0],   s[2*jk][1]);
            ph[1] = hcvt2hi(s[2*jk][2],   s[2*jk][3]);
            ph[2] = hcvt2hi(s[2*jk+1][0], s[2*jk+1][1]);
            ph[3] = hcvt2hi(s[2*jk+1][2], s[2*jk+1][3]);
            pl[0] = hcvt2lo(s[2*jk][0],   s[2*jk][1],   ph[0]);
            pl[1] = hcvt2lo(s[2*jk][2],   s[2*jk][3],   ph[1]);
            pl[2] = hcvt2lo(s[2*jk+1][0], s[2*jk+1][1], ph[2]);
            pl[3] = hcvt2lo(s[2*jk+1][2], s[2*jk+1][3], ph[3]);
#pragma unroll
            for (int db = 0; db < 4; db++) {
                uint32_t vh2[4];
                ldsm4t(vh2, vAd[jk] + db * 32);
#pragma unroll
                for (int half = 0; half < 2; half++) {
                    int nb = db * 2 + half;
                    mma16816(o[nb], ph, &vh2[half * 2]);
                    mma16816(o[nb], pl, &vh2[half * 2]);
                }
            }
        }
    }

    __syncthreads();
    if (g2 == 1) {
#pragma unroll
        for (int nb = 0; nb < 8; nb++) {
            *reinterpret_cast<float2*>(&mO[(wq * 16 + row0) * 64 + nb * 8 + c0])     = make_float2(o[nb][0], o[nb][1]);
            *reinterpret_cast<float2*>(&mO[(wq * 16 + row0 + 8) * 64 + nb * 8 + c0]) = make_float2(o[nb][2], o[nb][3]);
        }
        if ((lane & 3) == 0) {
            s_mSt[(wq * 16 + row0) * 2]         = m0;
            s_mSt[(wq * 16 + row0) * 2 + 1]     = l0;
            s_mSt[(wq * 16 + row0 + 8) * 2]     = m1;
            s_mSt[(wq * 16 + row0 + 8) * 2 + 1] = l1;
        }
        if (RA) {
#pragma unroll
            for (int hh = 0; hh < 2; hh++)
#pragma unroll
                for (int r = 0; r < 8; r++) {
                    arr[hh][r] += __shfl_xor_sync(0xffffffffu, arr[hh][r], 1);
                    arr[hh][r] += __shfl_xor_sync(0xffffffffu, arr[hh][r], 2);
                }
            if ((lane & 3) == 0)
#pragma unroll
                for (int r = 0; r < 8; r++) {
                    mAr[(wq * 16 + row0) * 8 + r]     = arr[0][r];
                    mAr[(wq * 16 + row0 + 8) * 8 + r] = arr[1][r];
                }
        }
    }
    __syncthreads();
    if (g2 == 0) {
        if (RA) {
#pragma unroll
            for (int hh = 0; hh < 2; hh++)
#pragma unroll
                for (int r = 0; r < 8; r++) {
                    arr[hh][r] += __shfl_xor_sync(0xffffffffu, arr[hh][r], 1);
                    arr[hh][r] += __shfl_xor_sync(0xffffffffu, arr[hh][r], 2);
                }
        }
#pragma unroll
        for (int half = 0; half < 2; half++) {
            int rr = wq * 16 + row0 + half * 8;
            float mo = half ? m1 : m0, lo_ = half ? l1 : l0;
            float m2 = s_mSt[rr * 2], l2 = s_mSt[rr * 2 + 1];
            float mf = fmaxf(mo, m2);
            float e1 = __expf(mo - mf), e2 = __expf(m2 - mf);
            float inv = 1.f / (lo_ * e1 + l2 * e2);
            float arf[8];
            if (RA)
#pragma unroll
                for (int r = 0; r < 8; r++)
                    arf[r] = (arr[half][r] * e1 + mAr[rr * 8 + r] * e2) * inv;
#pragma unroll
            for (int nb = 0; nb < 8; nb++) {
                float2 o2 = *reinterpret_cast<float2*>(&mO[rr * 64 + nb * 8 + c0]);
                float v0 = (o[nb][half * 2] * e1     + o2.x * e2) * inv;
                float v1 = (o[nb][half * 2 + 1] * e1 + o2.y * e2) * inv;
                if (RA) {
                    int d0 = nb * 8 + c0;
                    float r0s = 0.f, r1s = 0.f;
#pragma unroll
                    for (int r = 0; r < 8; r++) {
                        r0s = fmaf(arf[r], s_wrs[d0 * 8 + r], r0s);
                        r1s = fmaf(arf[r], s_wrs[(d0 + 1) * 8 + r], r1s);
                    }
                    v0 += r0s; v1 += r1s;
                }
                size_t oo = ((size_t)(b * SLEN + it * 64 + rr)) * PROJ + h * 64 + nb * 8 + c0;
                uint32_t hp = hcvt2hi(v0, v1), lp = hcvt2lo(v0, v1, hp);
                *reinterpret_cast<uint32_t*>(&Ohi[oo]) = hp;
                *reinterpret_cast<uint32_t*>(&Olo[oo]) = lp;
            }
        }
    }
}

// ---------------- host launcher --------------------------------------------------
extern "C" void kernel_launch(void* const* d_in, const int* in_sizes, int n_in,
                              void* d_out, int out_size)
{
    const float* x       = (const float*)d_in[0];
    const float* symbols = (const float*)d_in[1];
    const float* fc      = (const float*)d_in[2];
    const float* fs      = (const float*)d_in[3];
    const float* wsrc[10] = {
        (const float*)d_in[4],  (const float*)d_in[5],  (const float*)d_in[6],
        (const float*)d_in[8],  (const float*)d_in[9],  (const float*)d_in[10],
        (const float*)d_in[11], (const float*)d_in[13], (const float*)d_in[7],
        (const float*)d_in[14],
    };
    const float* wr = (const float*)d_in[12];
    float* out = (float*)d_out;

    __half *xhi, *xlo, *shi, *slo, *w, *chi, *clo;
    __half *qhi, *qlo, *qahi, *qalo, *qrhi, *qrlo;
    __half *k, *ka, *v, *sv, *kr;
    cudaGetSymbolAddress((void**)&xhi, g_xhi);   cudaGetSymbolAddress((void**)&xlo, g_xlo);
    cudaGetSymbolAddress((void**)&shi, g_shi);   cudaGetSymbolAddress((void**)&slo, g_slo);
    cudaGetSymbolAddress((void**)&w,   g_w);
    cudaGetSymbolAddress((void**)&chi, g_chi);   cudaGetSymbolAddress((void**)&clo, g_clo);
    cudaGetSymbolAddress((void**)&qhi, g_qhi);   cudaGetSymbolAddress((void**)&qlo, g_qlo);
    cudaGetSymbolAddress((void**)&qahi, g_qahi); cudaGetSymbolAddress((void**)&qalo, g_qalo);
    cudaGetSymbolAddress((void**)&qrhi, g_qrhi); cudaGetSymbolAddress((void**)&qrlo, g_qrlo);
    cudaGetSymbolAddress((void**)&k,  g_k);
    cudaGetSymbolAddress((void**)&ka, g_ka);
    cudaGetSymbolAddress((void**)&v,  g_v);
    cudaGetSymbolAddress((void**)&sv, g_sv);
    cudaGetSymbolAddress((void**)&kr, g_kr);

    const int wsz[10] = { PROJ*DMODEL, PROJ*DMODEL, PROJ*DMODEL, PROJ*DMODEL, PROJ*DMODEL,
                          PROJ*DMODEL, PROJ*DMODEL, PROJ*DMODEL, PROJ*PROJ, PROJ*PROJ };
    size_t woff[10];
    { size_t o = 0; for (int i = 0; i < 10; i++) { woff[i] = o; o += wsz[i]; } }

    // split launch A: x + symbols (hi/lo)
    {
        SBatch sb;
        sb.e[0] = { x,       xhi, xlo, MTOT * DMODEL };
        sb.e[1] = { symbols, shi, slo, MTOT * DMODEL };
        for (int i = 2; i < 10; i++) sb.e[i] = sb.e[0];
        dim3 grid((MTOT * DMODEL + 255) / 256, 2);
        split_multi<<<grid, 256>>>(sb);
    }
    // split launch B: 10 weights, single fp16
    {
        SBatch sb;
        for (int i = 0; i < 10; i++)
            sb.e[i] = { wsrc[i], w + woff[i], nullptr, wsz[i] };
        dim3 grid((PROJ * DMODEL + 255) / 256, 10);
        split_multi<<<grid, 256>>>(sb);
    }

    // projections: q 4, k 3, v 1, qa 4, ka 3, qr 2, kr 1, sv 1
    {
        GBatch gb;
        gb.fc = fc; gb.fs = fs; gb.K = DMODEL;
        __half* yh[8] = { qhi, k, v, qahi, ka, qrhi, kr, sv };
        __half* yl[8] = { qlo, nullptr, nullptr, qalo, nullptr, qrlo, nullptr, nullptr };
        int modes[8] = { 4, 3, 1, 4, 3, 2, 1, 1 };
        for (int i = 0; i < 8; i++) {
            gb.e[i].ahi = (i == 7) ? shi : xhi;
            gb.e[i].alo = (i == 7) ? slo : xlo;
            gb.e[i].b = w + woff[i];
            gb.e[i].y = nullptr; gb.e[i].ldy = PROJ; gb.e[i].col_off = 0;
            gb.e[i].mode = modes[i]; gb.e[i].yhi = yh[i]; gb.e[i].ylo = yl[i];
        }
        dim3 grid(PROJ / 128, MTOT / 128, 8);
        gemm_mma<<<grid, 256>>>(gb);
    }

    // rel transposed
    {
        const int RSM = 94208;
        cudaFuncSetAttribute(rel_mma_t, cudaFuncAttributeMaxDynamicSharedMemorySize, RSM);
        dim3 grid(SLEN / 64, SLEN / 64, NBATCH);
        rel_mma_t<<<grid, 256, RSM>>>();
    }

    // flash attentions merged (z=0 SA, z=1 RA)
    {
        dim3 gfl(SLEN / 64, NBATCH * 8, 2);
        flash_mma<<<gfl, 256>>>(qhi, qlo, k, v, qahi, qalo, ka, sv, wr, chi, clo);
    }

    // output projections -> fp32 halves of out
    {
        GBatch gb;
        gb.fc = fc; gb.fs = fs; gb.K = PROJ;
        gb.e[0].ahi = chi; gb.e[0].alo = clo;
        gb.e[0].b = w + woff[8];
        gb.e[0].y = out; gb.e[0].ldy = DMODEL; gb.e[0].col_off = 0; gb.e[0].mode = 0;
        gb.e[0].yhi = nullptr; gb.e[0].ylo = nullptr;
        gb.e[1] = gb.e[0];
        gb.e[1].ahi = chi + (size_t)MTOT * PROJ; gb.e[1].alo = clo + (size_t)MTOT * PROJ;
        gb.e[1].b = w + woff[9];
        gb.e[1].col_off = 512;
        for (int i = 2; i < 8; i++) gb.e[i] = gb.e[0];
        dim3 grid(PROJ / 128, MTOT / 128, 2);
        gemm_mma<<<grid, 256>>>(gb);
    }
}